// round 6
// baseline (speedup 1.0000x reference)
#include <cuda_runtime.h>
#include <cuda_bf16.h>
#include <math.h>
#include <stdint.h>

// ---------------- problem constants ----------------
#define B_      16
#define S_      576
#define F_      700
#define FP_     704             // F padded to mult of 32
#define D_      64
#define KC_     1024
#define T_      (B_*S_)         // 9216 tokens
#define H1_     512
#define H2_     256
#define ENC_    128             // 2*D
#define SF_     (S_*F_)         // 403200
#define SD_     (S_*D_)         // 36864
#define ZSPLIT  2

#define OUT_REC  0
#define OUT_MEAN (B_*SF_)
#define OUT_LV   (OUT_MEAN + T_*D_)
#define OUT_VQL  (OUT_LV + T_*D_)

#define DEC1_CHUNKS 144

typedef unsigned long long u64;
typedef __nv_bfloat16 bf16;

// ---------------- scratch (device globals; no allocation allowed) ----------------
__device__ __align__(256) bf16  g_xh[T_*FP_];
__device__ __align__(256) bf16  g_xl[T_*FP_];
__device__ __align__(256) bf16  g_w1h[H1_*FP_];
__device__ __align__(256) bf16  g_w1l[H1_*FP_];
__device__ __align__(256) bf16  g_w2h[H2_*H1_];
__device__ __align__(256) bf16  g_w2l[H2_*H1_];
__device__ __align__(256) bf16  g_w3h[ENC_*H2_];
__device__ __align__(256) bf16  g_w3l[ENC_*H2_];
__device__ __align__(256) bf16  g_h1h[T_*H1_];
__device__ __align__(256) bf16  g_h1l[T_*H1_];
__device__ __align__(256) bf16  g_h2h[T_*H2_];
__device__ __align__(256) bf16  g_h2l[T_*H2_];
__device__ __align__(256) bf16  g_zeh[T_*D_];
__device__ __align__(256) bf16  g_zel[T_*D_];
__device__ __align__(256) bf16  g_cbh[KC_*D_];
__device__ __align__(256) bf16  g_cbl[KC_*D_];
__device__ __align__(256) float g_encp[ZSPLIT*T_*ENC_];
__device__ __align__(256) float g_ze[T_*D_];
__device__ __align__(256) float g_zq[T_*D_];
__device__ __align__(256) float g_cross[T_*KC_];
__device__ __align__(256) float g_csq[KC_];
__device__ __align__(256) float g_tokloss[T_];
__device__ __align__(256) float g_dpart[DEC1_CHUNKS*16*H2_];
__device__ __align__(256) float g_dvec[16*H2_];

// ---------------- f32x2 helpers (decoder kernels) ----------------
__device__ __forceinline__ u64 dupf(float a) {
    unsigned r = __float_as_uint(a);
    u64 d;
    asm("mov.b64 %0, {%1, %1};" : "=l"(d) : "r"(r));
    return d;
}
__device__ __forceinline__ void ffma2(u64 &d, u64 a, u64 b) {
    asm("fma.rn.f32x2 %0, %1, %2, %0;" : "+l"(d) : "l"(a), "l"(b));
}
__device__ __forceinline__ float2 unpk(u64 v) {
    unsigned lo, hi;
    asm("mov.b64 {%0, %1}, %2;" : "=r"(lo), "=r"(hi) : "l"(v));
    return make_float2(__uint_as_float(lo), __uint_as_float(hi));
}
__device__ __forceinline__ float softplusf(float x) {
    return fmaxf(x, 0.0f) + log1pf(expf(-fabsf(x)));
}

// ---------------- bf16 split helpers ----------------
__device__ __forceinline__ void split2u(float x, float y, uint32_t &hi, uint32_t &lo) {
    __nv_bfloat162 h = __floats2bfloat162_rn(x, y);
    float hx = __bfloat162float(h.x), hy = __bfloat162float(h.y);
    __nv_bfloat162 l = __floats2bfloat162_rn(x - hx, y - hy);
    hi = *reinterpret_cast<uint32_t*>(&h);
    lo = *reinterpret_cast<uint32_t*>(&l);
}

// ---------------- mma.sync / cp.async helpers ----------------
__device__ __forceinline__ uint32_t smem_u32(const void* p) {
    uint32_t a;
    asm("{ .reg .u64 t; cvta.to.shared.u64 t, %1; cvt.u32.u64 %0, t; }" : "=r"(a) : "l"(p));
    return a;
}
__device__ __forceinline__ void ldsm4(uint32_t (&r)[4], uint32_t addr) {
    asm volatile("ldmatrix.sync.aligned.m8n8.x4.shared.b16 {%0,%1,%2,%3}, [%4];"
                 : "=r"(r[0]), "=r"(r[1]), "=r"(r[2]), "=r"(r[3]) : "r"(addr));
}
__device__ __forceinline__ void mma_bf16(float (&d)[4], const uint32_t (&a)[4],
                                         uint32_t b0, uint32_t b1) {
    asm volatile("mma.sync.aligned.m16n8k16.row.col.f32.bf16.bf16.f32 "
                 "{%0,%1,%2,%3}, {%4,%5,%6,%7}, {%8,%9}, {%0,%1,%2,%3};"
                 : "+f"(d[0]), "+f"(d[1]), "+f"(d[2]), "+f"(d[3])
                 : "r"(a[0]), "r"(a[1]), "r"(a[2]), "r"(a[3]), "r"(b0), "r"(b1));
}
__device__ __forceinline__ void cp16(uint32_t s, const void* g) {
    asm volatile("cp.async.cg.shared.global [%0], [%1], 16;" :: "r"(s), "l"(g));
}
#define CP_COMMIT() asm volatile("cp.async.commit_group;" ::: "memory")
#define CP_WAIT2()  asm volatile("cp.async.wait_group 2;" ::: "memory")

// SMEM per stage (bytes): Ah [128 rows x 80B] (10240) | Al +10240 | Bh +20480 | Bl +30720
#define STAGE_B   40960
#define NSTG      3
#define SMEM_BYTES (NSTG * STAGE_B)

// ---------------- bf16x3 tensor-core GEMM, cp.async 3-stage pipeline -------------
// C = act(A(MxK) * Bt(NxK)^T [+ bias]); A = Ah+Al, B = Bh+Bl (pre-split bf16).
// K mult of 32 (zero-padded). BM=BN=128, BK=32, 256 thr, warp grid 4(M)x2(N).
// MODE 1: relu+bias, split bf16 out. MODE 2: split-K fp32 partials. MODE 3: fp32 out.
template<int MODE>
__global__ __launch_bounds__(256, 1) void mma_gemm_bf(
    int M, int N, int K, int kPerZ,
    const bf16* __restrict__ Ah, const bf16* __restrict__ Al,
    const bf16* __restrict__ Bh, const bf16* __restrict__ Bl,
    const float* __restrict__ bias,
    float* __restrict__ Cf, bf16* __restrict__ Ch, bf16* __restrict__ Cl)
{
    extern __shared__ __align__(16) char sm[];
    const int tid  = threadIdx.x;
    const int wid  = tid >> 5;
    const int lane = tid & 31;
    const int row0 = blockIdx.y * 128;
    const int col0 = blockIdx.x * 128;
    const int kStart = (MODE == 2) ? blockIdx.z * kPerZ : 0;
    const int kLen   = (MODE == 2) ? kPerZ : K;
    const int NS = kLen >> 5;                  // always >= 2 here
    const uint32_t smb = smem_u32(sm);

    float acc[2][8][4];
#pragma unroll
    for (int mt = 0; mt < 2; ++mt)
#pragma unroll
        for (int nt = 0; nt < 8; ++nt)
#pragma unroll
            for (int q = 0; q < 4; ++q) acc[mt][nt][q] = 0.0f;

    const int lrow = tid >> 1;                 // 0..127
    const int lce  = (tid & 1) * 16;           // elem offset within BK=32

    const size_t aBase = (size_t)(row0 + lrow) * K + lce;
    const size_t bBase = (size_t)(col0 + lrow) * K + lce;
    const uint32_t sOff = (uint32_t)lrow * 80u + (uint32_t)lce * 2u;

    // stage loader: 8 x cp.async of 16B
    auto load_stage = [&](int slot, int k0) {
        uint32_t so = smb + (uint32_t)slot * STAGE_B + sOff;
        const bf16* a0 = Ah + aBase + k0;
        const bf16* a1 = Al + aBase + k0;
        const bf16* b0 = Bh + bBase + k0;
        const bf16* b1 = Bl + bBase + k0;
        cp16(so,              a0); cp16(so + 16,          a0 + 8);
        cp16(so + 10240,      a1); cp16(so + 10240 + 16,  a1 + 8);
        cp16(so + 20480,      b0); cp16(so + 20480 + 16,  b0 + 8);
        cp16(so + 30720,      b1); cp16(so + 30720 + 16,  b1 + 8);
    };

    // prologue: stages 0 and 1
    load_stage(0, kStart);      CP_COMMIT();
    load_stage(1, kStart + 32); CP_COMMIT();

    const int wm = wid >> 1, wn = wid & 1;
    const int arow  = wm * 32 + (lane & 15);
    const int acolB = (lane >> 4) * 16;
    const int brow  = wn * 64 + ((lane >> 4) << 3) + (lane & 7);
    const int bkhB  = ((lane >> 3) & 1) * 16;

    for (int s = 0; s < NS; ++s) {
        if (s + 2 < NS) {
            int sl = s + 2; while (sl >= NSTG) sl -= NSTG;
            load_stage(sl, kStart + (s + 2) * 32);
        }
        CP_COMMIT();
        CP_WAIT2();
        __syncthreads();

        int cslot = s; while (cslot >= NSTG) cslot -= NSTG;
        const uint32_t stgB = (uint32_t)cslot * STAGE_B;
#pragma unroll
        for (int ks = 0; ks < 2; ++ks) {
            uint32_t ah[2][4], al[2][4];
#pragma unroll
            for (int mt = 0; mt < 2; ++mt) {
                uint32_t addr = smb + stgB + (uint32_t)(arow + mt * 16) * 80u
                              + (uint32_t)ks * 32u + acolB;
                ldsm4(ah[mt], addr);
                ldsm4(al[mt], addr + 10240u);
            }
            uint32_t bh[8][2], bl[8][2];
#pragma unroll
            for (int p = 0; p < 4; ++p) {
                uint32_t addr = smb + stgB + 20480u + (uint32_t)(brow + p * 16) * 80u
                              + (uint32_t)ks * 32u + bkhB;
                uint32_t r[4];
                ldsm4(r, addr);
                bh[2*p][0] = r[0]; bh[2*p][1] = r[1];
                bh[2*p+1][0] = r[2]; bh[2*p+1][1] = r[3];
                ldsm4(r, addr + 10240u);
                bl[2*p][0] = r[0]; bl[2*p][1] = r[1];
                bl[2*p+1][0] = r[2]; bl[2*p+1][1] = r[3];
            }
#pragma unroll
            for (int mt = 0; mt < 2; ++mt)
#pragma unroll
                for (int nt = 0; nt < 8; ++nt) {
                    mma_bf16(acc[mt][nt], ah[mt], bh[nt][0], bh[nt][1]);
                    mma_bf16(acc[mt][nt], ah[mt], bl[nt][0], bl[nt][1]);
                    mma_bf16(acc[mt][nt], al[mt], bh[nt][0], bh[nt][1]);
                }
        }
        __syncthreads();
    }

    // ---- epilogue ----
#pragma unroll
    for (int mt = 0; mt < 2; ++mt) {
        int r = row0 + wm * 32 + mt * 16 + (lane >> 2);
#pragma unroll
        for (int nt = 0; nt < 8; ++nt) {
            int c = col0 + wn * 64 + nt * 8 + (lane & 3) * 2;
            if (MODE == 1) {
                float b0 = bias[c], b1 = bias[c + 1];
                float v0 = fmaxf(acc[mt][nt][0] + b0, 0.0f);
                float v1 = fmaxf(acc[mt][nt][1] + b1, 0.0f);
                float v2 = fmaxf(acc[mt][nt][2] + b0, 0.0f);
                float v3 = fmaxf(acc[mt][nt][3] + b1, 0.0f);
                uint32_t h, l;
                split2u(v0, v1, h, l);
                *(uint32_t*)&Ch[(size_t)r * N + c] = h;
                *(uint32_t*)&Cl[(size_t)r * N + c] = l;
                split2u(v2, v3, h, l);
                *(uint32_t*)&Ch[(size_t)(r + 8) * N + c] = h;
                *(uint32_t*)&Cl[(size_t)(r + 8) * N + c] = l;
            } else if (MODE == 2) {
                float* Co = Cf + (size_t)blockIdx.z * M * N;
                *(float2*)&Co[(size_t)r * N + c]       = make_float2(acc[mt][nt][0], acc[mt][nt][1]);
                *(float2*)&Co[(size_t)(r + 8) * N + c] = make_float2(acc[mt][nt][2], acc[mt][nt][3]);
            } else {
                *(float2*)&Cf[(size_t)r * N + c]       = make_float2(acc[mt][nt][0], acc[mt][nt][1]);
                *(float2*)&Cf[(size_t)(r + 8) * N + c] = make_float2(acc[mt][nt][2], acc[mt][nt][3]);
            }
        }
    }
}

// ---------------- transpose + split: Wt{h,l}[n][kp] = split(W[k][n]), zero-pad ----
__global__ void transpose_split_kernel(const float* __restrict__ W,
                                       bf16* __restrict__ Wth, bf16* __restrict__ Wtl,
                                       int K, int N, int KP)
{
    __shared__ float tile[32][33];
    int kb = blockIdx.y * 32, nb = blockIdx.x * 32;
    int tx = threadIdx.x, ty = threadIdx.y;   // 32 x 8
#pragma unroll
    for (int i = 0; i < 32; i += 8) {
        int k = kb + ty + i, n = nb + tx;
        tile[ty + i][tx] = (k < K && n < N) ? W[(size_t)k * N + n] : 0.0f;
    }
    __syncthreads();
#pragma unroll
    for (int i = 0; i < 32; i += 8) {
        int n = nb + ty + i, k = kb + tx;
        if (n < N && k < KP) {
            float v = tile[tx][ty + i];
            bf16 h = __float2bfloat16(v);
            Wth[(size_t)n * KP + k] = h;
            Wtl[(size_t)n * KP + k] = __float2bfloat16(v - __bfloat162float(h));
        }
    }
}

// ---------------- split x into padded bf16 hi/lo ----------------
__global__ void split_x_kernel(const float* __restrict__ x) {
    int idx = blockIdx.x * 256 + threadIdx.x;
    if (idx >= T_ * (FP_ / 4)) return;
    int t  = idx / (FP_ / 4);
    int c4 = (idx % (FP_ / 4)) * 4;
    float4 v = make_float4(0.f, 0.f, 0.f, 0.f);
    if (c4 < F_) v = *(const float4*)(x + (size_t)t * F_ + c4);
    uint32_t h01, l01, h23, l23;
    split2u(v.x, v.y, h01, l01);
    split2u(v.z, v.w, h23, l23);
    *(uint2*)&g_xh[(size_t)t * FP_ + c4] = make_uint2(h01, h23);
    *(uint2*)&g_xl[(size_t)t * FP_ + c4] = make_uint2(l01, l23);
}

// ---------------- codebook split + squared norms (warp per code) ----------------
__global__ void cb_prep_kernel(const float* __restrict__ cb) {
    int w    = (blockIdx.x * 256 + threadIdx.x) >> 5;
    int lane = threadIdx.x & 31;
    float2 v = *(const float2*)(cb + (size_t)w * 64 + lane * 2);
    float s = v.x * v.x + v.y * v.y;
#pragma unroll
    for (int off = 16; off; off >>= 1) s += __shfl_down_sync(0xffffffffu, s, off);
    uint32_t h, l;
    split2u(v.x, v.y, h, l);
    *(uint32_t*)&g_cbh[(size_t)w * 64 + lane * 2] = h;
    *(uint32_t*)&g_cbl[(size_t)w * 64 + lane * 2] = l;
    if (lane == 0) g_csq[w] = s;
}

// ---------------- combine enc partials + reparameterize + split z_e ----------------
__global__ void reparam_kernel(const float* __restrict__ eps,
                               const float* __restrict__ be3,
                               float* __restrict__ out) {
    int i = blockIdx.x * 256 + threadIdx.x;
    if (i >= T_ * D_) return;
    int t = i >> 6, d = i & 63;
    float m  = be3[d]      + g_encp[t * ENC_ + d]      + g_encp[T_*ENC_ + t * ENC_ + d];
    float lv = be3[64 + d] + g_encp[t * ENC_ + 64 + d] + g_encp[T_*ENC_ + t * ENC_ + 64 + d];
    float zv = m + expf(0.5f * lv) * eps[i];
    g_ze[i] = zv;
    bf16 zh = __float2bfloat16(zv);
    g_zeh[i] = zh;
    g_zel[i] = __float2bfloat16(zv - __bfloat162float(zh));
    out[OUT_MEAN + i] = m;
    out[OUT_LV + i]   = lv;
}

// warp per token: argmin over 1024 codes of (c_sq - 2*cross), gather, per-token loss
__global__ __launch_bounds__(256) void argmin_kernel(const float* __restrict__ cb) {
    int t    = (blockIdx.x * 256 + threadIdx.x) >> 5;
    int lane = threadIdx.x & 31;

    const float4* cr = (const float4*)g_cross + (size_t)t * 256;
    const float4* cq = (const float4*)g_csq;

    float best = 3.4e38f;
    int bestk = 0;
#pragma unroll
    for (int i = 0; i < 8; ++i) {
        int v = lane + i * 32;
        float4 c = cr[v];
        float4 q = cq[v];
        float s0 = q.x - 2.0f * c.x;
        float s1 = q.y - 2.0f * c.y;
        float s2 = q.z - 2.0f * c.z;
        float s3 = q.w - 2.0f * c.w;
        int kb = v * 4;
        if (s0 < best) { best = s0; bestk = kb;     }
        if (s1 < best) { best = s1; bestk = kb + 1; }
        if (s2 < best) { best = s2; bestk = kb + 2; }
        if (s3 < best) { best = s3; bestk = kb + 3; }
    }
#pragma unroll
    for (int off = 16; off; off >>= 1) {
        float ob = __shfl_down_sync(0xffffffffu, best, off);
        int   ok = __shfl_down_sync(0xffffffffu, bestk, off);
        if (ob < best || (ob == best && ok < bestk)) { best = ob; bestk = ok; }
    }
    bestk = __shfl_sync(0xffffffffu, bestk, 0);

    float l = 0.0f;
    if (lane < 16) {
        float4 cv = ((const float4*)cb)[bestk * 16 + lane];
        float4 zv = ((const float4*)g_ze)[t * 16 + lane];
        ((float4*)g_zq)[t * 16 + lane] = cv;
        float dx = zv.x - cv.x, dy = zv.y - cv.y;
        float dz = zv.z - cv.z, dw = zv.w - cv.w;
        l = dx * dx + dy * dy + dz * dz + dw * dw;
    }
#pragma unroll
    for (int off = 16; off; off >>= 1)
        l += __shfl_down_sync(0xffffffffu, l, off);
    if (lane == 0) g_tokloss[t] = l;
}

__global__ __launch_bounds__(256) void dec1_part_kernel(const float* __restrict__ W) {
    __shared__ __align__(16) float zs[256 * 16];
    int k0 = blockIdx.x * 256;
    for (int i = threadIdx.x; i < 4096; i += 256) {
        int b = i >> 8, kk = i & 255;
        zs[kk * 16 + b] = g_zq[b * SD_ + k0 + kk];
    }
    __syncthreads();

    int n = threadIdx.x;
    u64 acc[8];
#pragma unroll
    for (int b2 = 0; b2 < 8; ++b2) acc[b2] = 0ULL;

#pragma unroll 4
    for (int kk = 0; kk < 256; ++kk) {
        u64 wd = dupf(W[(size_t)(k0 + kk) * H2_ + n]);
        const ulonglong2* dk = (const ulonglong2*)(zs + kk * 16);
        ulonglong2 p0 = dk[0], p1 = dk[1], p2 = dk[2], p3 = dk[3];
        u64 dp[8] = {p0.x, p0.y, p1.x, p1.y, p2.x, p2.y, p3.x, p3.y};
#pragma unroll
        for (int b2 = 0; b2 < 8; ++b2) ffma2(acc[b2], dp[b2], wd);
    }
#pragma unroll
    for (int b2 = 0; b2 < 8; ++b2) {
        float2 f = unpk(acc[b2]);
        g_dpart[blockIdx.x * 4096 + (2*b2)   * H2_ + n] = f.x;
        g_dpart[blockIdx.x * 4096 + (2*b2+1) * H2_ + n] = f.y;
    }
}

__global__ void dec1_fin_kernel(const float* __restrict__ bias) {
    int n = blockIdx.x * 256 + threadIdx.x;
    float s = 0.0f;
    for (int c = 0; c < DEC1_CHUNKS; ++c) s += g_dpart[c * 4096 + n];
    g_dvec[n] = fmaxf(s + bias[n & 255], 0.0f);
}

__global__ void vqloss_kernel(float* __restrict__ out) {
    __shared__ float sb[256];
    float a = 0.0f;
    for (int i = threadIdx.x; i < T_; i += 256) a += g_tokloss[i];
    sb[threadIdx.x] = a;
    __syncthreads();
    for (int s = 128; s > 0; s >>= 1) {
        if (threadIdx.x < s) sb[threadIdx.x] += sb[threadIdx.x + s];
        __syncthreads();
    }
    if (threadIdx.x == 0) out[OUT_VQL] = sb[0] / (float)(T_ * D_);
}

__global__ __launch_bounds__(256, 2) void dec2_kernel(
    const float* __restrict__ W, const float* __restrict__ bias,
    float* __restrict__ out)
{
    __shared__ __align__(16) float ds[H2_ * 16];
    for (int i = threadIdx.x; i < 4096; i += 256) {
        int b = i >> 8, k = i & 255;
        ds[k * 16 + b] = g_dvec[i];
    }
    __syncthreads();

    int n = (blockIdx.x * 256 + threadIdx.x) * 4;
    if (n >= SF_) return;

    u64 acc[8][4];
#pragma unroll
    for (int b2 = 0; b2 < 8; ++b2)
#pragma unroll
        for (int c = 0; c < 4; ++c) acc[b2][c] = 0ULL;

#pragma unroll 4
    for (int k = 0; k < H2_; ++k) {
        float4 w = *(const float4*)(W + (size_t)k * SF_ + n);
        u64 wd[4] = {dupf(w.x), dupf(w.y), dupf(w.z), dupf(w.w)};
        const ulonglong2* dk = (const ulonglong2*)(ds + k * 16);
        ulonglong2 p0 = dk[0], p1 = dk[1], p2 = dk[2], p3 = dk[3];
        u64 dp[8] = {p0.x, p0.y, p1.x, p1.y, p2.x, p2.y, p3.x, p3.y};
#pragma unroll
        for (int b2 = 0; b2 < 8; ++b2)
#pragma unroll
            for (int c = 0; c < 4; ++c)
                ffma2(acc[b2][c], dp[b2], wd[c]);
    }

    float4 bb = *(const float4*)(bias + n);
#pragma unroll
    for (int b2 = 0; b2 < 8; ++b2) {
        float2 f0 = unpk(acc[b2][0]);
        float2 f1 = unpk(acc[b2][1]);
        float2 f2 = unpk(acc[b2][2]);
        float2 f3 = unpk(acc[b2][3]);
        float4 v0, v1;
        v0.x = softplusf(f0.x + bb.x);
        v0.y = softplusf(f1.x + bb.y);
        v0.z = softplusf(f2.x + bb.z);
        v0.w = softplusf(f3.x + bb.w);
        v1.x = softplusf(f0.y + bb.x);
        v1.y = softplusf(f1.y + bb.y);
        v1.z = softplusf(f2.y + bb.z);
        v1.w = softplusf(f3.y + bb.w);
        *(float4*)(out + (size_t)(2*b2)   * SF_ + n) = v0;
        *(float4*)(out + (size_t)(2*b2+1) * SF_ + n) = v1;
    }
}

// ---------------- launch ----------------
#define SYM(var) ({ void* _p; cudaGetSymbolAddress(&_p, var); _p; })

extern "C" void kernel_launch(void* const* d_in, const int* in_sizes, int n_in,
                              void* d_out, int out_size)
{
    const float* x   = (const float*)d_in[0];
    const float* eps = (const float*)d_in[1];
    const float* We1 = (const float*)d_in[2];
    const float* be1 = (const float*)d_in[3];
    const float* We2 = (const float*)d_in[4];
    const float* be2 = (const float*)d_in[5];
    const float* We3 = (const float*)d_in[6];
    const float* be3 = (const float*)d_in[7];
    const float* cb  = (const float*)d_in[8];
    const float* Wd1 = (const float*)d_in[9];
    const float* bd1 = (const float*)d_in[10];
    const float* Wd2 = (const float*)d_in[11];
    const float* bd2 = (const float*)d_in[12];
    float* out = (float*)d_out;

    bf16 *xh  = (bf16*)SYM(g_xh),  *xl  = (bf16*)SYM(g_xl);
    bf16 *w1h = (bf16*)SYM(g_w1h), *w1l = (bf16*)SYM(g_w1l);
    bf16 *w2h = (bf16*)SYM(g_w2h), *w2l = (bf16*)SYM(g_w2l);
    bf16 *w3h = (bf16*)SYM(g_w3h), *w3l = (bf16*)SYM(g_w3l);
    bf16 *h1h = (bf16*)SYM(g_h1h), *h1l = (bf16*)SYM(g_h1l);
    bf16 *h2h = (bf16*)SYM(g_h2h), *h2l = (bf16*)SYM(g_h2l);
    bf16 *zeh = (bf16*)SYM(g_zeh), *zel = (bf16*)SYM(g_zel);
    bf16 *cbh = (bf16*)SYM(g_cbh), *cbl = (bf16*)SYM(g_cbl);
    float *encp  = (float*)SYM(g_encp);
    float *cross = (float*)SYM(g_cross);

    cudaFuncSetAttribute(mma_gemm_bf<1>, cudaFuncAttributeMaxDynamicSharedMemorySize, SMEM_BYTES);
    cudaFuncSetAttribute(mma_gemm_bf<2>, cudaFuncAttributeMaxDynamicSharedMemorySize, SMEM_BYTES);
    cudaFuncSetAttribute(mma_gemm_bf<3>, cudaFuncAttributeMaxDynamicSharedMemorySize, SMEM_BYTES);

    // pre-split operands
    split_x_kernel<<<(T_ * (FP_/4) + 255) / 256, 256>>>(x);
    transpose_split_kernel<<<dim3(16, 22), dim3(32, 8)>>>(We1, w1h, w1l, F_,  H1_, FP_);
    transpose_split_kernel<<<dim3(8, 16),  dim3(32, 8)>>>(We2, w2h, w2l, H1_, H2_, H1_);
    transpose_split_kernel<<<dim3(4, 8),   dim3(32, 8)>>>(We3, w3h, w3l, H2_, ENC_, H2_);
    cb_prep_kernel<<<128, 256>>>(cb);

    // encoder MLP on tensor cores (bf16x3, cp.async pipeline)
    mma_gemm_bf<1><<<dim3(4, 72), 256, SMEM_BYTES>>>(T_, H1_, FP_, 0,
        xh, xl, w1h, w1l, be1, nullptr, h1h, h1l);
    mma_gemm_bf<1><<<dim3(2, 72), 256, SMEM_BYTES>>>(T_, H2_, H1_, 0,
        h1h, h1l, w2h, w2l, be2, nullptr, h2h, h2l);
    mma_gemm_bf<2><<<dim3(1, 72, ZSPLIT), 256, SMEM_BYTES>>>(T_, ENC_, H2_, H2_/ZSPLIT,
        h2h, h2l, w3h, w3l, nullptr, encp, nullptr, nullptr);

    reparam_kernel<<<(T_ * D_ + 255) / 256, 256>>>(eps, be3, out);

    // VQ cross = z_e @ codebook^T
    mma_gemm_bf<3><<<dim3(8, 72), 256, SMEM_BYTES>>>(T_, KC_, D_, 0,
        zeh, zel, cbh, cbl, nullptr, cross, nullptr, nullptr);
    argmin_kernel<<<T_ / 8, 256>>>(cb);

    // decoder
    dec1_part_kernel<<<DEC1_CHUNKS, 256>>>(Wd1);
    dec1_fin_kernel<<<16, 256>>>(bd1);
    vqloss_kernel<<<1, 256>>>(out);
    dec2_kernel<<<(SF_ / 4 + 255) / 256, 256>>>(Wd2, bd2, out);
}

// round 7
// speedup vs baseline: 1.0168x; 1.0168x over previous
#include <cuda_runtime.h>
#include <cuda_bf16.h>
#include <math.h>
#include <stdint.h>

// ---------------- problem constants ----------------
#define B_      16
#define S_      576
#define F_      700
#define D_      64
#define KC_     1024
#define T_      (B_*S_)         // 9216 tokens
#define H1_     512
#define H2_     256
#define ENC_    128             // 2*D
#define SF_     (S_*F_)         // 403200
#define SD_     (S_*D_)         // 36864
#define ZSPLIT  2

#define OUT_REC  0
#define OUT_MEAN (B_*SF_)
#define OUT_LV   (OUT_MEAN + T_*D_)
#define OUT_VQL  (OUT_LV + T_*D_)

#define DEC1_CHUNKS 144

typedef unsigned long long u64;
typedef __nv_bfloat16 bf16;

// ---------------- scratch (device globals; no allocation allowed) ----------------
__device__ __align__(256) float g_h1[T_*H1_];
__device__ __align__(256) float g_h2[T_*H2_];
__device__ __align__(256) float g_encp[ZSPLIT*T_*ENC_];
__device__ __align__(256) float g_ze[T_*D_];
__device__ __align__(256) float g_zq[T_*D_];
__device__ __align__(256) float g_cross[T_*KC_];
__device__ __align__(256) float g_csq[KC_];
__device__ __align__(256) float g_tokloss[T_];
__device__ __align__(256) float g_dpart[DEC1_CHUNKS*16*H2_];
__device__ __align__(256) float g_dvec[16*H2_];
__device__ __align__(256) float g_wt1[H1_*F_];     // We1^T  [512][700]
__device__ __align__(256) float g_wt2[H2_*H1_];    // We2^T  [256][512]
__device__ __align__(256) float g_wt3[ENC_*H2_];   // We3^T  [128][256]

// ---------------- f32x2 helpers (decoder kernels) ----------------
__device__ __forceinline__ u64 dupf(float a) {
    unsigned r = __float_as_uint(a);
    u64 d;
    asm("mov.b64 %0, {%1, %1};" : "=l"(d) : "r"(r));
    return d;
}
__device__ __forceinline__ void ffma2(u64 &d, u64 a, u64 b) {
    asm("fma.rn.f32x2 %0, %1, %2, %0;" : "+l"(d) : "l"(a), "l"(b));
}
__device__ __forceinline__ float2 unpk(u64 v) {
    unsigned lo, hi;
    asm("mov.b64 {%0, %1}, %2;" : "=r"(lo), "=r"(hi) : "l"(v));
    return make_float2(__uint_as_float(lo), __uint_as_float(hi));
}
__device__ __forceinline__ float softplusf(float x) {
    return fmaxf(x, 0.0f) + log1pf(expf(-fabsf(x)));
}

// ---------------- mma.sync helpers ----------------
__device__ __forceinline__ uint32_t smem_u32(const void* p) {
    uint32_t a;
    asm("{ .reg .u64 t; cvta.to.shared.u64 t, %1; cvt.u32.u64 %0, t; }" : "=r"(a) : "l"(p));
    return a;
}
__device__ __forceinline__ void ldsm4(uint32_t (&r)[4], uint32_t addr) {
    asm volatile("ldmatrix.sync.aligned.m8n8.x4.shared.b16 {%0,%1,%2,%3}, [%4];"
                 : "=r"(r[0]), "=r"(r[1]), "=r"(r[2]), "=r"(r[3]) : "r"(addr));
}
__device__ __forceinline__ void mma_bf16(float (&d)[4], const uint32_t (&a)[4],
                                         uint32_t b0, uint32_t b1) {
    asm volatile("mma.sync.aligned.m16n8k16.row.col.f32.bf16.bf16.f32 "
                 "{%0,%1,%2,%3}, {%4,%5,%6,%7}, {%8,%9}, {%0,%1,%2,%3};"
                 : "+f"(d[0]), "+f"(d[1]), "+f"(d[2]), "+f"(d[3])
                 : "r"(a[0]), "r"(a[1]), "r"(a[2]), "r"(a[3]), "r"(b0), "r"(b1));
}
// split fp32 pair -> packed bf16x2 hi and lo
__device__ __forceinline__ void split2(float x, float y, uint32_t &hi, uint32_t &lo) {
    __nv_bfloat162 h = __floats2bfloat162_rn(x, y);
    float hx = __bfloat162float(h.x), hy = __bfloat162float(h.y);
    __nv_bfloat162 l = __floats2bfloat162_rn(x - hx, y - hy);
    hi = *reinterpret_cast<uint32_t*>(&h);
    lo = *reinterpret_cast<uint32_t*>(&l);
}

// SMEM per stage (bytes): Ah[128][40bf16]=10240 | Al @10240 | Bh[64][40]=5120 @20480 | Bl @25600
// stage = 30720 B, double-buffered = 61440 B -> 2 CTAs/SM.
#define STAGE_B   30720
#define SMEM_BYTES (2 * STAGE_B)

// ---------------- bf16x3 tensor-core GEMM: C = act(A(MxK) * Bt(NxK)^T + bias) ------
// BM=128, BN=64, BK=32; 256 threads, warp grid 4(M) x 2(N), warp tile 32x32.
// In-kernel fp32->bf16 hi/lo split; register double-buffer; 2 CTAs/SM.
template<int ACT, int HASBIAS, int SPLITK>
__global__ __launch_bounds__(256, 2) void mma_gemm(
    int M, int N, int K, int kPerZ,
    const float* __restrict__ A, const float* __restrict__ Bt,
    const float* __restrict__ bias, float* __restrict__ C)
{
    extern __shared__ __align__(16) char sm[];
    const int tid  = threadIdx.x;
    const int wid  = tid >> 5;
    const int lane = tid & 31;
    const int row0 = blockIdx.y * 128;
    const int col0 = blockIdx.x * 64;
    const int kStart = SPLITK ? blockIdx.z * kPerZ : 0;
    const int kEnd   = SPLITK ? min(kStart + kPerZ, K) : K;
    const int NS = (kEnd - kStart + 31) >> 5;
    const uint32_t smb = smem_u32(sm);

    float acc[2][4][4];
#pragma unroll
    for (int mt = 0; mt < 2; ++mt)
#pragma unroll
        for (int nt = 0; nt < 4; ++nt)
#pragma unroll
            for (int q = 0; q < 4; ++q) acc[mt][nt][q] = 0.0f;

    // A loader: thread -> row (tid>>1), 16 cols at (tid&1)*16
    const int alrow = tid >> 1;
    const int alc   = (tid & 1) * 16;
    // B loader: thread -> row (tid>>2), 8 cols at (tid&3)*8
    const int blrow = tid >> 2;
    const int blc   = (tid & 3) * 8;

    float4 pa[4], pb[2];

    auto fetch = [&](int k0) {
#pragma unroll
        for (int i = 0; i < 4; ++i) {
            int kk = k0 + alc + i * 4;
            const float* ap = A + (size_t)(row0 + alrow) * K + kk;
            float4 v;
            if (kk + 3 < kEnd) v = *(const float4*)ap;
            else {
                v.x = (kk     < kEnd) ? ap[0] : 0.0f;
                v.y = (kk + 1 < kEnd) ? ap[1] : 0.0f;
                v.z = (kk + 2 < kEnd) ? ap[2] : 0.0f;
                v.w = (kk + 3 < kEnd) ? ap[3] : 0.0f;
            }
            pa[i] = v;
        }
#pragma unroll
        for (int i = 0; i < 2; ++i) {
            int kk = k0 + blc + i * 4;
            const float* bp = Bt + (size_t)(col0 + blrow) * K + kk;
            float4 v;
            if (kk + 3 < kEnd) v = *(const float4*)bp;
            else {
                v.x = (kk     < kEnd) ? bp[0] : 0.0f;
                v.y = (kk + 1 < kEnd) ? bp[1] : 0.0f;
                v.z = (kk + 2 < kEnd) ? bp[2] : 0.0f;
                v.w = (kk + 3 < kEnd) ? bp[3] : 0.0f;
            }
            pb[i] = v;
        }
    };

    auto store_stage = [&](int b) {
        char* base = sm + b * STAGE_B;
        bf16* Ahp = (bf16*)base;
        bf16* Alp = (bf16*)(base + 10240);
        bf16* Bhp = (bf16*)(base + 20480);
        bf16* Blp = (bf16*)(base + 25600);
        uint32_t offA = (uint32_t)alrow * 40u + (uint32_t)alc;
#pragma unroll
        for (int i = 0; i < 4; ++i) {
            uint32_t h01, l01, h23, l23;
            split2(pa[i].x, pa[i].y, h01, l01);
            split2(pa[i].z, pa[i].w, h23, l23);
            *(uint2*)&Ahp[offA + i * 4] = make_uint2(h01, h23);
            *(uint2*)&Alp[offA + i * 4] = make_uint2(l01, l23);
        }
        uint32_t offB = (uint32_t)blrow * 40u + (uint32_t)blc;
#pragma unroll
        for (int i = 0; i < 2; ++i) {
            uint32_t h01, l01, h23, l23;
            split2(pb[i].x, pb[i].y, h01, l01);
            split2(pb[i].z, pb[i].w, h23, l23);
            *(uint2*)&Bhp[offB + i * 4] = make_uint2(h01, h23);
            *(uint2*)&Blp[offB + i * 4] = make_uint2(l01, l23);
        }
    };

    fetch(kStart);
    store_stage(0);
    __syncthreads();

    const int wm = wid >> 1, wn = wid & 1;
    const int arow  = wm * 32 + (lane & 15);
    const int acolB = (lane >> 4) * 16;
    const int brow  = wn * 32 + ((lane >> 4) << 3) + (lane & 7);
    const int bkhB  = ((lane >> 3) & 1) * 16;

    for (int s = 0; s < NS; ++s) {
        if (s + 1 < NS) fetch(kStart + (s + 1) * 32);

        const uint32_t stgB = (uint32_t)(s & 1) * STAGE_B;
#pragma unroll
        for (int ks = 0; ks < 2; ++ks) {
            uint32_t ah[2][4], al[2][4];
#pragma unroll
            for (int mt = 0; mt < 2; ++mt) {
                uint32_t addr = smb + stgB + (uint32_t)(arow + mt * 16) * 80u
                              + (uint32_t)ks * 32u + acolB;
                ldsm4(ah[mt], addr);
                ldsm4(al[mt], addr + 10240u);
            }
            uint32_t bh[4][2], bl[4][2];
#pragma unroll
            for (int p = 0; p < 2; ++p) {
                uint32_t addr = smb + stgB + 20480u + (uint32_t)(brow + p * 16) * 80u
                              + (uint32_t)ks * 32u + bkhB;
                uint32_t r[4];
                ldsm4(r, addr);
                bh[2*p][0] = r[0]; bh[2*p][1] = r[1];
                bh[2*p+1][0] = r[2]; bh[2*p+1][1] = r[3];
                ldsm4(r, addr + 5120u);
                bl[2*p][0] = r[0]; bl[2*p][1] = r[1];
                bl[2*p+1][0] = r[2]; bl[2*p+1][1] = r[3];
            }
#pragma unroll
            for (int mt = 0; mt < 2; ++mt)
#pragma unroll
                for (int nt = 0; nt < 4; ++nt) {
                    mma_bf16(acc[mt][nt], ah[mt], bh[nt][0], bh[nt][1]);
                    mma_bf16(acc[mt][nt], ah[mt], bl[nt][0], bl[nt][1]);
                    mma_bf16(acc[mt][nt], al[mt], bh[nt][0], bh[nt][1]);
                }
        }

        if (s + 1 < NS) {
            __syncthreads();
            store_stage((s + 1) & 1);
            __syncthreads();
        }
    }

    // ---- epilogue ----
    float* Co = SPLITK ? (C + (size_t)blockIdx.z * M * N) : C;
#pragma unroll
    for (int mt = 0; mt < 2; ++mt) {
        int r = row0 + wm * 32 + mt * 16 + (lane >> 2);
#pragma unroll
        for (int nt = 0; nt < 4; ++nt) {
            int c = col0 + wn * 32 + nt * 8 + (lane & 3) * 2;
            float b0 = 0.0f, b1 = 0.0f;
            if (HASBIAS) { b0 = bias[c]; b1 = bias[c + 1]; }
            float v0 = acc[mt][nt][0] + b0;
            float v1 = acc[mt][nt][1] + b1;
            float v2 = acc[mt][nt][2] + b0;
            float v3 = acc[mt][nt][3] + b1;
            if (ACT) {
                v0 = fmaxf(v0, 0.0f); v1 = fmaxf(v1, 0.0f);
                v2 = fmaxf(v2, 0.0f); v3 = fmaxf(v3, 0.0f);
            }
            *(float2*)&Co[(size_t)r * N + c]       = make_float2(v0, v1);
            *(float2*)&Co[(size_t)(r + 8) * N + c] = make_float2(v2, v3);
        }
    }
}

// ---------------- weight transpose: Wt[n][k] = W[k][n] ----------------
__global__ void transpose_kernel(const float* __restrict__ W, float* __restrict__ Wt,
                                 int K, int N)
{
    __shared__ float tile[32][33];
    int kb = blockIdx.y * 32, nb = blockIdx.x * 32;
    int tx = threadIdx.x, ty = threadIdx.y;   // 32 x 8
#pragma unroll
    for (int i = 0; i < 32; i += 8) {
        int k = kb + ty + i, n = nb + tx;
        tile[ty + i][tx] = (k < K && n < N) ? W[(size_t)k * N + n] : 0.0f;
    }
    __syncthreads();
#pragma unroll
    for (int i = 0; i < 32; i += 8) {
        int n = nb + ty + i, k = kb + tx;
        if (n < N && k < K) Wt[(size_t)n * K + k] = tile[tx][ty + i];
    }
}

// ---------------- small kernels ----------------
__global__ void csq_kernel(const float* __restrict__ cb) {
    int k = blockIdx.x * 256 + threadIdx.x;
    const float4* c = (const float4*)cb + k * 16;
    float s = 0.0f;
#pragma unroll
    for (int i = 0; i < 16; ++i) {
        float4 v = c[i];
        s += v.x * v.x + v.y * v.y + v.z * v.z + v.w * v.w;
    }
    g_csq[k] = s;
}

// combine split-K partials + bias, emit mean/logvar and z_e
__global__ void reparam_kernel(const float* __restrict__ eps,
                               const float* __restrict__ be3,
                               float* __restrict__ out) {
    int i = blockIdx.x * 256 + threadIdx.x;
    if (i >= T_ * D_) return;
    int t = i >> 6, d = i & 63;
    float m  = be3[d]      + g_encp[t * ENC_ + d]      + g_encp[T_*ENC_ + t * ENC_ + d];
    float lv = be3[64 + d] + g_encp[t * ENC_ + 64 + d] + g_encp[T_*ENC_ + t * ENC_ + 64 + d];
    float zv = m + expf(0.5f * lv) * eps[i];
    g_ze[i] = zv;
    out[OUT_MEAN + i] = m;
    out[OUT_LV + i]   = lv;
}

// warp per token: argmin over 1024 codes of (c_sq - 2*cross), gather, per-token loss
__global__ __launch_bounds__(256) void argmin_kernel(const float* __restrict__ cb) {
    int t    = (blockIdx.x * 256 + threadIdx.x) >> 5;
    int lane = threadIdx.x & 31;

    const float4* cr = (const float4*)g_cross + (size_t)t * 256;
    const float4* cq = (const float4*)g_csq;

    float best = 3.4e38f;
    int bestk = 0;
#pragma unroll
    for (int i = 0; i < 8; ++i) {
        int v = lane + i * 32;
        float4 c = cr[v];
        float4 q = cq[v];
        float s0 = q.x - 2.0f * c.x;
        float s1 = q.y - 2.0f * c.y;
        float s2 = q.z - 2.0f * c.z;
        float s3 = q.w - 2.0f * c.w;
        int kb = v * 4;
        if (s0 < best) { best = s0; bestk = kb;     }
        if (s1 < best) { best = s1; bestk = kb + 1; }
        if (s2 < best) { best = s2; bestk = kb + 2; }
        if (s3 < best) { best = s3; bestk = kb + 3; }
    }
#pragma unroll
    for (int off = 16; off; off >>= 1) {
        float ob = __shfl_down_sync(0xffffffffu, best, off);
        int   ok = __shfl_down_sync(0xffffffffu, bestk, off);
        if (ob < best || (ob == best && ok < bestk)) { best = ob; bestk = ok; }
    }
    bestk = __shfl_sync(0xffffffffu, bestk, 0);

    float l = 0.0f;
    if (lane < 16) {
        float4 cv = ((const float4*)cb)[bestk * 16 + lane];
        float4 zv = ((const float4*)g_ze)[t * 16 + lane];
        ((float4*)g_zq)[t * 16 + lane] = cv;
        float dx = zv.x - cv.x, dy = zv.y - cv.y;
        float dz = zv.z - cv.z, dw = zv.w - cv.w;
        l = dx * dx + dy * dy + dz * dz + dw * dw;
    }
#pragma unroll
    for (int off = 16; off; off >>= 1)
        l += __shfl_down_sync(0xffffffffu, l, off);
    if (lane == 0) g_tokloss[t] = l;
}

__global__ __launch_bounds__(256) void dec1_part_kernel(const float* __restrict__ W) {
    __shared__ __align__(16) float zs[256 * 16];
    int k0 = blockIdx.x * 256;
    for (int i = threadIdx.x; i < 4096; i += 256) {
        int b = i >> 8, kk = i & 255;
        zs[kk * 16 + b] = g_zq[b * SD_ + k0 + kk];
    }
    __syncthreads();

    int n = threadIdx.x;
    u64 acc[8];
#pragma unroll
    for (int b2 = 0; b2 < 8; ++b2) acc[b2] = 0ULL;

#pragma unroll 4
    for (int kk = 0; kk < 256; ++kk) {
        u64 wd = dupf(W[(size_t)(k0 + kk) * H2_ + n]);
        const ulonglong2* dk = (const ulonglong2*)(zs + kk * 16);
        ulonglong2 p0 = dk[0], p1 = dk[1], p2 = dk[2], p3 = dk[3];
        u64 dp[8] = {p0.x, p0.y, p1.x, p1.y, p2.x, p2.y, p3.x, p3.y};
#pragma unroll
        for (int b2 = 0; b2 < 8; ++b2) ffma2(acc[b2], dp[b2], wd);
    }
#pragma unroll
    for (int b2 = 0; b2 < 8; ++b2) {
        float2 f = unpk(acc[b2]);
        g_dpart[blockIdx.x * 4096 + (2*b2)   * H2_ + n] = f.x;
        g_dpart[blockIdx.x * 4096 + (2*b2+1) * H2_ + n] = f.y;
    }
}

__global__ void dec1_fin_kernel(const float* __restrict__ bias) {
    int n = blockIdx.x * 256 + threadIdx.x;
    float s = 0.0f;
    for (int c = 0; c < DEC1_CHUNKS; ++c) s += g_dpart[c * 4096 + n];
    g_dvec[n] = fmaxf(s + bias[n & 255], 0.0f);
}

__global__ void vqloss_kernel(float* __restrict__ out) {
    __shared__ float sb[256];
    float a = 0.0f;
    for (int i = threadIdx.x; i < T_; i += 256) a += g_tokloss[i];
    sb[threadIdx.x] = a;
    __syncthreads();
    for (int s = 128; s > 0; s >>= 1) {
        if (threadIdx.x < s) sb[threadIdx.x] += sb[threadIdx.x + s];
        __syncthreads();
    }
    if (threadIdx.x == 0) out[OUT_VQL] = sb[0] / (float)(T_ * D_);
}

__global__ __launch_bounds__(256, 2) void dec2_kernel(
    const float* __restrict__ W, const float* __restrict__ bias,
    float* __restrict__ out)
{
    __shared__ __align__(16) float ds[H2_ * 16];
    for (int i = threadIdx.x; i < 4096; i += 256) {
        int b = i >> 8, k = i & 255;
        ds[k * 16 + b] = g_dvec[i];
    }
    __syncthreads();

    int n = (blockIdx.x * 256 + threadIdx.x) * 4;
    if (n >= SF_) return;

    u64 acc[8][4];
#pragma unroll
    for (int b2 = 0; b2 < 8; ++b2)
#pragma unroll
        for (int c = 0; c < 4; ++c) acc[b2][c] = 0ULL;

#pragma unroll 4
    for (int k = 0; k < H2_; ++k) {
        float4 w = *(const float4*)(W + (size_t)k * SF_ + n);
        u64 wd[4] = {dupf(w.x), dupf(w.y), dupf(w.z), dupf(w.w)};
        const ulonglong2* dk = (const ulonglong2*)(ds + k * 16);
        ulonglong2 p0 = dk[0], p1 = dk[1], p2 = dk[2], p3 = dk[3];
        u64 dp[8] = {p0.x, p0.y, p1.x, p1.y, p2.x, p2.y, p3.x, p3.y};
#pragma unroll
        for (int b2 = 0; b2 < 8; ++b2)
#pragma unroll
            for (int c = 0; c < 4; ++c)
                ffma2(acc[b2][c], dp[b2], wd[c]);
    }

    float4 bb = *(const float4*)(bias + n);
#pragma unroll
    for (int b2 = 0; b2 < 8; ++b2) {
        float2 f0 = unpk(acc[b2][0]);
        float2 f1 = unpk(acc[b2][1]);
        float2 f2 = unpk(acc[b2][2]);
        float2 f3 = unpk(acc[b2][3]);
        float4 v0, v1;
        v0.x = softplusf(f0.x + bb.x);
        v0.y = softplusf(f1.x + bb.y);
        v0.z = softplusf(f2.x + bb.z);
        v0.w = softplusf(f3.x + bb.w);
        v1.x = softplusf(f0.y + bb.x);
        v1.y = softplusf(f1.y + bb.y);
        v1.z = softplusf(f2.y + bb.z);
        v1.w = softplusf(f3.y + bb.w);
        *(float4*)(out + (size_t)(2*b2)   * SF_ + n) = v0;
        *(float4*)(out + (size_t)(2*b2+1) * SF_ + n) = v1;
    }
}

// ---------------- launch ----------------
#define SYM(var) ({ void* _p; cudaGetSymbolAddress(&_p, var); _p; })

extern "C" void kernel_launch(void* const* d_in, const int* in_sizes, int n_in,
                              void* d_out, int out_size)
{
    const float* x   = (const float*)d_in[0];
    const float* eps = (const float*)d_in[1];
    const float* We1 = (const float*)d_in[2];
    const float* be1 = (const float*)d_in[3];
    const float* We2 = (const float*)d_in[4];
    const float* be2 = (const float*)d_in[5];
    const float* We3 = (const float*)d_in[6];
    const float* be3 = (const float*)d_in[7];
    const float* cb  = (const float*)d_in[8];
    const float* Wd1 = (const float*)d_in[9];
    const float* bd1 = (const float*)d_in[10];
    const float* Wd2 = (const float*)d_in[11];
    const float* bd2 = (const float*)d_in[12];
    float* out = (float*)d_out;

    float *h1    = (float*)SYM(g_h1);
    float *h2    = (float*)SYM(g_h2);
    float *encp  = (float*)SYM(g_encp);
    float *ze    = (float*)SYM(g_ze);
    float *cross = (float*)SYM(g_cross);
    float *wt1   = (float*)SYM(g_wt1);
    float *wt2   = (float*)SYM(g_wt2);
    float *wt3   = (float*)SYM(g_wt3);

    cudaFuncSetAttribute(mma_gemm<1,1,0>, cudaFuncAttributeMaxDynamicSharedMemorySize, SMEM_BYTES);
    cudaFuncSetAttribute(mma_gemm<0,0,0>, cudaFuncAttributeMaxDynamicSharedMemorySize, SMEM_BYTES);
    cudaFuncSetAttribute(mma_gemm<0,0,1>, cudaFuncAttributeMaxDynamicSharedMemorySize, SMEM_BYTES);

    // weight transposes (K-major operands); order so gemm1 is the 4th launch (ncu slot)
    transpose_kernel<<<dim3(16, 22), dim3(32, 8)>>>(We1, wt1, F_,  H1_);
    transpose_kernel<<<dim3(8, 16),  dim3(32, 8)>>>(We2, wt2, H1_, H2_);
    transpose_kernel<<<dim3(4, 8),   dim3(32, 8)>>>(We3, wt3, H2_, ENC_);

    // encoder MLP on tensor cores (bf16x3, BN=64, 2 CTAs/SM)
    mma_gemm<1,1,0><<<dim3(8, 72), 256, SMEM_BYTES>>>(T_, H1_, F_,  0,
        x,  wt1, be1, h1);
    csq_kernel<<<4, 256>>>(cb);
    mma_gemm<1,1,0><<<dim3(4, 72), 256, SMEM_BYTES>>>(T_, H2_, H1_, 0,
        h1, wt2, be2, h2);
    mma_gemm<0,0,1><<<dim3(2, 72, ZSPLIT), 256, SMEM_BYTES>>>(T_, ENC_, H2_, H2_/ZSPLIT,
        h2, wt3, nullptr, encp);

    reparam_kernel<<<(T_ * D_ + 255) / 256, 256>>>(eps, be3, out);

    // VQ cross = z_e @ codebook^T (codebook already [N][K] K-major)
    mma_gemm<0,0,0><<<dim3(16, 72), 256, SMEM_BYTES>>>(T_, KC_, D_, 0,
        ze, cb, nullptr, cross);
    argmin_kernel<<<T_ / 8, 256>>>(cb);

    // decoder
    dec1_part_kernel<<<DEC1_CHUNKS, 256>>>(Wd1);
    dec1_fin_kernel<<<16, 256>>>(bd1);
    vqloss_kernel<<<1, 256>>>(out);
    dec2_kernel<<<(SF_ / 4 + 255) / 256, 256>>>(Wd2, bd2, out);
}

// round 8
// speedup vs baseline: 1.1349x; 1.1162x over previous
#include <cuda_runtime.h>
#include <cuda_bf16.h>
#include <math.h>
#include <stdint.h>

// ---------------- problem constants ----------------
#define B_      16
#define S_      576
#define F_      700
#define D_      64
#define KC_     1024
#define T_      (B_*S_)         // 9216 tokens
#define H1_     512
#define H2_     256
#define ENC_    128             // 2*D
#define SF_     (S_*F_)         // 403200
#define SD_     (S_*D_)         // 36864
#define ZSPLIT  2

#define OUT_REC  0
#define OUT_MEAN (B_*SF_)
#define OUT_LV   (OUT_MEAN + T_*D_)
#define OUT_VQL  (OUT_LV + T_*D_)

#define DEC1_CHUNKS 144
#define NCB         8            // KC_/128 candidate blocks

typedef unsigned long long u64;
typedef __nv_bfloat16 bf16;

// ---------------- scratch (device globals; no allocation allowed) ----------------
__device__ __align__(256) float g_h1[T_*H1_];
__device__ __align__(256) float g_h2[T_*H2_];
__device__ __align__(256) float g_encp[ZSPLIT*T_*ENC_];
__device__ __align__(256) float g_ze[T_*D_];
__device__ __align__(256) float g_zq[T_*D_];
__device__ __align__(256) float g_csq[KC_];
__device__ __align__(256) float g_tokloss[T_];
__device__ __align__(256) float g_dpart[DEC1_CHUNKS*16*H2_];
__device__ __align__(256) float g_dvec[16*H2_];
__device__ __align__(256) float g_wt1[H1_*F_];
__device__ __align__(256) float g_wt2[H2_*H1_];
__device__ __align__(256) float g_wt3[ENC_*H2_];
__device__ __align__(256) float g_candD[NCB*T_];
__device__ __align__(256) int   g_candI[NCB*T_];

// ---------------- f32x2 helpers (decoder kernels) ----------------
__device__ __forceinline__ u64 dupf(float a) {
    unsigned r = __float_as_uint(a);
    u64 d;
    asm("mov.b64 %0, {%1, %1};" : "=l"(d) : "r"(r));
    return d;
}
__device__ __forceinline__ void ffma2(u64 &d, u64 a, u64 b) {
    asm("fma.rn.f32x2 %0, %1, %2, %0;" : "+l"(d) : "l"(a), "l"(b));
}
__device__ __forceinline__ float2 unpk(u64 v) {
    unsigned lo, hi;
    asm("mov.b64 {%0, %1}, %2;" : "=r"(lo), "=r"(hi) : "l"(v));
    return make_float2(__uint_as_float(lo), __uint_as_float(hi));
}
__device__ __forceinline__ float softplusf(float x) {
    return fmaxf(x, 0.0f) + log1pf(expf(-fabsf(x)));
}

// ---------------- mma.sync helpers ----------------
__device__ __forceinline__ uint32_t smem_u32(const void* p) {
    uint32_t a;
    asm("{ .reg .u64 t; cvta.to.shared.u64 t, %1; cvt.u32.u64 %0, t; }" : "=r"(a) : "l"(p));
    return a;
}
__device__ __forceinline__ void ldsm4(uint32_t (&r)[4], uint32_t addr) {
    asm volatile("ldmatrix.sync.aligned.m8n8.x4.shared.b16 {%0,%1,%2,%3}, [%4];"
                 : "=r"(r[0]), "=r"(r[1]), "=r"(r[2]), "=r"(r[3]) : "r"(addr));
}
__device__ __forceinline__ void mma_bf16(float (&d)[4], const uint32_t (&a)[4],
                                         uint32_t b0, uint32_t b1) {
    asm volatile("mma.sync.aligned.m16n8k16.row.col.f32.bf16.bf16.f32 "
                 "{%0,%1,%2,%3}, {%4,%5,%6,%7}, {%8,%9}, {%0,%1,%2,%3};"
                 : "+f"(d[0]), "+f"(d[1]), "+f"(d[2]), "+f"(d[3])
                 : "r"(a[0]), "r"(a[1]), "r"(a[2]), "r"(a[3]), "r"(b0), "r"(b1));
}
// split fp32 pair -> packed bf16x2 hi and lo
__device__ __forceinline__ void split2(float x, float y, uint32_t &hi, uint32_t &lo) {
    __nv_bfloat162 h = __floats2bfloat162_rn(x, y);
    float hx = __bfloat162float(h.x), hy = __bfloat162float(h.y);
    __nv_bfloat162 l = __floats2bfloat162_rn(x - hx, y - hy);
    hi = *reinterpret_cast<uint32_t*>(&h);
    lo = *reinterpret_cast<uint32_t*>(&l);
}

// SMEM layout (bf16 elems), per stage of 20480 elems (40960 B):
//   Ah: [128][40] pad rows (5120)   Al: +5120   Bh: +10240   Bl: +15360
#define STAGE_E   20480
#define SMEM_BYTES (2 * STAGE_E * 2)

// ---------------- bf16x3 tensor-core GEMM (round-4 config) -----------------------
// C = act(A(MxK) * Bt(NxK)^T + bias); in-kernel hi/lo split; reg double-buffer.
// BM=128, BN=128, BK=32; 256 threads, warp grid 4(M) x 2(N), warp tile 32x64.
// MODE 1: relu+bias fp32 out.  MODE 2: split-K raw partials.  MODE 4: VQ argmin
//   (bias = csq; emits per-token (dist,idx) candidate for this 128-code block).
template<int MODE>
__global__ __launch_bounds__(256, 1) void mma_gemm(
    int M, int N, int K, int kPerZ,
    const float* __restrict__ A, const float* __restrict__ Bt,
    const float* __restrict__ bias, float* __restrict__ C,
    float* __restrict__ candD, int* __restrict__ candI)
{
    extern __shared__ __align__(16) __nv_bfloat16 sm[];
    const int tid  = threadIdx.x;
    const int wid  = tid >> 5;
    const int lane = tid & 31;
    const int row0 = blockIdx.y * 128;
    const int col0 = blockIdx.x * 128;
    const int kStart = (MODE == 2) ? blockIdx.z * kPerZ : 0;
    const int kEnd   = (MODE == 2) ? min(kStart + kPerZ, K) : K;
    const int NS = (kEnd - kStart + 31) >> 5;
    const uint32_t smb = smem_u32(sm);

    float acc[2][8][4];
#pragma unroll
    for (int mt = 0; mt < 2; ++mt)
#pragma unroll
        for (int nt = 0; nt < 8; ++nt)
#pragma unroll
            for (int q = 0; q < 4; ++q) acc[mt][nt][q] = 0.0f;

    const int lrow = tid >> 3;        // 0..31 base row (with +32*i)
    const int lc4  = tid & 7;         // float4 col within BK

    float4 pa[4], pb[4];

    // ---- prefetch stage 0 ----
    {
        int k0 = kStart;
#pragma unroll
        for (int i = 0; i < 4; ++i) {
            int row = lrow + i * 32;
            int kk  = k0 + lc4 * 4;
            if (kk < kEnd) {
                pa[i] = *(const float4*)(A  + (size_t)(row0 + row) * K + kk);
                pb[i] = *(const float4*)(Bt + (size_t)(col0 + row) * K + kk);
            } else {
                pa[i] = make_float4(0.f, 0.f, 0.f, 0.f);
                pb[i] = make_float4(0.f, 0.f, 0.f, 0.f);
            }
        }
    }
    // ---- store stage 0 ----
    {
        uint32_t stg = 0;
#pragma unroll
        for (int i = 0; i < 4; ++i) {
            int row = lrow + i * 32;
            uint32_t off = stg + row * 40 + lc4 * 4;
            uint32_t h0, l0, h1, l1;
            split2(pa[i].x, pa[i].y, h0, l0);
            split2(pa[i].z, pa[i].w, h1, l1);
            *(uint2*)&sm[off]          = make_uint2(h0, h1);
            *(uint2*)&sm[off + 5120]   = make_uint2(l0, l1);
            split2(pb[i].x, pb[i].y, h0, l0);
            split2(pb[i].z, pb[i].w, h1, l1);
            *(uint2*)&sm[off + 10240]  = make_uint2(h0, h1);
            *(uint2*)&sm[off + 15360]  = make_uint2(l0, l1);
        }
    }
    __syncthreads();

    const int wm = wid >> 1, wn = wid & 1;
    const int arow  = wm * 32 + (lane & 15);
    const int acolB = (lane >> 4) * 16;
    const int brow  = wn * 64 + ((lane >> 4) << 3) + (lane & 7);
    const int bkhB  = ((lane >> 3) & 1) * 16;

    for (int s = 0; s < NS; ++s) {
        if (s + 1 < NS) {
            int k0 = kStart + (s + 1) * 32;
#pragma unroll
            for (int i = 0; i < 4; ++i) {
                int row = lrow + i * 32;
                int kk  = k0 + lc4 * 4;
                if (kk < kEnd) {
                    pa[i] = *(const float4*)(A  + (size_t)(row0 + row) * K + kk);
                    pb[i] = *(const float4*)(Bt + (size_t)(col0 + row) * K + kk);
                } else {
                    pa[i] = make_float4(0.f, 0.f, 0.f, 0.f);
                    pb[i] = make_float4(0.f, 0.f, 0.f, 0.f);
                }
            }
        }

        const uint32_t stgB = (uint32_t)(s & 1) * (STAGE_E * 2);
#pragma unroll
        for (int ks = 0; ks < 2; ++ks) {
            uint32_t ah[2][4], al[2][4];
#pragma unroll
            for (int mt = 0; mt < 2; ++mt) {
                uint32_t addr = smb + stgB + (uint32_t)(arow + mt * 16) * 80u
                              + (uint32_t)ks * 32u + acolB;
                ldsm4(ah[mt], addr);
                ldsm4(al[mt], addr + 10240u);
            }
            uint32_t bh[8][2], bl[8][2];
#pragma unroll
            for (int p = 0; p < 4; ++p) {
                uint32_t addr = smb + stgB + 20480u + (uint32_t)(brow + p * 16) * 80u
                              + (uint32_t)ks * 32u + bkhB;
                uint32_t r[4];
                ldsm4(r, addr);
                bh[2*p][0] = r[0]; bh[2*p][1] = r[1];
                bh[2*p+1][0] = r[2]; bh[2*p+1][1] = r[3];
                ldsm4(r, addr + 10240u);
                bl[2*p][0] = r[0]; bl[2*p][1] = r[1];
                bl[2*p+1][0] = r[2]; bl[2*p+1][1] = r[3];
            }
#pragma unroll
            for (int mt = 0; mt < 2; ++mt)
#pragma unroll
                for (int nt = 0; nt < 8; ++nt) {
                    mma_bf16(acc[mt][nt], ah[mt], bh[nt][0], bh[nt][1]);
                    mma_bf16(acc[mt][nt], ah[mt], bl[nt][0], bl[nt][1]);
                    mma_bf16(acc[mt][nt], al[mt], bh[nt][0], bh[nt][1]);
                }
        }

        if (s + 1 < NS) {
            __syncthreads();
            uint32_t stg = (uint32_t)((s + 1) & 1) * STAGE_E;
#pragma unroll
            for (int i = 0; i < 4; ++i) {
                int row = lrow + i * 32;
                uint32_t off = stg + row * 40 + lc4 * 4;
                uint32_t h0, l0, h1, l1;
                split2(pa[i].x, pa[i].y, h0, l0);
                split2(pa[i].z, pa[i].w, h1, l1);
                *(uint2*)&sm[off]          = make_uint2(h0, h1);
                *(uint2*)&sm[off + 5120]   = make_uint2(l0, l1);
                split2(pb[i].x, pb[i].y, h0, l0);
                split2(pb[i].z, pb[i].w, h1, l1);
                *(uint2*)&sm[off + 10240]  = make_uint2(h0, h1);
                *(uint2*)&sm[off + 15360]  = make_uint2(l0, l1);
            }
            __syncthreads();
        }
    }

    // ---- epilogue ----
    if (MODE == 4) {
        // distance argmin over this CTA's 128 codes, per token row
        __syncthreads();                            // smem free for overlay
        float* sd = (float*)sm;                     // [2][128]
        int*   si = (int*)(sm + 1024);              // after 2 KB (1024 bf16)

        float2 cs[8];
#pragma unroll
        for (int nt = 0; nt < 8; ++nt)
            cs[nt] = *(const float2*)&bias[col0 + wn * 64 + nt * 8 + (lane & 3) * 2];

#pragma unroll
        for (int mt = 0; mt < 2; ++mt) {
#pragma unroll
            for (int rp = 0; rp < 2; ++rp) {
                float best = 3.4e38f; int bidx = 0;
#pragma unroll
                for (int nt = 0; nt < 8; ++nt) {
                    int c = col0 + wn * 64 + nt * 8 + (lane & 3) * 2;
                    float d0 = cs[nt].x - 2.0f * acc[mt][nt][rp * 2 + 0];
                    float d1 = cs[nt].y - 2.0f * acc[mt][nt][rp * 2 + 1];
                    if (d0 < best) { best = d0; bidx = c;     }
                    if (d1 < best) { best = d1; bidx = c + 1; }
                }
#pragma unroll
                for (int msk = 1; msk <= 2; msk <<= 1) {
                    float od = __shfl_xor_sync(0xffffffffu, best, msk);
                    int   oi = __shfl_xor_sync(0xffffffffu, bidx, msk);
                    if (od < best || (od == best && oi < bidx)) { best = od; bidx = oi; }
                }
                if ((lane & 3) == 0) {
                    int rl = wm * 32 + mt * 16 + rp * 8 + (lane >> 2);
                    sd[wn * 128 + rl] = best;
                    si[wn * 128 + rl] = bidx;
                }
            }
        }
        __syncthreads();
        if (tid < 128) {
            float d0 = sd[tid], d1 = sd[128 + tid];
            int   i0 = si[tid], i1 = si[128 + tid];
            bool t1 = (d1 < d0) || (d1 == d0 && i1 < i0);
            candD[(size_t)blockIdx.x * M + row0 + tid] = t1 ? d1 : d0;
            candI[(size_t)blockIdx.x * M + row0 + tid] = t1 ? i1 : i0;
        }
        return;
    }

    float* Co = (MODE == 2) ? (C + (size_t)blockIdx.z * M * N) : C;
#pragma unroll
    for (int mt = 0; mt < 2; ++mt) {
        int r = row0 + wm * 32 + mt * 16 + (lane >> 2);
#pragma unroll
        for (int nt = 0; nt < 8; ++nt) {
            int c = col0 + wn * 64 + nt * 8 + (lane & 3) * 2;
            float b0 = 0.0f, b1 = 0.0f;
            if (MODE == 1) { b0 = bias[c]; b1 = bias[c + 1]; }
            float v0 = acc[mt][nt][0] + b0;
            float v1 = acc[mt][nt][1] + b1;
            float v2 = acc[mt][nt][2] + b0;
            float v3 = acc[mt][nt][3] + b1;
            if (MODE == 1) {
                v0 = fmaxf(v0, 0.0f); v1 = fmaxf(v1, 0.0f);
                v2 = fmaxf(v2, 0.0f); v3 = fmaxf(v3, 0.0f);
            }
            *(float2*)&Co[(size_t)r * N + c]       = make_float2(v0, v1);
            *(float2*)&Co[(size_t)(r + 8) * N + c] = make_float2(v2, v3);
        }
    }
}

// ---------------- weight transpose: Wt[n][k] = W[k][n] ----------------
__global__ void transpose_kernel(const float* __restrict__ W, float* __restrict__ Wt,
                                 int K, int N)
{
    __shared__ float tile[32][33];
    int kb = blockIdx.y * 32, nb = blockIdx.x * 32;
    int tx = threadIdx.x, ty = threadIdx.y;   // 32 x 8
#pragma unroll
    for (int i = 0; i < 32; i += 8) {
        int k = kb + ty + i, n = nb + tx;
        tile[ty + i][tx] = (k < K && n < N) ? W[(size_t)k * N + n] : 0.0f;
    }
    __syncthreads();
#pragma unroll
    for (int i = 0; i < 32; i += 8) {
        int n = nb + ty + i, k = kb + tx;
        if (n < N && k < K) Wt[(size_t)n * K + k] = tile[tx][ty + i];
    }
}

// ---------------- small kernels ----------------
__global__ void csq_kernel(const float* __restrict__ cb) {
    int k = blockIdx.x * 256 + threadIdx.x;
    const float4* c = (const float4*)cb + k * 16;
    float s = 0.0f;
#pragma unroll
    for (int i = 0; i < 16; ++i) {
        float4 v = c[i];
        s += v.x * v.x + v.y * v.y + v.z * v.z + v.w * v.w;
    }
    g_csq[k] = s;
}

// combine split-K partials + bias, emit mean/logvar and z_e
__global__ void reparam_kernel(const float* __restrict__ eps,
                               const float* __restrict__ be3,
                               float* __restrict__ out) {
    int i = blockIdx.x * 256 + threadIdx.x;
    if (i >= T_ * D_) return;
    int t = i >> 6, d = i & 63;
    float m  = be3[d]      + g_encp[t * ENC_ + d]      + g_encp[T_*ENC_ + t * ENC_ + d];
    float lv = be3[64 + d] + g_encp[t * ENC_ + 64 + d] + g_encp[T_*ENC_ + t * ENC_ + 64 + d];
    float zv = m + expf(0.5f * lv) * eps[i];
    g_ze[i] = zv;
    out[OUT_MEAN + i] = m;
    out[OUT_LV + i]   = lv;
}

// final VQ: reduce 8 block candidates per token, gather code, per-token loss
__global__ __launch_bounds__(256) void vq_finish_kernel(const float* __restrict__ cb) {
    int t    = (blockIdx.x * 256 + threadIdx.x) >> 5;
    int lane = threadIdx.x & 31;

    float d = 3.4e38f; int ix = 0x7fffffff;
    if (lane < NCB) {
        d  = g_candD[(size_t)lane * T_ + t];
        ix = g_candI[(size_t)lane * T_ + t];
    }
#pragma unroll
    for (int off = 4; off; off >>= 1) {
        float od = __shfl_down_sync(0xffffffffu, d, off);
        int   oi = __shfl_down_sync(0xffffffffu, ix, off);
        if (od < d || (od == d && oi < ix)) { d = od; ix = oi; }
    }
    ix = __shfl_sync(0xffffffffu, ix, 0);

    float l = 0.0f;
    if (lane < 16) {
        float4 cv = ((const float4*)cb)[ix * 16 + lane];
        float4 zv = ((const float4*)g_ze)[t * 16 + lane];
        ((float4*)g_zq)[t * 16 + lane] = cv;
        float dx = zv.x - cv.x, dy = zv.y - cv.y;
        float dz = zv.z - cv.z, dw = zv.w - cv.w;
        l = dx * dx + dy * dy + dz * dz + dw * dw;
    }
#pragma unroll
    for (int off = 16; off; off >>= 1)
        l += __shfl_down_sync(0xffffffffu, l, off);
    if (lane == 0) g_tokloss[t] = l;
}

__global__ __launch_bounds__(256) void dec1_part_kernel(const float* __restrict__ W) {
    __shared__ __align__(16) float zs[256 * 16];
    int k0 = blockIdx.x * 256;
    for (int i = threadIdx.x; i < 4096; i += 256) {
        int b = i >> 8, kk = i & 255;
        zs[kk * 16 + b] = g_zq[b * SD_ + k0 + kk];
    }
    __syncthreads();

    int n = threadIdx.x;
    u64 acc[8];
#pragma unroll
    for (int b2 = 0; b2 < 8; ++b2) acc[b2] = 0ULL;

#pragma unroll 4
    for (int kk = 0; kk < 256; ++kk) {
        u64 wd = dupf(W[(size_t)(k0 + kk) * H2_ + n]);
        const ulonglong2* dk = (const ulonglong2*)(zs + kk * 16);
        ulonglong2 p0 = dk[0], p1 = dk[1], p2 = dk[2], p3 = dk[3];
        u64 dp[8] = {p0.x, p0.y, p1.x, p1.y, p2.x, p2.y, p3.x, p3.y};
#pragma unroll
        for (int b2 = 0; b2 < 8; ++b2) ffma2(acc[b2], dp[b2], wd);
    }
#pragma unroll
    for (int b2 = 0; b2 < 8; ++b2) {
        float2 f = unpk(acc[b2]);
        g_dpart[blockIdx.x * 4096 + (2*b2)   * H2_ + n] = f.x;
        g_dpart[blockIdx.x * 4096 + (2*b2+1) * H2_ + n] = f.y;
    }
}

__global__ void dec1_fin_kernel(const float* __restrict__ bias) {
    int n = blockIdx.x * 256 + threadIdx.x;
    float s = 0.0f;
    for (int c = 0; c < DEC1_CHUNKS; ++c) s += g_dpart[c * 4096 + n];
    g_dvec[n] = fmaxf(s + bias[n & 255], 0.0f);
}

__global__ void vqloss_kernel(float* __restrict__ out) {
    __shared__ float sb[256];
    float a = 0.0f;
    for (int i = threadIdx.x; i < T_; i += 256) a += g_tokloss[i];
    sb[threadIdx.x] = a;
    __syncthreads();
    for (int s = 128; s > 0; s >>= 1) {
        if (threadIdx.x < s) sb[threadIdx.x] += sb[threadIdx.x + s];
        __syncthreads();
    }
    if (threadIdx.x == 0) out[OUT_VQL] = sb[0] / (float)(T_ * D_);
}

__global__ __launch_bounds__(256, 2) void dec2_kernel(
    const float* __restrict__ W, const float* __restrict__ bias,
    float* __restrict__ out)
{
    __shared__ __align__(16) float ds[H2_ * 16];
    for (int i = threadIdx.x; i < 4096; i += 256) {
        int b = i >> 8, k = i & 255;
        ds[k * 16 + b] = g_dvec[i];
    }
    __syncthreads();

    int n = (blockIdx.x * 256 + threadIdx.x) * 4;
    if (n >= SF_) return;

    u64 acc[8][4];
#pragma unroll
    for (int b2 = 0; b2 < 8; ++b2)
#pragma unroll
        for (int c = 0; c < 4; ++c) acc[b2][c] = 0ULL;

#pragma unroll 4
    for (int k = 0; k < H2_; ++k) {
        float4 w = *(const float4*)(W + (size_t)k * SF_ + n);
        u64 wd[4] = {dupf(w.x), dupf(w.y), dupf(w.z), dupf(w.w)};
        const ulonglong2* dk = (const ulonglong2*)(ds + k * 16);
        ulonglong2 p0 = dk[0], p1 = dk[1], p2 = dk[2], p3 = dk[3];
        u64 dp[8] = {p0.x, p0.y, p1.x, p1.y, p2.x, p2.y, p3.x, p3.y};
#pragma unroll
        for (int b2 = 0; b2 < 8; ++b2)
#pragma unroll
            for (int c = 0; c < 4; ++c)
                ffma2(acc[b2][c], dp[b2], wd[c]);
    }

    float4 bb = *(const float4*)(bias + n);
#pragma unroll
    for (int b2 = 0; b2 < 8; ++b2) {
        float2 f0 = unpk(acc[b2][0]);
        float2 f1 = unpk(acc[b2][1]);
        float2 f2 = unpk(acc[b2][2]);
        float2 f3 = unpk(acc[b2][3]);
        float4 v0, v1;
        v0.x = softplusf(f0.x + bb.x);
        v0.y = softplusf(f1.x + bb.y);
        v0.z = softplusf(f2.x + bb.z);
        v0.w = softplusf(f3.x + bb.w);
        v1.x = softplusf(f0.y + bb.x);
        v1.y = softplusf(f1.y + bb.y);
        v1.z = softplusf(f2.y + bb.z);
        v1.w = softplusf(f3.y + bb.w);
        *(float4*)(out + (size_t)(2*b2)   * SF_ + n) = v0;
        *(float4*)(out + (size_t)(2*b2+1) * SF_ + n) = v1;
    }
}

// ---------------- launch ----------------
#define SYM(var) ({ void* _p; cudaGetSymbolAddress(&_p, var); _p; })

extern "C" void kernel_launch(void* const* d_in, const int* in_sizes, int n_in,
                              void* d_out, int out_size)
{
    const float* x   = (const float*)d_in[0];
    const float* eps = (const float*)d_in[1];
    const float* We1 = (const float*)d_in[2];
    const float* be1 = (const float*)d_in[3];
    const float* We2 = (const float*)d_in[4];
    const float* be2 = (const float*)d_in[5];
    const float* We3 = (const float*)d_in[6];
    const float* be3 = (const float*)d_in[7];
    const float* cb  = (const float*)d_in[8];
    const float* Wd1 = (const float*)d_in[9];
    const float* bd1 = (const float*)d_in[10];
    const float* Wd2 = (const float*)d_in[11];
    const float* bd2 = (const float*)d_in[12];
    float* out = (float*)d_out;

    float *h1    = (float*)SYM(g_h1);
    float *h2    = (float*)SYM(g_h2);
    float *encp  = (float*)SYM(g_encp);
    float *ze    = (float*)SYM(g_ze);
    float *wt1   = (float*)SYM(g_wt1);
    float *wt2   = (float*)SYM(g_wt2);
    float *wt3   = (float*)SYM(g_wt3);
    float *csq   = (float*)SYM(g_csq);
    float *candD = (float*)SYM(g_candD);
    int   *candI = (int*)SYM(g_candI);

    cudaFuncSetAttribute(mma_gemm<1>, cudaFuncAttributeMaxDynamicSharedMemorySize, SMEM_BYTES);
    cudaFuncSetAttribute(mma_gemm<2>, cudaFuncAttributeMaxDynamicSharedMemorySize, SMEM_BYTES);
    cudaFuncSetAttribute(mma_gemm<4>, cudaFuncAttributeMaxDynamicSharedMemorySize, SMEM_BYTES);

    // weight transposes (gemm1 stays the 4th launch = ncu slot)
    transpose_kernel<<<dim3(16, 22), dim3(32, 8)>>>(We1, wt1, F_,  H1_);
    transpose_kernel<<<dim3(8, 16),  dim3(32, 8)>>>(We2, wt2, H1_, H2_);
    transpose_kernel<<<dim3(4, 8),   dim3(32, 8)>>>(We3, wt3, H2_, ENC_);

    // encoder MLP on tensor cores (bf16x3, round-4 config)
    mma_gemm<1><<<dim3(4, 72), 256, SMEM_BYTES>>>(T_, H1_, F_,  0,
        x,  wt1, be1, h1, nullptr, nullptr);
    csq_kernel<<<4, 256>>>(cb);
    mma_gemm<1><<<dim3(2, 72), 256, SMEM_BYTES>>>(T_, H2_, H1_, 0,
        h1, wt2, be2, h2, nullptr, nullptr);
    mma_gemm<2><<<dim3(1, 72, ZSPLIT), 256, SMEM_BYTES>>>(T_, ENC_, H2_, H2_/ZSPLIT,
        h2, wt3, nullptr, encp, nullptr, nullptr);

    reparam_kernel<<<(T_ * D_ + 255) / 256, 256>>>(eps, be3, out);

    // fused VQ: cross GEMM + per-block argmin (no g_cross materialization)
    mma_gemm<4><<<dim3(NCB, 72), 256, SMEM_BYTES>>>(T_, KC_, D_, 0,
        ze, cb, csq, nullptr, candD, candI);
    vq_finish_kernel<<<T_ / 8, 256>>>(cb);

    // decoder
    dec1_part_kernel<<<DEC1_CHUNKS, 256>>>(Wd1);
    dec1_fin_kernel<<<16, 256>>>(bd1);
    vqloss_kernel<<<1, 256>>>(out);
    dec2_kernel<<<(SF_ / 4 + 255) / 256, 256>>>(Wd2, bd2, out);
}

// round 9
// speedup vs baseline: 1.1473x; 1.0109x over previous
#include <cuda_runtime.h>
#include <cuda_bf16.h>
#include <math.h>
#include <stdint.h>

// ---------------- problem constants ----------------
#define B_      16
#define S_      576
#define F_      700
#define D_      64
#define KC_     1024
#define T_      (B_*S_)         // 9216 tokens
#define H1_     512
#define H2_     256
#define ENC_    128             // 2*D
#define SF_     (S_*F_)         // 403200
#define SD_     (S_*D_)         // 36864
#define ZSPLIT  2

#define OUT_REC  0
#define OUT_MEAN (B_*SF_)
#define OUT_LV   (OUT_MEAN + T_*D_)
#define OUT_VQL  (OUT_LV + T_*D_)

#define DEC1_CHUNKS 144
#define NCB         8            // KC_/128 candidate blocks

typedef unsigned long long u64;
typedef __nv_bfloat16 bf16;

// ---------------- scratch (device globals; no allocation allowed) ----------------
__device__ __align__(256) float g_h1[T_*H1_];
__device__ __align__(256) float g_h2[T_*H2_];
__device__ __align__(256) float g_encp[ZSPLIT*T_*ENC_];
__device__ __align__(256) float g_ze[T_*D_];
__device__ __align__(256) float g_zq[T_*D_];
__device__ __align__(256) float g_csq[KC_];
__device__ __align__(256) float g_tokloss[T_];
__device__ __align__(256) float g_dpart[DEC1_CHUNKS*16*H2_];
__device__ __align__(256) float g_dvec[16*H2_];
__device__ __align__(256) float g_wt1[H1_*F_];
__device__ __align__(256) float g_wt2[H2_*H1_];
__device__ __align__(256) float g_wt3[ENC_*H2_];
__device__ __align__(256) float g_candD[NCB*T_];
__device__ __align__(256) int   g_candI[NCB*T_];

// ---------------- f32x2 helpers (decoder kernels) ----------------
__device__ __forceinline__ u64 dupf(float a) {
    unsigned r = __float_as_uint(a);
    u64 d;
    asm("mov.b64 %0, {%1, %1};" : "=l"(d) : "r"(r));
    return d;
}
__device__ __forceinline__ void ffma2(u64 &d, u64 a, u64 b) {
    asm("fma.rn.f32x2 %0, %1, %2, %0;" : "+l"(d) : "l"(a), "l"(b));
}
__device__ __forceinline__ float2 unpk(u64 v) {
    unsigned lo, hi;
    asm("mov.b64 {%0, %1}, %2;" : "=r"(lo), "=r"(hi) : "l"(v));
    return make_float2(__uint_as_float(lo), __uint_as_float(hi));
}
__device__ __forceinline__ float softplusf(float x) {
    return fmaxf(x, 0.0f) + log1pf(expf(-fabsf(x)));
}

// ---------------- mma.sync helpers ----------------
__device__ __forceinline__ uint32_t smem_u32(const void* p) {
    uint32_t a;
    asm("{ .reg .u64 t; cvta.to.shared.u64 t, %1; cvt.u32.u64 %0, t; }" : "=r"(a) : "l"(p));
    return a;
}
__device__ __forceinline__ void ldsm4(uint32_t (&r)[4], uint32_t addr) {
    asm volatile("ldmatrix.sync.aligned.m8n8.x4.shared.b16 {%0,%1,%2,%3}, [%4];"
                 : "=r"(r[0]), "=r"(r[1]), "=r"(r[2]), "=r"(r[3]) : "r"(addr));
}
__device__ __forceinline__ void mma_bf16(float (&d)[4], const uint32_t (&a)[4],
                                         uint32_t b0, uint32_t b1) {
    asm volatile("mma.sync.aligned.m16n8k16.row.col.f32.bf16.bf16.f32 "
                 "{%0,%1,%2,%3}, {%4,%5,%6,%7}, {%8,%9}, {%0,%1,%2,%3};"
                 : "+f"(d[0]), "+f"(d[1]), "+f"(d[2]), "+f"(d[3])
                 : "r"(a[0]), "r"(a[1]), "r"(a[2]), "r"(a[3]), "r"(b0), "r"(b1));
}
// split fp32 pair -> packed bf16x2 hi and lo
__device__ __forceinline__ void split2(float x, float y, uint32_t &hi, uint32_t &lo) {
    __nv_bfloat162 h = __floats2bfloat162_rn(x, y);
    float hx = __bfloat162float(h.x), hy = __bfloat162float(h.y);
    __nv_bfloat162 l = __floats2bfloat162_rn(x - hx, y - hy);
    hi = *reinterpret_cast<uint32_t*>(&h);
    lo = *reinterpret_cast<uint32_t*>(&l);
}

// SMEM per stage: 20480 bf16 elems (40960 B): Ah[128][40] | Al +5120 | Bh +10240 | Bl +15360
// 3 buffers (single sync per stage) = 122880 B
#define STAGE_E   20480
#define NSTG      3
#define SMEM_BYTES (NSTG * STAGE_E * 2)

// ---------------- bf16x3 tensor-core GEMM, 3-buffer single-sync pipeline ---------
// C = act(A(MxK) * Bt(NxK)^T + bias); in-kernel hi/lo split.
// BM=128, BN=128, BK=32; 256 threads, warp grid 4(M) x 2(N), warp tile 32x64.
// MODE 1: relu+bias fp32 out.  MODE 2: split-K raw partials.  MODE 4: VQ argmin.
template<int MODE>
__global__ __launch_bounds__(256, 1) void mma_gemm(
    int M, int N, int K, int kPerZ,
    const float* __restrict__ A, const float* __restrict__ Bt,
    const float* __restrict__ bias, float* __restrict__ C,
    float* __restrict__ candD, int* __restrict__ candI)
{
    extern __shared__ __align__(16) __nv_bfloat16 sm[];
    const int tid  = threadIdx.x;
    const int wid  = tid >> 5;
    const int lane = tid & 31;
    const int row0 = blockIdx.y * 128;
    const int col0 = blockIdx.x * 128;
    const int kStart = (MODE == 2) ? blockIdx.z * kPerZ : 0;
    const int kEnd   = (MODE == 2) ? min(kStart + kPerZ, K) : K;
    const int NS = (kEnd - kStart + 31) >> 5;
    const uint32_t smb = smem_u32(sm);

    float acc[2][8][4];
#pragma unroll
    for (int mt = 0; mt < 2; ++mt)
#pragma unroll
        for (int nt = 0; nt < 8; ++nt)
#pragma unroll
            for (int q = 0; q < 4; ++q) acc[mt][nt][q] = 0.0f;

    const int lrow = tid >> 3;        // 0..31 base row (with +32*i)
    const int lc4  = tid & 7;         // float4 col within BK

    float4 pa[4], pb[4];

    auto fetch = [&](int k0) {
#pragma unroll
        for (int i = 0; i < 4; ++i) {
            int row = lrow + i * 32;
            int kk  = k0 + lc4 * 4;
            if (kk < kEnd) {
                pa[i] = *(const float4*)(A  + (size_t)(row0 + row) * K + kk);
                pb[i] = *(const float4*)(Bt + (size_t)(col0 + row) * K + kk);
            } else {
                pa[i] = make_float4(0.f, 0.f, 0.f, 0.f);
                pb[i] = make_float4(0.f, 0.f, 0.f, 0.f);
            }
        }
    };

    auto store_to = [&](int slot) {
        uint32_t stg = (uint32_t)slot * STAGE_E;
#pragma unroll
        for (int i = 0; i < 4; ++i) {
            int row = lrow + i * 32;
            uint32_t off = stg + row * 40 + lc4 * 4;
            uint32_t h0, l0, h1, l1;
            split2(pa[i].x, pa[i].y, h0, l0);
            split2(pa[i].z, pa[i].w, h1, l1);
            *(uint2*)&sm[off]          = make_uint2(h0, h1);
            *(uint2*)&sm[off + 5120]   = make_uint2(l0, l1);
            split2(pb[i].x, pb[i].y, h0, l0);
            split2(pb[i].z, pb[i].w, h1, l1);
            *(uint2*)&sm[off + 10240]  = make_uint2(h0, h1);
            *(uint2*)&sm[off + 15360]  = make_uint2(l0, l1);
        }
    };

    const int wm = wid >> 1, wn = wid & 1;
    const int arow  = wm * 32 + (lane & 15);
    const int acolB = (lane >> 4) * 16;
    const int brow  = wn * 64 + ((lane >> 4) << 3) + (lane & 7);
    const int bkhB  = ((lane >> 3) & 1) * 16;

    auto compute = [&](int slot) {
        const uint32_t stgB = (uint32_t)slot * (STAGE_E * 2);
#pragma unroll
        for (int ks = 0; ks < 2; ++ks) {
            uint32_t ah[2][4], al[2][4];
#pragma unroll
            for (int mt = 0; mt < 2; ++mt) {
                uint32_t addr = smb + stgB + (uint32_t)(arow + mt * 16) * 80u
                              + (uint32_t)ks * 32u + acolB;
                ldsm4(ah[mt], addr);
                ldsm4(al[mt], addr + 10240u);
            }
            uint32_t bh[8][2], bl[8][2];
#pragma unroll
            for (int p = 0; p < 4; ++p) {
                uint32_t addr = smb + stgB + 20480u + (uint32_t)(brow + p * 16) * 80u
                              + (uint32_t)ks * 32u + bkhB;
                uint32_t r[4];
                ldsm4(r, addr);
                bh[2*p][0] = r[0]; bh[2*p][1] = r[1];
                bh[2*p+1][0] = r[2]; bh[2*p+1][1] = r[3];
                ldsm4(r, addr + 10240u);
                bl[2*p][0] = r[0]; bl[2*p][1] = r[1];
                bl[2*p+1][0] = r[2]; bl[2*p+1][1] = r[3];
            }
#pragma unroll
            for (int mt = 0; mt < 2; ++mt)
#pragma unroll
                for (int nt = 0; nt < 8; ++nt) {
                    mma_bf16(acc[mt][nt], ah[mt], bh[nt][0], bh[nt][1]);
                    mma_bf16(acc[mt][nt], ah[mt], bl[nt][0], bl[nt][1]);
                    mma_bf16(acc[mt][nt], al[mt], bh[nt][0], bh[nt][1]);
                }
        }
    };

    // prologue: stage 0 stored, stage 1 fetched into regs
    fetch(kStart);
    store_to(0);
    if (NS > 1) fetch(kStart + 32);

    int scur = 0, sst = 1;
    for (int s = 0; s < NS; ++s) {
        __syncthreads();
        if (s + 1 < NS) store_to(sst);
        if (s + 2 < NS) fetch(kStart + (s + 2) * 32);
        compute(scur);
        scur = (scur + 1 == NSTG) ? 0 : scur + 1;
        sst  = (sst  + 1 == NSTG) ? 0 : sst  + 1;
    }

    // ---- epilogue ----
    if (MODE == 4) {
        // distance argmin over this CTA's 128 codes, per token row
        __syncthreads();                            // smem free for overlay
        float* sd = (float*)sm;                     // [2][128]
        int*   si = (int*)(sm + 1024);              // after 2 KB

        float2 cs[8];
#pragma unroll
        for (int nt = 0; nt < 8; ++nt)
            cs[nt] = *(const float2*)&bias[col0 + wn * 64 + nt * 8 + (lane & 3) * 2];

#pragma unroll
        for (int mt = 0; mt < 2; ++mt) {
#pragma unroll
            for (int rp = 0; rp < 2; ++rp) {
                float best = 3.4e38f; int bidx = 0;
#pragma unroll
                for (int nt = 0; nt < 8; ++nt) {
                    int c = col0 + wn * 64 + nt * 8 + (lane & 3) * 2;
                    float d0 = cs[nt].x - 2.0f * acc[mt][nt][rp * 2 + 0];
                    float d1 = cs[nt].y - 2.0f * acc[mt][nt][rp * 2 + 1];
                    if (d0 < best) { best = d0; bidx = c;     }
                    if (d1 < best) { best = d1; bidx = c + 1; }
                }
#pragma unroll
                for (int msk = 1; msk <= 2; msk <<= 1) {
                    float od = __shfl_xor_sync(0xffffffffu, best, msk);
                    int   oi = __shfl_xor_sync(0xffffffffu, bidx, msk);
                    if (od < best || (od == best && oi < bidx)) { best = od; bidx = oi; }
                }
                if ((lane & 3) == 0) {
                    int rl = wm * 32 + mt * 16 + rp * 8 + (lane >> 2);
                    sd[wn * 128 + rl] = best;
                    si[wn * 128 + rl] = bidx;
                }
            }
        }
        __syncthreads();
        if (tid < 128) {
            float d0 = sd[tid], d1 = sd[128 + tid];
            int   i0 = si[tid], i1 = si[128 + tid];
            bool t1 = (d1 < d0) || (d1 == d0 && i1 < i0);
            candD[(size_t)blockIdx.x * M + row0 + tid] = t1 ? d1 : d0;
            candI[(size_t)blockIdx.x * M + row0 + tid] = t1 ? i1 : i0;
        }
        return;
    }

    float* Co = (MODE == 2) ? (C + (size_t)blockIdx.z * M * N) : C;
#pragma unroll
    for (int mt = 0; mt < 2; ++mt) {
        int r = row0 + wm * 32 + mt * 16 + (lane >> 2);
#pragma unroll
        for (int nt = 0; nt < 8; ++nt) {
            int c = col0 + wn * 64 + nt * 8 + (lane & 3) * 2;
            float b0 = 0.0f, b1 = 0.0f;
            if (MODE == 1) { b0 = bias[c]; b1 = bias[c + 1]; }
            float v0 = acc[mt][nt][0] + b0;
            float v1 = acc[mt][nt][1] + b1;
            float v2 = acc[mt][nt][2] + b0;
            float v3 = acc[mt][nt][3] + b1;
            if (MODE == 1) {
                v0 = fmaxf(v0, 0.0f); v1 = fmaxf(v1, 0.0f);
                v2 = fmaxf(v2, 0.0f); v3 = fmaxf(v3, 0.0f);
            }
            *(float2*)&Co[(size_t)r * N + c]       = make_float2(v0, v1);
            *(float2*)&Co[(size_t)(r + 8) * N + c] = make_float2(v2, v3);
        }
    }
}

// ---------------- fused prep: 3 weight transposes + codebook sq norms ------------
__device__ __forceinline__ void transpose_tile(const float* __restrict__ W,
                                               float* __restrict__ Wt,
                                               int K, int N, int kb, int nb, int tid)
{
    __shared__ float tile[32][33];
    int tx = tid & 31, ty = tid >> 5;   // 32 x 8
#pragma unroll
    for (int i = 0; i < 32; i += 8) {
        int k = kb + ty + i, n = nb + tx;
        tile[ty + i][tx] = (k < K && n < N) ? W[(size_t)k * N + n] : 0.0f;
    }
    __syncthreads();
#pragma unroll
    for (int i = 0; i < 32; i += 8) {
        int n = nb + ty + i, k = kb + tx;
        if (n < N && k < K) Wt[(size_t)n * K + k] = tile[tx][ty + i];
    }
}

__global__ void prep_kernel(const float* __restrict__ We1, const float* __restrict__ We2,
                            const float* __restrict__ We3, const float* __restrict__ cb)
{
    int bx = blockIdx.x, tid = threadIdx.x;
    if (bx < 352) {               // W1: 16 x 22 tiles
        transpose_tile(We1, g_wt1, F_,  H1_, (bx >> 4) * 32, (bx & 15) * 32, tid);
    } else if (bx < 480) {        // W2: 8 x 16 tiles
        int b = bx - 352;
        transpose_tile(We2, g_wt2, H1_, H2_, (b >> 3) * 32, (b & 7) * 32, tid);
    } else if (bx < 512) {        // W3: 4 x 8 tiles
        int b = bx - 480;
        transpose_tile(We3, g_wt3, H2_, ENC_, (b >> 2) * 32, (b & 3) * 32, tid);
    } else {                      // csq: 4 blocks x 256 codes
        int k = (bx - 512) * 256 + tid;
        const float4* c = (const float4*)cb + k * 16;
        float s = 0.0f;
#pragma unroll
        for (int i = 0; i < 16; ++i) {
            float4 v = c[i];
            s += v.x * v.x + v.y * v.y + v.z * v.z + v.w * v.w;
        }
        g_csq[k] = s;
    }
}

// combine split-K partials + bias, emit mean/logvar and z_e
__global__ void reparam_kernel(const float* __restrict__ eps,
                               const float* __restrict__ be3,
                               float* __restrict__ out) {
    int i = blockIdx.x * 256 + threadIdx.x;
    if (i >= T_ * D_) return;
    int t = i >> 6, d = i & 63;
    float m  = be3[d]      + g_encp[t * ENC_ + d]      + g_encp[T_*ENC_ + t * ENC_ + d];
    float lv = be3[64 + d] + g_encp[t * ENC_ + 64 + d] + g_encp[T_*ENC_ + t * ENC_ + 64 + d];
    float zv = m + expf(0.5f * lv) * eps[i];
    g_ze[i] = zv;
    out[OUT_MEAN + i] = m;
    out[OUT_LV + i]   = lv;
}

// final VQ: reduce 8 block candidates per token, gather code, per-token loss
__global__ __launch_bounds__(256) void vq_finish_kernel(const float* __restrict__ cb) {
    int t    = (blockIdx.x * 256 + threadIdx.x) >> 5;
    int lane = threadIdx.x & 31;

    float d = 3.4e38f; int ix = 0x7fffffff;
    if (lane < NCB) {
        d  = g_candD[(size_t)lane * T_ + t];
        ix = g_candI[(size_t)lane * T_ + t];
    }
#pragma unroll
    for (int off = 4; off; off >>= 1) {
        float od = __shfl_down_sync(0xffffffffu, d, off);
        int   oi = __shfl_down_sync(0xffffffffu, ix, off);
        if (od < d || (od == d && oi < ix)) { d = od; ix = oi; }
    }
    ix = __shfl_sync(0xffffffffu, ix, 0);

    float l = 0.0f;
    if (lane < 16) {
        float4 cv = ((const float4*)cb)[ix * 16 + lane];
        float4 zv = ((const float4*)g_ze)[t * 16 + lane];
        ((float4*)g_zq)[t * 16 + lane] = cv;
        float dx = zv.x - cv.x, dy = zv.y - cv.y;
        float dz = zv.z - cv.z, dw = zv.w - cv.w;
        l = dx * dx + dy * dy + dz * dz + dw * dw;
    }
#pragma unroll
    for (int off = 16; off; off >>= 1)
        l += __shfl_down_sync(0xffffffffu, l, off);
    if (lane == 0) g_tokloss[t] = l;
}

__global__ __launch_bounds__(256) void dec1_part_kernel(const float* __restrict__ W) {
    __shared__ __align__(16) float zs[256 * 16];
    int k0 = blockIdx.x * 256;
    for (int i = threadIdx.x; i < 4096; i += 256) {
        int b = i >> 8, kk = i & 255;
        zs[kk * 16 + b] = g_zq[b * SD_ + k0 + kk];
    }
    __syncthreads();

    int n = threadIdx.x;
    u64 acc[8];
#pragma unroll
    for (int b2 = 0; b2 < 8; ++b2) acc[b2] = 0ULL;

#pragma unroll 4
    for (int kk = 0; kk < 256; ++kk) {
        u64 wd = dupf(W[(size_t)(k0 + kk) * H2_ + n]);
        const ulonglong2* dk = (const ulonglong2*)(zs + kk * 16);
        ulonglong2 p0 = dk[0], p1 = dk[1], p2 = dk[2], p3 = dk[3];
        u64 dp[8] = {p0.x, p0.y, p1.x, p1.y, p2.x, p2.y, p3.x, p3.y};
#pragma unroll
        for (int b2 = 0; b2 < 8; ++b2) ffma2(acc[b2], dp[b2], wd);
    }
#pragma unroll
    for (int b2 = 0; b2 < 8; ++b2) {
        float2 f = unpk(acc[b2]);
        g_dpart[blockIdx.x * 4096 + (2*b2)   * H2_ + n] = f.x;
        g_dpart[blockIdx.x * 4096 + (2*b2+1) * H2_ + n] = f.y;
    }
}

// fused: blocks 0-15 finish dec1 (split-K reduce + bias + relu); block 16 does vq_loss
__global__ void dec1fin_vqloss_kernel(const float* __restrict__ bias, float* __restrict__ out) {
    if (blockIdx.x < 16) {
        int n = blockIdx.x * 256 + threadIdx.x;
        float s = 0.0f;
        for (int c = 0; c < DEC1_CHUNKS; ++c) s += g_dpart[c * 4096 + n];
        g_dvec[n] = fmaxf(s + bias[n & 255], 0.0f);
    } else {
        __shared__ float sb[256];
        float a = 0.0f;
        for (int i = threadIdx.x; i < T_; i += 256) a += g_tokloss[i];
        sb[threadIdx.x] = a;
        __syncthreads();
        for (int s = 128; s > 0; s >>= 1) {
            if (threadIdx.x < s) sb[threadIdx.x] += sb[threadIdx.x + s];
            __syncthreads();
        }
        if (threadIdx.x == 0) out[OUT_VQL] = sb[0] / (float)(T_ * D_);
    }
}

__global__ __launch_bounds__(256, 2) void dec2_kernel(
    const float* __restrict__ W, const float* __restrict__ bias,
    float* __restrict__ out)
{
    __shared__ __align__(16) float ds[H2_ * 16];
    for (int i = threadIdx.x; i < 4096; i += 256) {
        int b = i >> 8, k = i & 255;
        ds[k * 16 + b] = g_dvec[i];
    }
    __syncthreads();

    int n = (blockIdx.x * 256 + threadIdx.x) * 4;
    if (n >= SF_) return;

    u64 acc[8][4];
#pragma unroll
    for (int b2 = 0; b2 < 8; ++b2)
#pragma unroll
        for (int c = 0; c < 4; ++c) acc[b2][c] = 0ULL;

#pragma unroll 4
    for (int k = 0; k < H2_; ++k) {
        float4 w = *(const float4*)(W + (size_t)k * SF_ + n);
        u64 wd[4] = {dupf(w.x), dupf(w.y), dupf(w.z), dupf(w.w)};
        const ulonglong2* dk = (const ulonglong2*)(ds + k * 16);
        ulonglong2 p0 = dk[0], p1 = dk[1], p2 = dk[2], p3 = dk[3];
        u64 dp[8] = {p0.x, p0.y, p1.x, p1.y, p2.x, p2.y, p3.x, p3.y};
#pragma unroll
        for (int b2 = 0; b2 < 8; ++b2)
#pragma unroll
            for (int c = 0; c < 4; ++c)
                ffma2(acc[b2][c], dp[b2], wd[c]);
    }

    float4 bb = *(const float4*)(bias + n);
#pragma unroll
    for (int b2 = 0; b2 < 8; ++b2) {
        float2 f0 = unpk(acc[b2][0]);
        float2 f1 = unpk(acc[b2][1]);
        float2 f2 = unpk(acc[b2][2]);
        float2 f3 = unpk(acc[b2][3]);
        float4 v0, v1;
        v0.x = softplusf(f0.x + bb.x);
        v0.y = softplusf(f1.x + bb.y);
        v0.z = softplusf(f2.x + bb.z);
        v0.w = softplusf(f3.x + bb.w);
        v1.x = softplusf(f0.y + bb.x);
        v1.y = softplusf(f1.y + bb.y);
        v1.z = softplusf(f2.y + bb.z);
        v1.w = softplusf(f3.y + bb.w);
        *(float4*)(out + (size_t)(2*b2)   * SF_ + n) = v0;
        *(float4*)(out + (size_t)(2*b2+1) * SF_ + n) = v1;
    }
}

// ---------------- launch ----------------
#define SYM(var) ({ void* _p; cudaGetSymbolAddress(&_p, var); _p; })

extern "C" void kernel_launch(void* const* d_in, const int* in_sizes, int n_in,
                              void* d_out, int out_size)
{
    const float* x   = (const float*)d_in[0];
    const float* eps = (const float*)d_in[1];
    const float* We1 = (const float*)d_in[2];
    const float* be1 = (const float*)d_in[3];
    const float* We2 = (const float*)d_in[4];
    const float* be2 = (const float*)d_in[5];
    const float* We3 = (const float*)d_in[6];
    const float* be3 = (const float*)d_in[7];
    const float* cb  = (const float*)d_in[8];
    const float* Wd1 = (const float*)d_in[9];
    const float* bd1 = (const float*)d_in[10];
    const float* Wd2 = (const float*)d_in[11];
    const float* bd2 = (const float*)d_in[12];
    float* out = (float*)d_out;

    float *h1    = (float*)SYM(g_h1);
    float *h2    = (float*)SYM(g_h2);
    float *encp  = (float*)SYM(g_encp);
    float *ze    = (float*)SYM(g_ze);
    float *wt1   = (float*)SYM(g_wt1);
    float *wt2   = (float*)SYM(g_wt2);
    float *wt3   = (float*)SYM(g_wt3);
    float *csq   = (float*)SYM(g_csq);
    float *candD = (float*)SYM(g_candD);
    int   *candI = (int*)SYM(g_candI);

    cudaFuncSetAttribute(mma_gemm<1>, cudaFuncAttributeMaxDynamicSharedMemorySize, SMEM_BYTES);
    cudaFuncSetAttribute(mma_gemm<2>, cudaFuncAttributeMaxDynamicSharedMemorySize, SMEM_BYTES);
    cudaFuncSetAttribute(mma_gemm<4>, cudaFuncAttributeMaxDynamicSharedMemorySize, SMEM_BYTES);

    // fused prep: 3 transposes + codebook norms (one launch)
    prep_kernel<<<516, 256>>>(We1, We2, We3, cb);

    // encoder MLP on tensor cores (bf16x3, 3-buffer single-sync pipeline)
    mma_gemm<1><<<dim3(4, 72), 256, SMEM_BYTES>>>(T_, H1_, F_,  0,
        x,  wt1, be1, h1, nullptr, nullptr);
    mma_gemm<1><<<dim3(2, 72), 256, SMEM_BYTES>>>(T_, H2_, H1_, 0,
        h1, wt2, be2, h2, nullptr, nullptr);
    mma_gemm<2><<<dim3(1, 72, ZSPLIT), 256, SMEM_BYTES>>>(T_, ENC_, H2_, H2_/ZSPLIT,
        h2, wt3, nullptr, encp, nullptr, nullptr);

    reparam_kernel<<<(T_ * D_ + 255) / 256, 256>>>(eps, be3, out);

    // fused VQ: cross GEMM + per-block argmin (no cross materialization)
    mma_gemm<4><<<dim3(NCB, 72), 256, SMEM_BYTES>>>(T_, KC_, D_, 0,
        ze, cb, csq, nullptr, candD, candI);
    vq_finish_kernel<<<T_ / 8, 256>>>(cb);

    // decoder
    dec1_part_kernel<<<DEC1_CHUNKS, 256>>>(Wd1);
    dec1fin_vqloss_kernel<<<17, 256>>>(bd1, out);
    dec2_kernel<<<(SF_ / 4 + 255) / 256, 256>>>(Wd2, bd2, out);
}

// round 10
// speedup vs baseline: 1.1521x; 1.0042x over previous
#include <cuda_runtime.h>
#include <cuda_bf16.h>
#include <math.h>
#include <stdint.h>

// ---------------- problem constants ----------------
#define B_      16
#define S_      576
#define F_      700
#define D_      64
#define KC_     1024
#define T_      (B_*S_)         // 9216 tokens
#define H1_     512
#define H2_     256
#define ENC_    128             // 2*D
#define SF_     (S_*F_)         // 403200
#define SD_     (S_*D_)         // 36864

#define OUT_REC  0
#define OUT_MEAN (B_*SF_)
#define OUT_LV   (OUT_MEAN + T_*D_)
#define OUT_VQL  (OUT_LV + T_*D_)

#define DEC1_CHUNKS 144
#define NCB         2            // candidate blocks (vq grid.x)
#define VQ_CB       4            // codebook col-blocks per vq CTA

typedef unsigned long long u64;
typedef __nv_bfloat16 bf16;

// ---------------- scratch (device globals; no allocation allowed) ----------------
__device__ __align__(256) float g_h1[T_*H1_];
__device__ __align__(256) float g_h2[T_*H2_];
__device__ __align__(256) float g_ze[T_*D_];
__device__ __align__(256) float g_zq[T_*D_];
__device__ __align__(256) float g_csq[KC_];
__device__ __align__(256) float g_tokloss[T_];
__device__ __align__(256) float g_dpart[DEC1_CHUNKS*16*H2_];
__device__ __align__(256) float g_dvec[16*H2_];
__device__ __align__(256) float g_wt1[H1_*F_];
__device__ __align__(256) float g_wt2[H2_*H1_];
__device__ __align__(256) float g_wt3[ENC_*H2_];
__device__ __align__(256) float g_candD[NCB*T_];
__device__ __align__(256) int   g_candI[NCB*T_];

// ---------------- f32x2 helpers (decoder kernels) ----------------
__device__ __forceinline__ u64 dupf(float a) {
    unsigned r = __float_as_uint(a);
    u64 d;
    asm("mov.b64 %0, {%1, %1};" : "=l"(d) : "r"(r));
    return d;
}
__device__ __forceinline__ void ffma2(u64 &d, u64 a, u64 b) {
    asm("fma.rn.f32x2 %0, %1, %2, %0;" : "+l"(d) : "l"(a), "l"(b));
}
__device__ __forceinline__ float2 unpk(u64 v) {
    unsigned lo, hi;
    asm("mov.b64 {%0, %1}, %2;" : "=r"(lo), "=r"(hi) : "l"(v));
    return make_float2(__uint_as_float(lo), __uint_as_float(hi));
}
__device__ __forceinline__ float softplusf(float x) {
    return fmaxf(x, 0.0f) + log1pf(expf(-fabsf(x)));
}

// ---------------- mma.sync helpers ----------------
__device__ __forceinline__ uint32_t smem_u32(const void* p) {
    uint32_t a;
    asm("{ .reg .u64 t; cvta.to.shared.u64 t, %1; cvt.u32.u64 %0, t; }" : "=r"(a) : "l"(p));
    return a;
}
__device__ __forceinline__ void ldsm4(uint32_t (&r)[4], uint32_t addr) {
    asm volatile("ldmatrix.sync.aligned.m8n8.x4.shared.b16 {%0,%1,%2,%3}, [%4];"
                 : "=r"(r[0]), "=r"(r[1]), "=r"(r[2]), "=r"(r[3]) : "r"(addr));
}
__device__ __forceinline__ void mma_bf16(float (&d)[4], const uint32_t (&a)[4],
                                         uint32_t b0, uint32_t b1) {
    asm volatile("mma.sync.aligned.m16n8k16.row.col.f32.bf16.bf16.f32 "
                 "{%0,%1,%2,%3}, {%4,%5,%6,%7}, {%8,%9}, {%0,%1,%2,%3};"
                 : "+f"(d[0]), "+f"(d[1]), "+f"(d[2]), "+f"(d[3])
                 : "r"(a[0]), "r"(a[1]), "r"(a[2]), "r"(a[3]), "r"(b0), "r"(b1));
}
// split fp32 pair -> packed bf16x2 hi and lo
__device__ __forceinline__ void split2(float x, float y, uint32_t &hi, uint32_t &lo) {
    __nv_bfloat162 h = __floats2bfloat162_rn(x, y);
    float hx = __bfloat162float(h.x), hy = __bfloat162float(h.y);
    __nv_bfloat162 l = __floats2bfloat162_rn(x - hx, y - hy);
    hi = *reinterpret_cast<uint32_t*>(&h);
    lo = *reinterpret_cast<uint32_t*>(&l);
}

// SMEM per stage: 20480 bf16 elems (40960 B): Ah[128][40] | Al +5120 | Bh +10240 | Bl +15360
#define STAGE_E   20480
#define NSTG      3
#define SMEM_BYTES (NSTG * STAGE_E * 2)

// ---------------- bf16x3 tensor-core GEMM, 3-buffer single-sync pipeline ---------
// C = act(A(MxK) * Bt(NxK)^T + bias); in-kernel hi/lo split.
// BM=128, BN=128, BK=32; 256 threads, warp grid 4(M) x 2(N), warp tile 32x64.
// MODE 1: relu+bias fp32 out.  MODE 5: encoder head — fused bias + reparam epilogue.
template<int MODE>
__global__ __launch_bounds__(256, 1) void mma_gemm(
    int M, int N, int K,
    const float* __restrict__ A, const float* __restrict__ Bt,
    const float* __restrict__ bias, float* __restrict__ C,
    const float* __restrict__ ep, float* __restrict__ outp)
{
    extern __shared__ __align__(16) __nv_bfloat16 sm[];
    const int tid  = threadIdx.x;
    const int wid  = tid >> 5;
    const int lane = tid & 31;
    const int row0 = blockIdx.y * 128;
    const int col0 = blockIdx.x * 128;
    const int NS = (K + 31) >> 5;
    const uint32_t smb = smem_u32(sm);

    float acc[2][8][4];
#pragma unroll
    for (int mt = 0; mt < 2; ++mt)
#pragma unroll
        for (int nt = 0; nt < 8; ++nt)
#pragma unroll
            for (int q = 0; q < 4; ++q) acc[mt][nt][q] = 0.0f;

    const int lrow = tid >> 3;        // 0..31 base row (with +32*i)
    const int lc4  = tid & 7;         // float4 col within BK

    float4 pa[4], pb[4];

    auto fetch = [&](int k0) {
#pragma unroll
        for (int i = 0; i < 4; ++i) {
            int row = lrow + i * 32;
            int kk  = k0 + lc4 * 4;
            if (kk < K) {
                pa[i] = *(const float4*)(A  + (size_t)(row0 + row) * K + kk);
                pb[i] = *(const float4*)(Bt + (size_t)(col0 + row) * K + kk);
            } else {
                pa[i] = make_float4(0.f, 0.f, 0.f, 0.f);
                pb[i] = make_float4(0.f, 0.f, 0.f, 0.f);
            }
        }
    };

    auto store_to = [&](int slot) {
        uint32_t stg = (uint32_t)slot * STAGE_E;
#pragma unroll
        for (int i = 0; i < 4; ++i) {
            int row = lrow + i * 32;
            uint32_t off = stg + row * 40 + lc4 * 4;
            uint32_t h0, l0, h1, l1;
            split2(pa[i].x, pa[i].y, h0, l0);
            split2(pa[i].z, pa[i].w, h1, l1);
            *(uint2*)&sm[off]          = make_uint2(h0, h1);
            *(uint2*)&sm[off + 5120]   = make_uint2(l0, l1);
            split2(pb[i].x, pb[i].y, h0, l0);
            split2(pb[i].z, pb[i].w, h1, l1);
            *(uint2*)&sm[off + 10240]  = make_uint2(h0, h1);
            *(uint2*)&sm[off + 15360]  = make_uint2(l0, l1);
        }
    };

    const int wm = wid >> 1, wn = wid & 1;
    const int arow  = wm * 32 + (lane & 15);
    const int acolB = (lane >> 4) * 16;
    const int brow  = wn * 64 + ((lane >> 4) << 3) + (lane & 7);
    const int bkhB  = ((lane >> 3) & 1) * 16;

    auto compute = [&](int slot) {
        const uint32_t stgB = (uint32_t)slot * (STAGE_E * 2);
#pragma unroll
        for (int ks = 0; ks < 2; ++ks) {
            uint32_t ah[2][4], al[2][4];
#pragma unroll
            for (int mt = 0; mt < 2; ++mt) {
                uint32_t addr = smb + stgB + (uint32_t)(arow + mt * 16) * 80u
                              + (uint32_t)ks * 32u + acolB;
                ldsm4(ah[mt], addr);
                ldsm4(al[mt], addr + 10240u);
            }
            uint32_t bh[8][2], bl[8][2];
#pragma unroll
            for (int p = 0; p < 4; ++p) {
                uint32_t addr = smb + stgB + 20480u + (uint32_t)(brow + p * 16) * 80u
                              + (uint32_t)ks * 32u + bkhB;
                uint32_t r[4];
                ldsm4(r, addr);
                bh[2*p][0] = r[0]; bh[2*p][1] = r[1];
                bh[2*p+1][0] = r[2]; bh[2*p+1][1] = r[3];
                ldsm4(r, addr + 10240u);
                bl[2*p][0] = r[0]; bl[2*p][1] = r[1];
                bl[2*p+1][0] = r[2]; bl[2*p+1][1] = r[3];
            }
#pragma unroll
            for (int mt = 0; mt < 2; ++mt)
#pragma unroll
                for (int nt = 0; nt < 8; ++nt) {
                    mma_bf16(acc[mt][nt], ah[mt], bh[nt][0], bh[nt][1]);
                    mma_bf16(acc[mt][nt], ah[mt], bl[nt][0], bl[nt][1]);
                    mma_bf16(acc[mt][nt], al[mt], bh[nt][0], bh[nt][1]);
                }
        }
    };

    fetch(0);
    store_to(0);
    if (NS > 1) fetch(32);

    int scur = 0, sst = 1;
    for (int s = 0; s < NS; ++s) {
        __syncthreads();
        if (s + 1 < NS) store_to(sst);
        if (s + 2 < NS) fetch((s + 2) * 32);
        compute(scur);
        scur = (scur + 1 == NSTG) ? 0 : scur + 1;
        sst  = (sst  + 1 == NSTG) ? 0 : sst  + 1;
    }

    // ---- epilogue ----
    if (MODE == 5) {
        // stage to smem, then fused bias + reparameterize
        __syncthreads();
        float* smf = (float*)sm;       // [128][132]
#pragma unroll
        for (int mt = 0; mt < 2; ++mt) {
            int r = wm * 32 + mt * 16 + (lane >> 2);
#pragma unroll
            for (int nt = 0; nt < 8; ++nt) {
                int c = wn * 64 + nt * 8 + (lane & 3) * 2;
                float b0 = bias[c], b1 = bias[c + 1];
                smf[r * 132 + c]           = acc[mt][nt][0] + b0;
                smf[r * 132 + c + 1]       = acc[mt][nt][1] + b1;
                smf[(r + 8) * 132 + c]     = acc[mt][nt][2] + b0;
                smf[(r + 8) * 132 + c + 1] = acc[mt][nt][3] + b1;
            }
        }
        __syncthreads();
#pragma unroll
        for (int it = 0; it < 32; ++it) {
            int idx = it * 256 + tid;          // 0..8191
            int r = idx >> 6, d = idx & 63;
            float m  = smf[r * 132 + d];
            float lv = smf[r * 132 + 64 + d];
            int gi = (row0 + r) * 64 + d;
            float zv = m + expf(0.5f * lv) * ep[gi];
            g_ze[gi] = zv;
            outp[OUT_MEAN + gi] = m;
            outp[OUT_LV + gi]   = lv;
        }
        return;
    }

#pragma unroll
    for (int mt = 0; mt < 2; ++mt) {
        int r = row0 + wm * 32 + mt * 16 + (lane >> 2);
#pragma unroll
        for (int nt = 0; nt < 8; ++nt) {
            int c = col0 + wn * 64 + nt * 8 + (lane & 3) * 2;
            float b0 = bias[c], b1 = bias[c + 1];
            float v0 = fmaxf(acc[mt][nt][0] + b0, 0.0f);
            float v1 = fmaxf(acc[mt][nt][1] + b1, 0.0f);
            float v2 = fmaxf(acc[mt][nt][2] + b0, 0.0f);
            float v3 = fmaxf(acc[mt][nt][3] + b1, 0.0f);
            *(float2*)&C[(size_t)r * N + c]       = make_float2(v0, v1);
            *(float2*)&C[(size_t)(r + 8) * N + c] = make_float2(v2, v3);
        }
    }
}

// ---------------- persistent VQ kernel ----------------
// grid (NCB, 72). Each CTA: 128 tokens, loops VQ_CB codebook 128-col blocks.
// A (z_e) tile cached in smem; B double-buffered; running register argmin.
__global__ __launch_bounds__(256, 1) void vq_kernel(
    const float* __restrict__ A, const float* __restrict__ cbk)
{
    extern __shared__ __align__(16) __nv_bfloat16 sm[];
    __shared__ float scsq[KC_];
    __shared__ float sdm[256];
    __shared__ int   sim[256];

    const int tid  = threadIdx.x;
    const int wid  = tid >> 5;
    const int lane = tid & 31;
    const int row0 = blockIdx.y * 128;
    const uint32_t smb = smem_u32(sm);

    for (int i = tid; i < KC_; i += 256) scsq[i] = g_csq[i];

    const int lrow = tid >> 3;
    const int lc4  = tid & 7;

    // ---- load A (z_e) tile: 2 k-stages, hi/lo ----
#pragma unroll
    for (int s2 = 0; s2 < 2; ++s2) {
#pragma unroll
        for (int i = 0; i < 4; ++i) {
            int row = lrow + i * 32;
            float4 v = *(const float4*)(A + (size_t)(row0 + row) * 64 + s2 * 32 + lc4 * 4);
            uint32_t h0, l0, h1, l1;
            split2(v.x, v.y, h0, l0);
            split2(v.z, v.w, h1, l1);
            uint32_t off = s2 * 10240 + row * 40 + lc4 * 4;
            *(uint2*)&sm[off]        = make_uint2(h0, h1);
            *(uint2*)&sm[off + 5120] = make_uint2(l0, l1);
        }
    }

    float4 pb[8];
    auto fetchB = [&](int cb) {
        int colcb = (blockIdx.x * VQ_CB + cb) * 128;
#pragma unroll
        for (int i = 0; i < 4; ++i) {
            int row = colcb + lrow + i * 32;
            pb[i]     = *(const float4*)(cbk + (size_t)row * 64 + lc4 * 4);
            pb[4 + i] = *(const float4*)(cbk + (size_t)row * 64 + 32 + lc4 * 4);
        }
    };
    auto storeB = [&](int buf) {
        uint32_t base = 20480 + (uint32_t)buf * 20480;
#pragma unroll
        for (int s2 = 0; s2 < 2; ++s2) {
#pragma unroll
            for (int i = 0; i < 4; ++i) {
                int row = lrow + i * 32;
                float4 v = pb[s2 * 4 + i];
                uint32_t h0, l0, h1, l1;
                split2(v.x, v.y, h0, l0);
                split2(v.z, v.w, h1, l1);
                uint32_t off = base + s2 * 10240 + row * 40 + lc4 * 4;
                *(uint2*)&sm[off]        = make_uint2(h0, h1);
                *(uint2*)&sm[off + 5120] = make_uint2(l0, l1);
            }
        }
    };

    const int wm = wid >> 1, wn = wid & 1;
    const int arow  = wm * 32 + (lane & 15);
    const int acolB = (lane >> 4) * 16;
    const int brow  = wn * 64 + ((lane >> 4) << 3) + (lane & 7);
    const int bkhB  = ((lane >> 3) & 1) * 16;

    // prologue
    fetchB(0);
    storeB(0);
    __syncthreads();

    float rbD[2][2] = {{3.4e38f, 3.4e38f}, {3.4e38f, 3.4e38f}};
    int   rbI[2][2] = {{0x7fffffff, 0x7fffffff}, {0x7fffffff, 0x7fffffff}};

    int buf = 0;
    for (int cb = 0; cb < VQ_CB; ++cb) {
        if (cb + 1 < VQ_CB) fetchB(cb + 1);

        float acc[2][8][4];
#pragma unroll
        for (int mt = 0; mt < 2; ++mt)
#pragma unroll
            for (int nt = 0; nt < 8; ++nt)
#pragma unroll
                for (int q = 0; q < 4; ++q) acc[mt][nt][q] = 0.0f;

        const uint32_t bbase = 40960u + (uint32_t)buf * 40960u;
#pragma unroll
        for (int s2 = 0; s2 < 2; ++s2) {
            const uint32_t aB = (uint32_t)s2 * 20480u;
            const uint32_t bB = bbase + (uint32_t)s2 * 20480u;
#pragma unroll
            for (int ks = 0; ks < 2; ++ks) {
                uint32_t ah[2][4], al[2][4];
#pragma unroll
                for (int mt = 0; mt < 2; ++mt) {
                    uint32_t addr = smb + aB + (uint32_t)(arow + mt * 16) * 80u
                                  + (uint32_t)ks * 32u + acolB;
                    ldsm4(ah[mt], addr);
                    ldsm4(al[mt], addr + 10240u);
                }
                uint32_t bh[8][2], bl[8][2];
#pragma unroll
                for (int p = 0; p < 4; ++p) {
                    uint32_t addr = smb + bB + (uint32_t)(brow + p * 16) * 80u
                                  + (uint32_t)ks * 32u + bkhB;
                    uint32_t r[4];
                    ldsm4(r, addr);
                    bh[2*p][0] = r[0]; bh[2*p][1] = r[1];
                    bh[2*p+1][0] = r[2]; bh[2*p+1][1] = r[3];
                    ldsm4(r, addr + 10240u);
                    bl[2*p][0] = r[0]; bl[2*p][1] = r[1];
                    bl[2*p+1][0] = r[2]; bl[2*p+1][1] = r[3];
                }
#pragma unroll
                for (int mt = 0; mt < 2; ++mt)
#pragma unroll
                    for (int nt = 0; nt < 8; ++nt) {
                        mma_bf16(acc[mt][nt], ah[mt], bh[nt][0], bh[nt][1]);
                        mma_bf16(acc[mt][nt], ah[mt], bl[nt][0], bl[nt][1]);
                        mma_bf16(acc[mt][nt], al[mt], bh[nt][0], bh[nt][1]);
                    }
            }
        }

        // running argmin update for this 128-code block
        int colcb = (blockIdx.x * VQ_CB + cb) * 128;
#pragma unroll
        for (int mt = 0; mt < 2; ++mt) {
#pragma unroll
            for (int rp = 0; rp < 2; ++rp) {
                float best = 3.4e38f; int bidx = 0;
#pragma unroll
                for (int nt = 0; nt < 8; ++nt) {
                    int cg = colcb + wn * 64 + nt * 8 + (lane & 3) * 2;
                    float d0 = scsq[cg]     - 2.0f * acc[mt][nt][rp * 2 + 0];
                    float d1 = scsq[cg + 1] - 2.0f * acc[mt][nt][rp * 2 + 1];
                    if (d0 < best) { best = d0; bidx = cg;     }
                    if (d1 < best) { best = d1; bidx = cg + 1; }
                }
#pragma unroll
                for (int msk = 1; msk <= 2; msk <<= 1) {
                    float od = __shfl_xor_sync(0xffffffffu, best, msk);
                    int   oi = __shfl_xor_sync(0xffffffffu, bidx, msk);
                    if (od < best || (od == best && oi < bidx)) { best = od; bidx = oi; }
                }
                if (best < rbD[mt][rp] || (best == rbD[mt][rp] && bidx < rbI[mt][rp])) {
                    rbD[mt][rp] = best; rbI[mt][rp] = bidx;
                }
            }
        }

        if (cb + 1 < VQ_CB) {
            __syncthreads();
            storeB(buf ^ 1);
            __syncthreads();
            buf ^= 1;
        }
    }

    // merge wn halves, emit candidates
    if ((lane & 3) == 0) {
#pragma unroll
        for (int mt = 0; mt < 2; ++mt)
#pragma unroll
            for (int rp = 0; rp < 2; ++rp) {
                int rl = wm * 32 + mt * 16 + rp * 8 + (lane >> 2);
                sdm[wn * 128 + rl] = rbD[mt][rp];
                sim[wn * 128 + rl] = rbI[mt][rp];
            }
    }
    __syncthreads();
    if (tid < 128) {
        float d0 = sdm[tid], d1 = sdm[128 + tid];
        int   i0 = sim[tid], i1 = sim[128 + tid];
        bool t1 = (d1 < d0) || (d1 == d0 && i1 < i0);
        g_candD[(size_t)blockIdx.x * T_ + row0 + tid] = t1 ? d1 : d0;
        g_candI[(size_t)blockIdx.x * T_ + row0 + tid] = t1 ? i1 : i0;
    }
}

// ---------------- fused prep: 3 weight transposes + codebook sq norms ------------
__device__ __forceinline__ void transpose_tile(const float* __restrict__ W,
                                               float* __restrict__ Wt,
                                               int K, int N, int kb, int nb, int tid)
{
    __shared__ float tile[32][33];
    int tx = tid & 31, ty = tid >> 5;   // 32 x 8
#pragma unroll
    for (int i = 0; i < 32; i += 8) {
        int k = kb + ty + i, n = nb + tx;
        tile[ty + i][tx] = (k < K && n < N) ? W[(size_t)k * N + n] : 0.0f;
    }
    __syncthreads();
#pragma unroll
    for (int i = 0; i < 32; i += 8) {
        int n = nb + ty + i, k = kb + tx;
        if (n < N && k < K) Wt[(size_t)n * K + k] = tile[tx][ty + i];
    }
}

__global__ void prep_kernel(const float* __restrict__ We1, const float* __restrict__ We2,
                            const float* __restrict__ We3, const float* __restrict__ cb)
{
    int bx = blockIdx.x, tid = threadIdx.x;
    if (bx < 352) {               // W1: 16 x 22 tiles
        transpose_tile(We1, g_wt1, F_,  H1_, (bx >> 4) * 32, (bx & 15) * 32, tid);
    } else if (bx < 480) {        // W2: 8 x 16 tiles
        int b = bx - 352;
        transpose_tile(We2, g_wt2, H1_, H2_, (b >> 3) * 32, (b & 7) * 32, tid);
    } else if (bx < 512) {        // W3: 4 x 8 tiles
        int b = bx - 480;
        transpose_tile(We3, g_wt3, H2_, ENC_, (b >> 2) * 32, (b & 3) * 32, tid);
    } else {                      // csq: 4 blocks x 256 codes
        int k = (bx - 512) * 256 + tid;
        const float4* c = (const float4*)cb + k * 16;
        float s = 0.0f;
#pragma unroll
        for (int i = 0; i < 16; ++i) {
            float4 v = c[i];
            s += v.x * v.x + v.y * v.y + v.z * v.z + v.w * v.w;
        }
        g_csq[k] = s;
    }
}

// final VQ: reduce 2 block candidates per token, gather code, per-token loss
__global__ __launch_bounds__(256) void vq_finish_kernel(const float* __restrict__ cb) {
    int t    = (blockIdx.x * 256 + threadIdx.x) >> 5;
    int lane = threadIdx.x & 31;

    float d = 3.4e38f; int ix = 0x7fffffff;
    if (lane < NCB) {
        d  = g_candD[(size_t)lane * T_ + t];
        ix = g_candI[(size_t)lane * T_ + t];
    }
    {
        float od = __shfl_down_sync(0xffffffffu, d, 1);
        int   oi = __shfl_down_sync(0xffffffffu, ix, 1);
        if (od < d || (od == d && oi < ix)) { d = od; ix = oi; }
    }
    ix = __shfl_sync(0xffffffffu, ix, 0);

    float l = 0.0f;
    if (lane < 16) {
        float4 cv = ((const float4*)cb)[ix * 16 + lane];
        float4 zv = ((const float4*)g_ze)[t * 16 + lane];
        ((float4*)g_zq)[t * 16 + lane] = cv;
        float dx = zv.x - cv.x, dy = zv.y - cv.y;
        float dz = zv.z - cv.z, dw = zv.w - cv.w;
        l = dx * dx + dy * dy + dz * dz + dw * dw;
    }
#pragma unroll
    for (int off = 16; off; off >>= 1)
        l += __shfl_down_sync(0xffffffffu, l, off);
    if (lane == 0) g_tokloss[t] = l;
}

__global__ __launch_bounds__(256) void dec1_part_kernel(const float* __restrict__ W) {
    __shared__ __align__(16) float zs[256 * 16];
    int k0 = blockIdx.x * 256;
    for (int i = threadIdx.x; i < 4096; i += 256) {
        int b = i >> 8, kk = i & 255;
        zs[kk * 16 + b] = g_zq[b * SD_ + k0 + kk];
    }
    __syncthreads();

    int n = threadIdx.x;
    u64 acc[8];
#pragma unroll
    for (int b2 = 0; b2 < 8; ++b2) acc[b2] = 0ULL;

#pragma unroll 4
    for (int kk = 0; kk < 256; ++kk) {
        u64 wd = dupf(W[(size_t)(k0 + kk) * H2_ + n]);
        const ulonglong2* dk = (const ulonglong2*)(zs + kk * 16);
        ulonglong2 p0 = dk[0], p1 = dk[1], p2 = dk[2], p3 = dk[3];
        u64 dp[8] = {p0.x, p0.y, p1.x, p1.y, p2.x, p2.y, p3.x, p3.y};
#pragma unroll
        for (int b2 = 0; b2 < 8; ++b2) ffma2(acc[b2], dp[b2], wd);
    }
#pragma unroll
    for (int b2 = 0; b2 < 8; ++b2) {
        float2 f = unpk(acc[b2]);
        g_dpart[blockIdx.x * 4096 + (2*b2)   * H2_ + n] = f.x;
        g_dpart[blockIdx.x * 4096 + (2*b2+1) * H2_ + n] = f.y;
    }
}

// fused: blocks 0-15 finish dec1; block 16 does vq_loss
__global__ void dec1fin_vqloss_kernel(const float* __restrict__ bias, float* __restrict__ out) {
    if (blockIdx.x < 16) {
        int n = blockIdx.x * 256 + threadIdx.x;
        float s = 0.0f;
        for (int c = 0; c < DEC1_CHUNKS; ++c) s += g_dpart[c * 4096 + n];
        g_dvec[n] = fmaxf(s + bias[n & 255], 0.0f);
    } else {
        __shared__ float sb[256];
        float a = 0.0f;
        for (int i = threadIdx.x; i < T_; i += 256) a += g_tokloss[i];
        sb[threadIdx.x] = a;
        __syncthreads();
        for (int s = 128; s > 0; s >>= 1) {
            if (threadIdx.x < s) sb[threadIdx.x] += sb[threadIdx.x + s];
            __syncthreads();
        }
        if (threadIdx.x == 0) out[OUT_VQL] = sb[0] / (float)(T_ * D_);
    }
}

__global__ __launch_bounds__(256, 2) void dec2_kernel(
    const float* __restrict__ W, const float* __restrict__ bias,
    float* __restrict__ out)
{
    __shared__ __align__(16) float ds[H2_ * 16];
    for (int i = threadIdx.x; i < 4096; i += 256) {
        int b = i >> 8, k = i & 255;
        ds[k * 16 + b] = g_dvec[i];
    }
    __syncthreads();

    int n = (blockIdx.x * 256 + threadIdx.x) * 4;
    if (n >= SF_) return;

    u64 acc[8][4];
#pragma unroll
    for (int b2 = 0; b2 < 8; ++b2)
#pragma unroll
        for (int c = 0; c < 4; ++c) acc[b2][c] = 0ULL;

#pragma unroll 4
    for (int k = 0; k < H2_; ++k) {
        float4 w = *(const float4*)(W + (size_t)k * SF_ + n);
        u64 wd[4] = {dupf(w.x), dupf(w.y), dupf(w.z), dupf(w.w)};
        const ulonglong2* dk = (const ulonglong2*)(ds + k * 16);
        ulonglong2 p0 = dk[0], p1 = dk[1], p2 = dk[2], p3 = dk[3];
        u64 dp[8] = {p0.x, p0.y, p1.x, p1.y, p2.x, p2.y, p3.x, p3.y};
#pragma unroll
        for (int b2 = 0; b2 < 8; ++b2)
#pragma unroll
            for (int c = 0; c < 4; ++c)
                ffma2(acc[b2][c], dp[b2], wd[c]);
    }

    float4 bb = *(const float4*)(bias + n);
#pragma unroll
    for (int b2 = 0; b2 < 8; ++b2) {
        float2 f0 = unpk(acc[b2][0]);
        float2 f1 = unpk(acc[b2][1]);
        float2 f2 = unpk(acc[b2][2]);
        float2 f3 = unpk(acc[b2][3]);
        float4 v0, v1;
        v0.x = softplusf(f0.x + bb.x);
        v0.y = softplusf(f1.x + bb.y);
        v0.z = softplusf(f2.x + bb.z);
        v0.w = softplusf(f3.x + bb.w);
        v1.x = softplusf(f0.y + bb.x);
        v1.y = softplusf(f1.y + bb.y);
        v1.z = softplusf(f2.y + bb.z);
        v1.w = softplusf(f3.y + bb.w);
        *(float4*)(out + (size_t)(2*b2)   * SF_ + n) = v0;
        *(float4*)(out + (size_t)(2*b2+1) * SF_ + n) = v1;
    }
}

// ---------------- launch ----------------
#define SYM(var) ({ void* _p; cudaGetSymbolAddress(&_p, var); _p; })

extern "C" void kernel_launch(void* const* d_in, const int* in_sizes, int n_in,
                              void* d_out, int out_size)
{
    const float* x   = (const float*)d_in[0];
    const float* eps = (const float*)d_in[1];
    const float* We1 = (const float*)d_in[2];
    const float* be1 = (const float*)d_in[3];
    const float* We2 = (const float*)d_in[4];
    const float* be2 = (const float*)d_in[5];
    const float* We3 = (const float*)d_in[6];
    const float* be3 = (const float*)d_in[7];
    const float* cb  = (const float*)d_in[8];
    const float* Wd1 = (const float*)d_in[9];
    const float* bd1 = (const float*)d_in[10];
    const float* Wd2 = (const float*)d_in[11];
    const float* bd2 = (const float*)d_in[12];
    float* out = (float*)d_out;

    float *h1  = (float*)SYM(g_h1);
    float *h2  = (float*)SYM(g_h2);
    float *ze  = (float*)SYM(g_ze);
    float *wt1 = (float*)SYM(g_wt1);
    float *wt2 = (float*)SYM(g_wt2);
    float *wt3 = (float*)SYM(g_wt3);

    cudaFuncSetAttribute(mma_gemm<1>, cudaFuncAttributeMaxDynamicSharedMemorySize, SMEM_BYTES);
    cudaFuncSetAttribute(mma_gemm<5>, cudaFuncAttributeMaxDynamicSharedMemorySize, SMEM_BYTES);
    cudaFuncSetAttribute(vq_kernel,   cudaFuncAttributeMaxDynamicSharedMemorySize, SMEM_BYTES);

    // fused prep: 3 transposes + codebook norms
    prep_kernel<<<516, 256>>>(We1, We2, We3, cb);

    // encoder MLP on tensor cores (bf16x3)
    mma_gemm<1><<<dim3(4, 72), 256, SMEM_BYTES>>>(T_, H1_, F_,
        x,  wt1, be1, h1, nullptr, nullptr);
    mma_gemm<1><<<dim3(2, 72), 256, SMEM_BYTES>>>(T_, H2_, H1_,
        h1, wt2, be2, h2, nullptr, nullptr);
    // encoder head: GEMM + bias + reparameterize fused
    mma_gemm<5><<<dim3(1, 72), 256, SMEM_BYTES>>>(T_, ENC_, H2_,
        h2, wt3, be3, nullptr, eps, out);

    // persistent VQ: cross GEMM + running argmin (2 candidates/token)
    vq_kernel<<<dim3(NCB, 72), 256, SMEM_BYTES>>>(ze, cb);
    vq_finish_kernel<<<T_ / 8, 256>>>(cb);

    // decoder
    dec1_part_kernel<<<DEC1_CHUNKS, 256>>>(Wd1);
    dec1fin_vqloss_kernel<<<17, 256>>>(bd1, out);
    dec2_kernel<<<(SF_ / 4 + 255) / 256, 256>>>(Wd2, bd2, out);
}

// round 11
// speedup vs baseline: 1.1554x; 1.0029x over previous
#include <cuda_runtime.h>
#include <cuda_bf16.h>
#include <math.h>
#include <stdint.h>

// ---------------- problem constants ----------------
#define B_      16
#define S_      576
#define F_      700
#define D_      64
#define KC_     1024
#define T_      (B_*S_)         // 9216 tokens
#define H1_     512
#define H2_     256
#define ENC_    128             // 2*D
#define SF_     (S_*F_)         // 403200
#define SD_     (S_*D_)         // 36864

#define OUT_REC  0
#define OUT_MEAN (B_*SF_)
#define OUT_LV   (OUT_MEAN + T_*D_)
#define OUT_VQL  (OUT_LV + T_*D_)

#define DEC1_CHUNKS 144
#define NCB         2            // candidate blocks (vq grid.x)
#define VQ_CB       4            // codebook col-blocks per vq CTA

typedef unsigned long long u64;
typedef __nv_bfloat16 bf16;

// ---------------- scratch (device globals; no allocation allowed) ----------------
__device__ __align__(256) float g_h1[T_*H1_];
__device__ __align__(256) float g_h2[T_*H2_];
__device__ __align__(256) float g_ze[T_*D_];
__device__ __align__(256) float g_csq[KC_];
__device__ __align__(256) float g_tokloss[T_];
__device__ __align__(256) float g_dpart[DEC1_CHUNKS*16*H2_];
__device__ __align__(256) float g_dvec[16*H2_];
__device__ __align__(256) float g_wt1[H1_*F_];
__device__ __align__(256) float g_wt2[H2_*H1_];
__device__ __align__(256) float g_wt3[ENC_*H2_];
__device__ __align__(256) float g_candD[NCB*T_];
__device__ __align__(256) int   g_candI[NCB*T_];

// ---------------- f32x2 helpers (decoder kernels) ----------------
__device__ __forceinline__ u64 dupf(float a) {
    unsigned r = __float_as_uint(a);
    u64 d;
    asm("mov.b64 %0, {%1, %1};" : "=l"(d) : "r"(r));
    return d;
}
__device__ __forceinline__ void ffma2(u64 &d, u64 a, u64 b) {
    asm("fma.rn.f32x2 %0, %1, %2, %0;" : "+l"(d) : "l"(a), "l"(b));
}
__device__ __forceinline__ float2 unpk(u64 v) {
    unsigned lo, hi;
    asm("mov.b64 {%0, %1}, %2;" : "=r"(lo), "=r"(hi) : "l"(v));
    return make_float2(__uint_as_float(lo), __uint_as_float(hi));
}
__device__ __forceinline__ float softplusf(float x) {
    return fmaxf(x, 0.0f) + log1pf(expf(-fabsf(x)));
}

// ---------------- mma.sync helpers ----------------
__device__ __forceinline__ uint32_t smem_u32(const void* p) {
    uint32_t a;
    asm("{ .reg .u64 t; cvta.to.shared.u64 t, %1; cvt.u32.u64 %0, t; }" : "=r"(a) : "l"(p));
    return a;
}
__device__ __forceinline__ void ldsm4(uint32_t (&r)[4], uint32_t addr) {
    asm volatile("ldmatrix.sync.aligned.m8n8.x4.shared.b16 {%0,%1,%2,%3}, [%4];"
                 : "=r"(r[0]), "=r"(r[1]), "=r"(r[2]), "=r"(r[3]) : "r"(addr));
}
__device__ __forceinline__ void mma_bf16(float (&d)[4], const uint32_t (&a)[4],
                                         uint32_t b0, uint32_t b1) {
    asm volatile("mma.sync.aligned.m16n8k16.row.col.f32.bf16.bf16.f32 "
                 "{%0,%1,%2,%3}, {%4,%5,%6,%7}, {%8,%9}, {%0,%1,%2,%3};"
                 : "+f"(d[0]), "+f"(d[1]), "+f"(d[2]), "+f"(d[3])
                 : "r"(a[0]), "r"(a[1]), "r"(a[2]), "r"(a[3]), "r"(b0), "r"(b1));
}
// split fp32 pair -> packed bf16x2 hi and lo
__device__ __forceinline__ void split2(float x, float y, uint32_t &hi, uint32_t &lo) {
    __nv_bfloat162 h = __floats2bfloat162_rn(x, y);
    float hx = __bfloat162float(h.x), hy = __bfloat162float(h.y);
    __nv_bfloat162 l = __floats2bfloat162_rn(x - hx, y - hy);
    hi = *reinterpret_cast<uint32_t*>(&h);
    lo = *reinterpret_cast<uint32_t*>(&l);
}

// SMEM per stage: 20480 bf16 elems (40960 B): Ah[128][40] | Al +5120 | Bh +10240 | Bl +15360
#define STAGE_E   20480
#define NSTG      3
#define SMEM_BYTES (NSTG * STAGE_E * 2)

// ---------------- bf16x3 tensor-core GEMM, 3-buffer single-sync pipeline ---------
// MODE 1: relu+bias fp32 out.  MODE 5: encoder head — fused bias + reparam epilogue.
template<int MODE>
__global__ __launch_bounds__(256, 1) void mma_gemm(
    int M, int N, int K,
    const float* __restrict__ A, const float* __restrict__ Bt,
    const float* __restrict__ bias, float* __restrict__ C,
    const float* __restrict__ ep, float* __restrict__ outp)
{
    extern __shared__ __align__(16) __nv_bfloat16 sm[];
    const int tid  = threadIdx.x;
    const int wid  = tid >> 5;
    const int lane = tid & 31;
    const int row0 = blockIdx.y * 128;
    const int col0 = blockIdx.x * 128;
    const int NS = (K + 31) >> 5;
    const uint32_t smb = smem_u32(sm);

    float acc[2][8][4];
#pragma unroll
    for (int mt = 0; mt < 2; ++mt)
#pragma unroll
        for (int nt = 0; nt < 8; ++nt)
#pragma unroll
            for (int q = 0; q < 4; ++q) acc[mt][nt][q] = 0.0f;

    const int lrow = tid >> 3;        // 0..31 base row (with +32*i)
    const int lc4  = tid & 7;         // float4 col within BK

    float4 pa[4], pb[4];

    auto fetch = [&](int k0) {
#pragma unroll
        for (int i = 0; i < 4; ++i) {
            int row = lrow + i * 32;
            int kk  = k0 + lc4 * 4;
            if (kk < K) {
                pa[i] = *(const float4*)(A  + (size_t)(row0 + row) * K + kk);
                pb[i] = *(const float4*)(Bt + (size_t)(col0 + row) * K + kk);
            } else {
                pa[i] = make_float4(0.f, 0.f, 0.f, 0.f);
                pb[i] = make_float4(0.f, 0.f, 0.f, 0.f);
            }
        }
    };

    auto store_to = [&](int slot) {
        uint32_t stg = (uint32_t)slot * STAGE_E;
#pragma unroll
        for (int i = 0; i < 4; ++i) {
            int row = lrow + i * 32;
            uint32_t off = stg + row * 40 + lc4 * 4;
            uint32_t h0, l0, h1, l1;
            split2(pa[i].x, pa[i].y, h0, l0);
            split2(pa[i].z, pa[i].w, h1, l1);
            *(uint2*)&sm[off]          = make_uint2(h0, h1);
            *(uint2*)&sm[off + 5120]   = make_uint2(l0, l1);
            split2(pb[i].x, pb[i].y, h0, l0);
            split2(pb[i].z, pb[i].w, h1, l1);
            *(uint2*)&sm[off + 10240]  = make_uint2(h0, h1);
            *(uint2*)&sm[off + 15360]  = make_uint2(l0, l1);
        }
    };

    const int wm = wid >> 1, wn = wid & 1;
    const int arow  = wm * 32 + (lane & 15);
    const int acolB = (lane >> 4) * 16;
    const int brow  = wn * 64 + ((lane >> 4) << 3) + (lane & 7);
    const int bkhB  = ((lane >> 3) & 1) * 16;

    auto compute = [&](int slot) {
        const uint32_t stgB = (uint32_t)slot * (STAGE_E * 2);
#pragma unroll
        for (int ks = 0; ks < 2; ++ks) {
            uint32_t ah[2][4], al[2][4];
#pragma unroll
            for (int mt = 0; mt < 2; ++mt) {
                uint32_t addr = smb + stgB + (uint32_t)(arow + mt * 16) * 80u
                              + (uint32_t)ks * 32u + acolB;
                ldsm4(ah[mt], addr);
                ldsm4(al[mt], addr + 10240u);
            }
            uint32_t bh[8][2], bl[8][2];
#pragma unroll
            for (int p = 0; p < 4; ++p) {
                uint32_t addr = smb + stgB + 20480u + (uint32_t)(brow + p * 16) * 80u
                              + (uint32_t)ks * 32u + bkhB;
                uint32_t r[4];
                ldsm4(r, addr);
                bh[2*p][0] = r[0]; bh[2*p][1] = r[1];
                bh[2*p+1][0] = r[2]; bh[2*p+1][1] = r[3];
                ldsm4(r, addr + 10240u);
                bl[2*p][0] = r[0]; bl[2*p][1] = r[1];
                bl[2*p+1][0] = r[2]; bl[2*p+1][1] = r[3];
            }
#pragma unroll
            for (int mt = 0; mt < 2; ++mt)
#pragma unroll
                for (int nt = 0; nt < 8; ++nt) {
                    mma_bf16(acc[mt][nt], ah[mt], bh[nt][0], bh[nt][1]);
                    mma_bf16(acc[mt][nt], ah[mt], bl[nt][0], bl[nt][1]);
                    mma_bf16(acc[mt][nt], al[mt], bh[nt][0], bh[nt][1]);
                }
        }
    };

    fetch(0);
    store_to(0);
    if (NS > 1) fetch(32);

    int scur = 0, sst = 1;
    for (int s = 0; s < NS; ++s) {
        __syncthreads();
        if (s + 1 < NS) store_to(sst);
        if (s + 2 < NS) fetch((s + 2) * 32);
        compute(scur);
        scur = (scur + 1 == NSTG) ? 0 : scur + 1;
        sst  = (sst  + 1 == NSTG) ? 0 : sst  + 1;
    }

    // ---- epilogue ----
    if (MODE == 5) {
        __syncthreads();
        float* smf = (float*)sm;       // [128][132]
#pragma unroll
        for (int mt = 0; mt < 2; ++mt) {
            int r = wm * 32 + mt * 16 + (lane >> 2);
#pragma unroll
            for (int nt = 0; nt < 8; ++nt) {
                int c = wn * 64 + nt * 8 + (lane & 3) * 2;
                float b0 = bias[c], b1 = bias[c + 1];
                smf[r * 132 + c]           = acc[mt][nt][0] + b0;
                smf[r * 132 + c + 1]       = acc[mt][nt][1] + b1;
                smf[(r + 8) * 132 + c]     = acc[mt][nt][2] + b0;
                smf[(r + 8) * 132 + c + 1] = acc[mt][nt][3] + b1;
            }
        }
        __syncthreads();
#pragma unroll
        for (int it = 0; it < 32; ++it) {
            int idx = it * 256 + tid;          // 0..8191
            int r = idx >> 6, d = idx & 63;
            float m  = smf[r * 132 + d];
            float lv = smf[r * 132 + 64 + d];
            int gi = (row0 + r) * 64 + d;
            float zv = m + expf(0.5f * lv) * ep[gi];
            g_ze[gi] = zv;
            outp[OUT_MEAN + gi] = m;
            outp[OUT_LV + gi]   = lv;
        }
        return;
    }

#pragma unroll
    for (int mt = 0; mt < 2; ++mt) {
        int r = row0 + wm * 32 + mt * 16 + (lane >> 2);
#pragma unroll
        for (int nt = 0; nt < 8; ++nt) {
            int c = col0 + wn * 64 + nt * 8 + (lane & 3) * 2;
            float b0 = bias[c], b1 = bias[c + 1];
            float v0 = fmaxf(acc[mt][nt][0] + b0, 0.0f);
            float v1 = fmaxf(acc[mt][nt][1] + b1, 0.0f);
            float v2 = fmaxf(acc[mt][nt][2] + b0, 0.0f);
            float v3 = fmaxf(acc[mt][nt][3] + b1, 0.0f);
            *(float2*)&C[(size_t)r * N + c]       = make_float2(v0, v1);
            *(float2*)&C[(size_t)(r + 8) * N + c] = make_float2(v2, v3);
        }
    }
}

// ---------------- persistent VQ kernel ----------------
__global__ __launch_bounds__(256, 1) void vq_kernel(
    const float* __restrict__ A, const float* __restrict__ cbk)
{
    extern __shared__ __align__(16) __nv_bfloat16 sm[];
    __shared__ float scsq[KC_];
    __shared__ float sdm[256];
    __shared__ int   sim[256];

    const int tid  = threadIdx.x;
    const int wid  = tid >> 5;
    const int lane = tid & 31;
    const int row0 = blockIdx.y * 128;
    const uint32_t smb = smem_u32(sm);

    for (int i = tid; i < KC_; i += 256) scsq[i] = g_csq[i];

    const int lrow = tid >> 3;
    const int lc4  = tid & 7;

    // ---- load A (z_e) tile: 2 k-stages, hi/lo ----
#pragma unroll
    for (int s2 = 0; s2 < 2; ++s2) {
#pragma unroll
        for (int i = 0; i < 4; ++i) {
            int row = lrow + i * 32;
            float4 v = *(const float4*)(A + (size_t)(row0 + row) * 64 + s2 * 32 + lc4 * 4);
            uint32_t h0, l0, h1, l1;
            split2(v.x, v.y, h0, l0);
            split2(v.z, v.w, h1, l1);
            uint32_t off = s2 * 10240 + row * 40 + lc4 * 4;
            *(uint2*)&sm[off]        = make_uint2(h0, h1);
            *(uint2*)&sm[off + 5120] = make_uint2(l0, l1);
        }
    }

    float4 pb[8];
    auto fetchB = [&](int cb) {
        int colcb = (blockIdx.x * VQ_CB + cb) * 128;
#pragma unroll
        for (int i = 0; i < 4; ++i) {
            int row = colcb + lrow + i * 32;
            pb[i]     = *(const float4*)(cbk + (size_t)row * 64 + lc4 * 4);
            pb[4 + i] = *(const float4*)(cbk + (size_t)row * 64 + 32 + lc4 * 4);
        }
    };
    auto storeB = [&](int buf) {
        uint32_t base = 20480 + (uint32_t)buf * 20480;
#pragma unroll
        for (int s2 = 0; s2 < 2; ++s2) {
#pragma unroll
            for (int i = 0; i < 4; ++i) {
                int row = lrow + i * 32;
                float4 v = pb[s2 * 4 + i];
                uint32_t h0, l0, h1, l1;
                split2(v.x, v.y, h0, l0);
                split2(v.z, v.w, h1, l1);
                uint32_t off = base + s2 * 10240 + row * 40 + lc4 * 4;
                *(uint2*)&sm[off]        = make_uint2(h0, h1);
                *(uint2*)&sm[off + 5120] = make_uint2(l0, l1);
            }
        }
    };

    const int wm = wid >> 1, wn = wid & 1;
    const int arow  = wm * 32 + (lane & 15);
    const int acolB = (lane >> 4) * 16;
    const int brow  = wn * 64 + ((lane >> 4) << 3) + (lane & 7);
    const int bkhB  = ((lane >> 3) & 1) * 16;

    fetchB(0);
    storeB(0);
    __syncthreads();

    float rbD[2][2] = {{3.4e38f, 3.4e38f}, {3.4e38f, 3.4e38f}};
    int   rbI[2][2] = {{0x7fffffff, 0x7fffffff}, {0x7fffffff, 0x7fffffff}};

    int buf = 0;
    for (int cb = 0; cb < VQ_CB; ++cb) {
        if (cb + 1 < VQ_CB) fetchB(cb + 1);

        float acc[2][8][4];
#pragma unroll
        for (int mt = 0; mt < 2; ++mt)
#pragma unroll
            for (int nt = 0; nt < 8; ++nt)
#pragma unroll
                for (int q = 0; q < 4; ++q) acc[mt][nt][q] = 0.0f;

        const uint32_t bbase = 40960u + (uint32_t)buf * 40960u;
#pragma unroll
        for (int s2 = 0; s2 < 2; ++s2) {
            const uint32_t aB = (uint32_t)s2 * 20480u;
            const uint32_t bB = bbase + (uint32_t)s2 * 20480u;
#pragma unroll
            for (int ks = 0; ks < 2; ++ks) {
                uint32_t ah[2][4], al[2][4];
#pragma unroll
                for (int mt = 0; mt < 2; ++mt) {
                    uint32_t addr = smb + aB + (uint32_t)(arow + mt * 16) * 80u
                                  + (uint32_t)ks * 32u + acolB;
                    ldsm4(ah[mt], addr);
                    ldsm4(al[mt], addr + 10240u);
                }
                uint32_t bh[8][2], bl[8][2];
#pragma unroll
                for (int p = 0; p < 4; ++p) {
                    uint32_t addr = smb + bB + (uint32_t)(brow + p * 16) * 80u
                                  + (uint32_t)ks * 32u + bkhB;
                    uint32_t r[4];
                    ldsm4(r, addr);
                    bh[2*p][0] = r[0]; bh[2*p][1] = r[1];
                    bh[2*p+1][0] = r[2]; bh[2*p+1][1] = r[3];
                    ldsm4(r, addr + 10240u);
                    bl[2*p][0] = r[0]; bl[2*p][1] = r[1];
                    bl[2*p+1][0] = r[2]; bl[2*p+1][1] = r[3];
                }
#pragma unroll
                for (int mt = 0; mt < 2; ++mt)
#pragma unroll
                    for (int nt = 0; nt < 8; ++nt) {
                        mma_bf16(acc[mt][nt], ah[mt], bh[nt][0], bh[nt][1]);
                        mma_bf16(acc[mt][nt], ah[mt], bl[nt][0], bl[nt][1]);
                        mma_bf16(acc[mt][nt], al[mt], bh[nt][0], bh[nt][1]);
                    }
            }
        }

        int colcb = (blockIdx.x * VQ_CB + cb) * 128;
#pragma unroll
        for (int mt = 0; mt < 2; ++mt) {
#pragma unroll
            for (int rp = 0; rp < 2; ++rp) {
                float best = 3.4e38f; int bidx = 0;
#pragma unroll
                for (int nt = 0; nt < 8; ++nt) {
                    int cg = colcb + wn * 64 + nt * 8 + (lane & 3) * 2;
                    float d0 = scsq[cg]     - 2.0f * acc[mt][nt][rp * 2 + 0];
                    float d1 = scsq[cg + 1] - 2.0f * acc[mt][nt][rp * 2 + 1];
                    if (d0 < best) { best = d0; bidx = cg;     }
                    if (d1 < best) { best = d1; bidx = cg + 1; }
                }
#pragma unroll
                for (int msk = 1; msk <= 2; msk <<= 1) {
                    float od = __shfl_xor_sync(0xffffffffu, best, msk);
                    int   oi = __shfl_xor_sync(0xffffffffu, bidx, msk);
                    if (od < best || (od == best && oi < bidx)) { best = od; bidx = oi; }
                }
                if (best < rbD[mt][rp] || (best == rbD[mt][rp] && bidx < rbI[mt][rp])) {
                    rbD[mt][rp] = best; rbI[mt][rp] = bidx;
                }
            }
        }

        if (cb + 1 < VQ_CB) {
            __syncthreads();
            storeB(buf ^ 1);
            __syncthreads();
            buf ^= 1;
        }
    }

    if ((lane & 3) == 0) {
#pragma unroll
        for (int mt = 0; mt < 2; ++mt)
#pragma unroll
            for (int rp = 0; rp < 2; ++rp) {
                int rl = wm * 32 + mt * 16 + rp * 8 + (lane >> 2);
                sdm[wn * 128 + rl] = rbD[mt][rp];
                sim[wn * 128 + rl] = rbI[mt][rp];
            }
    }
    __syncthreads();
    if (tid < 128) {
        float d0 = sdm[tid], d1 = sdm[128 + tid];
        int   i0 = sim[tid], i1 = sim[128 + tid];
        bool t1 = (d1 < d0) || (d1 == d0 && i1 < i0);
        g_candD[(size_t)blockIdx.x * T_ + row0 + tid] = t1 ? d1 : d0;
        g_candI[(size_t)blockIdx.x * T_ + row0 + tid] = t1 ? i1 : i0;
    }
}

// ---------------- fused prep: 3 weight transposes + codebook sq norms ------------
__device__ __forceinline__ void transpose_tile(const float* __restrict__ W,
                                               float* __restrict__ Wt,
                                               int K, int N, int kb, int nb, int tid)
{
    __shared__ float tile[32][33];
    int tx = tid & 31, ty = tid >> 5;   // 32 x 8
#pragma unroll
    for (int i = 0; i < 32; i += 8) {
        int k = kb + ty + i, n = nb + tx;
        tile[ty + i][tx] = (k < K && n < N) ? W[(size_t)k * N + n] : 0.0f;
    }
    __syncthreads();
#pragma unroll
    for (int i = 0; i < 32; i += 8) {
        int n = nb + ty + i, k = kb + tx;
        if (n < N && k < K) Wt[(size_t)n * K + k] = tile[tx][ty + i];
    }
}

__global__ void prep_kernel(const float* __restrict__ We1, const float* __restrict__ We2,
                            const float* __restrict__ We3, const float* __restrict__ cb)
{
    int bx = blockIdx.x, tid = threadIdx.x;
    if (bx < 352) {               // W1: 16 x 22 tiles
        transpose_tile(We1, g_wt1, F_,  H1_, (bx >> 4) * 32, (bx & 15) * 32, tid);
    } else if (bx < 480) {        // W2: 8 x 16 tiles
        int b = bx - 352;
        transpose_tile(We2, g_wt2, H1_, H2_, (b >> 3) * 32, (b & 7) * 32, tid);
    } else if (bx < 512) {        // W3: 4 x 8 tiles
        int b = bx - 480;
        transpose_tile(We3, g_wt3, H2_, ENC_, (b >> 2) * 32, (b & 3) * 32, tid);
    } else {                      // csq: 4 blocks x 256 codes
        int k = (bx - 512) * 256 + tid;
        const float4* c = (const float4*)cb + k * 16;
        float s = 0.0f;
#pragma unroll
        for (int i = 0; i < 16; ++i) {
            float4 v = c[i];
            s += v.x * v.x + v.y * v.y + v.z * v.z + v.w * v.w;
        }
        g_csq[k] = s;
    }
}

// ---------------- fused VQ-finish + decoder GEMM1 split-K partials ----------------
// CTA c owns K-chunk [256c, 256c+256) = tokens (b, s in [4c, 4c+4)), 64 tokens.
// Reduces the 2 VQ candidates, gathers the code row straight into zs smem
// (g_zq never materialized), emits per-token loss, then runs the dec1 mainloop.
__global__ __launch_bounds__(256) void dec1_vq_kernel(const float* __restrict__ W,
                                                      const float* __restrict__ cbk)
{
    __shared__ __align__(16) float zs[256 * 16];   // zs[kk*16 + b]
    const int c    = blockIdx.x;
    const int k0   = c * 256;
    const int wid  = threadIdx.x >> 5;
    const int lane = threadIdx.x & 31;

    // 64 tokens, 8 warps x 8 iterations
#pragma unroll
    for (int i = 0; i < 8; ++i) {
        int tt = i * 8 + wid;                 // 0..63
        int b = tt >> 2, j = tt & 3;
        int t = b * S_ + 4 * c + j;

        float d = 3.4e38f; int ix = 0x7fffffff;
        if (lane < NCB) {
            d  = g_candD[(size_t)lane * T_ + t];
            ix = g_candI[(size_t)lane * T_ + t];
        }
        {
            float od = __shfl_down_sync(0xffffffffu, d, 1);
            int   oi = __shfl_down_sync(0xffffffffu, ix, 1);
            if (od < d || (od == d && oi < ix)) { d = od; ix = oi; }
        }
        ix = __shfl_sync(0xffffffffu, ix, 0);

        float l = 0.0f;
        if (lane < 16) {
            float4 cv = ((const float4*)cbk)[ix * 16 + lane];
            float4 zv = ((const float4*)g_ze)[t * 16 + lane];
            int kk = j * 64 + lane * 4;
            zs[(kk + 0) * 16 + b] = cv.x;
            zs[(kk + 1) * 16 + b] = cv.y;
            zs[(kk + 2) * 16 + b] = cv.z;
            zs[(kk + 3) * 16 + b] = cv.w;
            float dx = zv.x - cv.x, dy = zv.y - cv.y;
            float dz = zv.z - cv.z, dw = zv.w - cv.w;
            l = dx * dx + dy * dy + dz * dz + dw * dw;
        }
#pragma unroll
        for (int off = 16; off; off >>= 1)
            l += __shfl_down_sync(0xffffffffu, l, off);
        if (lane == 0) g_tokloss[t] = l;
    }
    __syncthreads();

    int n = threadIdx.x;
    u64 acc[8];
#pragma unroll
    for (int b2 = 0; b2 < 8; ++b2) acc[b2] = 0ULL;

#pragma unroll 4
    for (int kk = 0; kk < 256; ++kk) {
        u64 wd = dupf(W[(size_t)(k0 + kk) * H2_ + n]);
        const ulonglong2* dk = (const ulonglong2*)(zs + kk * 16);
        ulonglong2 p0 = dk[0], p1 = dk[1], p2 = dk[2], p3 = dk[3];
        u64 dp[8] = {p0.x, p0.y, p1.x, p1.y, p2.x, p2.y, p3.x, p3.y};
#pragma unroll
        for (int b2 = 0; b2 < 8; ++b2) ffma2(acc[b2], dp[b2], wd);
    }
#pragma unroll
    for (int b2 = 0; b2 < 8; ++b2) {
        float2 f = unpk(acc[b2]);
        g_dpart[blockIdx.x * 4096 + (2*b2)   * H2_ + n] = f.x;
        g_dpart[blockIdx.x * 4096 + (2*b2+1) * H2_ + n] = f.y;
    }
}

// fused: blocks 0-15 finish dec1; block 16 does vq_loss
__global__ void dec1fin_vqloss_kernel(const float* __restrict__ bias, float* __restrict__ out) {
    if (blockIdx.x < 16) {
        int n = blockIdx.x * 256 + threadIdx.x;
        float s = 0.0f;
        for (int c = 0; c < DEC1_CHUNKS; ++c) s += g_dpart[c * 4096 + n];
        g_dvec[n] = fmaxf(s + bias[n & 255], 0.0f);
    } else {
        __shared__ float sb[256];
        float a = 0.0f;
        for (int i = threadIdx.x; i < T_; i += 256) a += g_tokloss[i];
        sb[threadIdx.x] = a;
        __syncthreads();
        for (int s = 128; s > 0; s >>= 1) {
            if (threadIdx.x < s) sb[threadIdx.x] += sb[threadIdx.x + s];
            __syncthreads();
        }
        if (threadIdx.x == 0) out[OUT_VQL] = sb[0] / (float)(T_ * D_);
    }
}

__global__ __launch_bounds__(256, 2) void dec2_kernel(
    const float* __restrict__ W, const float* __restrict__ bias,
    float* __restrict__ out)
{
    __shared__ __align__(16) float ds[H2_ * 16];
    for (int i = threadIdx.x; i < 4096; i += 256) {
        int b = i >> 8, k = i & 255;
        ds[k * 16 + b] = g_dvec[i];
    }
    __syncthreads();

    int n = (blockIdx.x * 256 + threadIdx.x) * 4;
    if (n >= SF_) return;

    u64 acc[8][4];
#pragma unroll
    for (int b2 = 0; b2 < 8; ++b2)
#pragma unroll
        for (int c = 0; c < 4; ++c) acc[b2][c] = 0ULL;

#pragma unroll 4
    for (int k = 0; k < H2_; ++k) {
        float4 w = *(const float4*)(W + (size_t)k * SF_ + n);
        u64 wd[4] = {dupf(w.x), dupf(w.y), dupf(w.z), dupf(w.w)};
        const ulonglong2* dk = (const ulonglong2*)(ds + k * 16);
        ulonglong2 p0 = dk[0], p1 = dk[1], p2 = dk[2], p3 = dk[3];
        u64 dp[8] = {p0.x, p0.y, p1.x, p1.y, p2.x, p2.y, p3.x, p3.y};
#pragma unroll
        for (int b2 = 0; b2 < 8; ++b2)
#pragma unroll
            for (int c = 0; c < 4; ++c)
                ffma2(acc[b2][c], dp[b2], wd[c]);
    }

    float4 bb = *(const float4*)(bias + n);
#pragma unroll
    for (int b2 = 0; b2 < 8; ++b2) {
        float2 f0 = unpk(acc[b2][0]);
        float2 f1 = unpk(acc[b2][1]);
        float2 f2 = unpk(acc[b2][2]);
        float2 f3 = unpk(acc[b2][3]);
        float4 v0, v1;
        v0.x = softplusf(f0.x + bb.x);
        v0.y = softplusf(f1.x + bb.y);
        v0.z = softplusf(f2.x + bb.z);
        v0.w = softplusf(f3.x + bb.w);
        v1.x = softplusf(f0.y + bb.x);
        v1.y = softplusf(f1.y + bb.y);
        v1.z = softplusf(f2.y + bb.z);
        v1.w = softplusf(f3.y + bb.w);
        *(float4*)(out + (size_t)(2*b2)   * SF_ + n) = v0;
        *(float4*)(out + (size_t)(2*b2+1) * SF_ + n) = v1;
    }
}

// ---------------- launch ----------------
#define SYM(var) ({ void* _p; cudaGetSymbolAddress(&_p, var); _p; })

extern "C" void kernel_launch(void* const* d_in, const int* in_sizes, int n_in,
                              void* d_out, int out_size)
{
    const float* x   = (const float*)d_in[0];
    const float* eps = (const float*)d_in[1];
    const float* We1 = (const float*)d_in[2];
    const float* be1 = (const float*)d_in[3];
    const float* We2 = (const float*)d_in[4];
    const float* be2 = (const float*)d_in[5];
    const float* We3 = (const float*)d_in[6];
    const float* be3 = (const float*)d_in[7];
    const float* cb  = (const float*)d_in[8];
    const float* Wd1 = (const float*)d_in[9];
    const float* bd1 = (const float*)d_in[10];
    const float* Wd2 = (const float*)d_in[11];
    const float* bd2 = (const float*)d_in[12];
    float* out = (float*)d_out;

    float *h1  = (float*)SYM(g_h1);
    float *h2  = (float*)SYM(g_h2);
    float *ze  = (float*)SYM(g_ze);
    float *wt1 = (float*)SYM(g_wt1);
    float *wt2 = (float*)SYM(g_wt2);
    float *wt3 = (float*)SYM(g_wt3);

    cudaFuncSetAttribute(mma_gemm<1>, cudaFuncAttributeMaxDynamicSharedMemorySize, SMEM_BYTES);
    cudaFuncSetAttribute(mma_gemm<5>, cudaFuncAttributeMaxDynamicSharedMemorySize, SMEM_BYTES);
    cudaFuncSetAttribute(vq_kernel,   cudaFuncAttributeMaxDynamicSharedMemorySize, SMEM_BYTES);

    // fused prep: 3 transposes + codebook norms
    prep_kernel<<<516, 256>>>(We1, We2, We3, cb);

    // encoder MLP on tensor cores (bf16x3)
    mma_gemm<1><<<dim3(4, 72), 256, SMEM_BYTES>>>(T_, H1_, F_,
        x,  wt1, be1, h1, nullptr, nullptr);
    mma_gemm<1><<<dim3(2, 72), 256, SMEM_BYTES>>>(T_, H2_, H1_,
        h1, wt2, be2, h2, nullptr, nullptr);
    // encoder head: GEMM + bias + reparameterize fused
    mma_gemm<5><<<dim3(1, 72), 256, SMEM_BYTES>>>(T_, ENC_, H2_,
        h2, wt3, be3, nullptr, eps, out);

    // persistent VQ: cross GEMM + running argmin (2 candidates/token)
    vq_kernel<<<dim3(NCB, 72), 256, SMEM_BYTES>>>(ze, cb);

    // decoder: fused VQ-finish + GEMM1 partials, then reduce + dec2
    dec1_vq_kernel<<<DEC1_CHUNKS, 256>>>(Wd1, cb);
    dec1fin_vqloss_kernel<<<17, 256>>>(bd1, out);
    dec2_kernel<<<(SF_ / 4 + 255) / 256, 256>>>(Wd2, bd2, out);
}

// round 12
// speedup vs baseline: 1.2959x; 1.1216x over previous
#include <cuda_runtime.h>
#include <cuda_bf16.h>
#include <math.h>
#include <stdint.h>

// ---------------- problem constants ----------------
#define B_      16
#define S_      576
#define F_      700
#define D_      64
#define KC_     1024
#define T_      (B_*S_)         // 9216 tokens
#define H1_     512
#define H2_     256
#define ENC_    128             // 2*D
#define SF_     (S_*F_)         // 403200
#define SD_     (S_*D_)         // 36864

#define OUT_REC  0
#define OUT_MEAN (B_*SF_)
#define OUT_LV   (OUT_MEAN + T_*D_)
#define OUT_VQL  (OUT_LV + T_*D_)

#define DEC1_CHUNKS 144
#define NCB         2            // candidate blocks (vq grid.x)
#define VQ_CB       4            // codebook col-blocks per vq CTA

typedef unsigned long long u64;
typedef __nv_bfloat16 bf16;

// ---------------- scratch (device globals; no allocation allowed) ----------------
__device__ __align__(256) float g_h1[T_*H1_];
__device__ __align__(256) float g_h2[T_*H2_];
__device__ __align__(256) float g_ze[T_*D_];
__device__ __align__(256) float g_csq[KC_];
__device__ __align__(256) float g_tokloss[T_];
__device__ __align__(256) float g_dpart[DEC1_CHUNKS*16*H2_];
__device__ __align__(256) float g_dvec[16*H2_];
__device__ __align__(256) float g_wt1[H1_*F_];
__device__ __align__(256) float g_wt2[H2_*H1_];
__device__ __align__(256) float g_wt3[ENC_*H2_];
__device__ __align__(256) float g_candD[NCB*T_];
__device__ __align__(256) int   g_candI[NCB*T_];

// ---------------- f32x2 helpers (decoder kernels) ----------------
__device__ __forceinline__ u64 dupf(float a) {
    unsigned r = __float_as_uint(a);
    u64 d;
    asm("mov.b64 %0, {%1, %1};" : "=l"(d) : "r"(r));
    return d;
}
__device__ __forceinline__ void ffma2(u64 &d, u64 a, u64 b) {
    asm("fma.rn.f32x2 %0, %1, %2, %0;" : "+l"(d) : "l"(a), "l"(b));
}
__device__ __forceinline__ float2 unpk(u64 v) {
    unsigned lo, hi;
    asm("mov.b64 {%0, %1}, %2;" : "=r"(lo), "=r"(hi) : "l"(v));
    return make_float2(__uint_as_float(lo), __uint_as_float(hi));
}
__device__ __forceinline__ float softplusf(float x) {
    return fmaxf(x, 0.0f) + log1pf(expf(-fabsf(x)));
}

// ---------------- mma.sync helpers ----------------
__device__ __forceinline__ uint32_t smem_u32(const void* p) {
    uint32_t a;
    asm("{ .reg .u64 t; cvta.to.shared.u64 t, %1; cvt.u32.u64 %0, t; }" : "=r"(a) : "l"(p));
    return a;
}
__device__ __forceinline__ void ldsm4(uint32_t (&r)[4], uint32_t addr) {
    asm volatile("ldmatrix.sync.aligned.m8n8.x4.shared.b16 {%0,%1,%2,%3}, [%4];"
                 : "=r"(r[0]), "=r"(r[1]), "=r"(r[2]), "=r"(r[3]) : "r"(addr));
}
__device__ __forceinline__ void mma_bf16(float (&d)[4], const uint32_t (&a)[4],
                                         uint32_t b0, uint32_t b1) {
    asm volatile("mma.sync.aligned.m16n8k16.row.col.f32.bf16.bf16.f32 "
                 "{%0,%1,%2,%3}, {%4,%5,%6,%7}, {%8,%9}, {%0,%1,%2,%3};"
                 : "+f"(d[0]), "+f"(d[1]), "+f"(d[2]), "+f"(d[3])
                 : "r"(a[0]), "r"(a[1]), "r"(a[2]), "r"(a[3]), "r"(b0), "r"(b1));
}
// split fp32 pair -> packed bf16x2 hi and lo
__device__ __forceinline__ void split2(float x, float y, uint32_t &hi, uint32_t &lo) {
    __nv_bfloat162 h = __floats2bfloat162_rn(x, y);
    float hx = __bfloat162float(h.x), hy = __bfloat162float(h.y);
    __nv_bfloat162 l = __floats2bfloat162_rn(x - hx, y - hy);
    hi = *reinterpret_cast<uint32_t*>(&h);
    lo = *reinterpret_cast<uint32_t*>(&l);
}

// SMEM per stage: 20480 bf16 elems (40960 B): Ah[128][40] | Al +5120 | Bh +10240 | Bl +15360
#define STAGE_E   20480
#define NSTG      3
#define SMEM_BYTES (NSTG * STAGE_E * 2)

// ---------------- bf16x3 tensor-core GEMM, 3-buffer single-sync pipeline ---------
// MODE 1: relu+bias fp32 out.  MODE 5: encoder head — fused bias + reparam epilogue.
template<int MODE>
__global__ __launch_bounds__(256, 1) void mma_gemm(
    int M, int N, int K,
    const float* __restrict__ A, const float* __restrict__ Bt,
    const float* __restrict__ bias, float* __restrict__ C,
    const float* __restrict__ ep, float* __restrict__ outp)
{
    extern __shared__ __align__(16) __nv_bfloat16 sm[];
    const int tid  = threadIdx.x;
    const int wid  = tid >> 5;
    const int lane = tid & 31;
    const int row0 = blockIdx.y * 128;
    const int col0 = blockIdx.x * 128;
    const int NS = (K + 31) >> 5;
    const uint32_t smb = smem_u32(sm);

    float acc[2][8][4];
#pragma unroll
    for (int mt = 0; mt < 2; ++mt)
#pragma unroll
        for (int nt = 0; nt < 8; ++nt)
#pragma unroll
            for (int q = 0; q < 4; ++q) acc[mt][nt][q] = 0.0f;

    const int lrow = tid >> 3;        // 0..31 base row (with +32*i)
    const int lc4  = tid & 7;         // float4 col within BK

    float4 pa[4], pb[4];

    auto fetch = [&](int k0) {
#pragma unroll
        for (int i = 0; i < 4; ++i) {
            int row = lrow + i * 32;
            int kk  = k0 + lc4 * 4;
            if (kk < K) {
                pa[i] = *(const float4*)(A  + (size_t)(row0 + row) * K + kk);
                pb[i] = *(const float4*)(Bt + (size_t)(col0 + row) * K + kk);
            } else {
                pa[i] = make_float4(0.f, 0.f, 0.f, 0.f);
                pb[i] = make_float4(0.f, 0.f, 0.f, 0.f);
            }
        }
    };

    auto store_to = [&](int slot) {
        uint32_t stg = (uint32_t)slot * STAGE_E;
#pragma unroll
        for (int i = 0; i < 4; ++i) {
            int row = lrow + i * 32;
            uint32_t off = stg + row * 40 + lc4 * 4;
            uint32_t h0, l0, h1, l1;
            split2(pa[i].x, pa[i].y, h0, l0);
            split2(pa[i].z, pa[i].w, h1, l1);
            *(uint2*)&sm[off]          = make_uint2(h0, h1);
            *(uint2*)&sm[off + 5120]   = make_uint2(l0, l1);
            split2(pb[i].x, pb[i].y, h0, l0);
            split2(pb[i].z, pb[i].w, h1, l1);
            *(uint2*)&sm[off + 10240]  = make_uint2(h0, h1);
            *(uint2*)&sm[off + 15360]  = make_uint2(l0, l1);
        }
    };

    const int wm = wid >> 1, wn = wid & 1;
    const int arow  = wm * 32 + (lane & 15);
    const int acolB = (lane >> 4) * 16;
    const int brow  = wn * 64 + ((lane >> 4) << 3) + (lane & 7);
    const int bkhB  = ((lane >> 3) & 1) * 16;

    auto compute = [&](int slot) {
        const uint32_t stgB = (uint32_t)slot * (STAGE_E * 2);
#pragma unroll
        for (int ks = 0; ks < 2; ++ks) {
            uint32_t ah[2][4], al[2][4];
#pragma unroll
            for (int mt = 0; mt < 2; ++mt) {
                uint32_t addr = smb + stgB + (uint32_t)(arow + mt * 16) * 80u
                              + (uint32_t)ks * 32u + acolB;
                ldsm4(ah[mt], addr);
                ldsm4(al[mt], addr + 10240u);
            }
            uint32_t bh[8][2], bl[8][2];
#pragma unroll
            for (int p = 0; p < 4; ++p) {
                uint32_t addr = smb + stgB + 20480u + (uint32_t)(brow + p * 16) * 80u
                              + (uint32_t)ks * 32u + bkhB;
                uint32_t r[4];
                ldsm4(r, addr);
                bh[2*p][0] = r[0]; bh[2*p][1] = r[1];
                bh[2*p+1][0] = r[2]; bh[2*p+1][1] = r[3];
                ldsm4(r, addr + 10240u);
                bl[2*p][0] = r[0]; bl[2*p][1] = r[1];
                bl[2*p+1][0] = r[2]; bl[2*p+1][1] = r[3];
            }
#pragma unroll
            for (int mt = 0; mt < 2; ++mt)
#pragma unroll
                for (int nt = 0; nt < 8; ++nt) {
                    mma_bf16(acc[mt][nt], ah[mt], bh[nt][0], bh[nt][1]);
                    mma_bf16(acc[mt][nt], ah[mt], bl[nt][0], bl[nt][1]);
                    mma_bf16(acc[mt][nt], al[mt], bh[nt][0], bh[nt][1]);
                }
        }
    };

    fetch(0);
    store_to(0);
    if (NS > 1) fetch(32);

    int scur = 0, sst = 1;
    for (int s = 0; s < NS; ++s) {
        __syncthreads();
        if (s + 1 < NS) store_to(sst);
        if (s + 2 < NS) fetch((s + 2) * 32);
        compute(scur);
        scur = (scur + 1 == NSTG) ? 0 : scur + 1;
        sst  = (sst  + 1 == NSTG) ? 0 : sst  + 1;
    }

    // ---- epilogue ----
    if (MODE == 5) {
        __syncthreads();
        float* smf = (float*)sm;       // [128][132]
#pragma unroll
        for (int mt = 0; mt < 2; ++mt) {
            int r = wm * 32 + mt * 16 + (lane >> 2);
#pragma unroll
            for (int nt = 0; nt < 8; ++nt) {
                int c = wn * 64 + nt * 8 + (lane & 3) * 2;
                float b0 = bias[c], b1 = bias[c + 1];
                smf[r * 132 + c]           = acc[mt][nt][0] + b0;
                smf[r * 132 + c + 1]       = acc[mt][nt][1] + b1;
                smf[(r + 8) * 132 + c]     = acc[mt][nt][2] + b0;
                smf[(r + 8) * 132 + c + 1] = acc[mt][nt][3] + b1;
            }
        }
        __syncthreads();
#pragma unroll
        for (int it = 0; it < 32; ++it) {
            int idx = it * 256 + tid;          // 0..8191
            int r = idx >> 6, d = idx & 63;
            float m  = smf[r * 132 + d];
            float lv = smf[r * 132 + 64 + d];
            int gi = (row0 + r) * 64 + d;
            float zv = m + expf(0.5f * lv) * ep[gi];
            g_ze[gi] = zv;
            outp[OUT_MEAN + gi] = m;
            outp[OUT_LV + gi]   = lv;
        }
        return;
    }

#pragma unroll
    for (int mt = 0; mt < 2; ++mt) {
        int r = row0 + wm * 32 + mt * 16 + (lane >> 2);
#pragma unroll
        for (int nt = 0; nt < 8; ++nt) {
            int c = col0 + wn * 64 + nt * 8 + (lane & 3) * 2;
            float b0 = bias[c], b1 = bias[c + 1];
            float v0 = fmaxf(acc[mt][nt][0] + b0, 0.0f);
            float v1 = fmaxf(acc[mt][nt][1] + b1, 0.0f);
            float v2 = fmaxf(acc[mt][nt][2] + b0, 0.0f);
            float v3 = fmaxf(acc[mt][nt][3] + b1, 0.0f);
            *(float2*)&C[(size_t)r * N + c]       = make_float2(v0, v1);
            *(float2*)&C[(size_t)(r + 8) * N + c] = make_float2(v2, v3);
        }
    }
}

// ---------------- persistent VQ kernel ----------------
__global__ __launch_bounds__(256, 1) void vq_kernel(
    const float* __restrict__ A, const float* __restrict__ cbk)
{
    extern __shared__ __align__(16) __nv_bfloat16 sm[];
    __shared__ float scsq[KC_];
    __shared__ float sdm[256];
    __shared__ int   sim[256];

    const int tid  = threadIdx.x;
    const int wid  = tid >> 5;
    const int lane = tid & 31;
    const int row0 = blockIdx.y * 128;
    const uint32_t smb = smem_u32(sm);

    for (int i = tid; i < KC_; i += 256) scsq[i] = g_csq[i];

    const int lrow = tid >> 3;
    const int lc4  = tid & 7;

    // ---- load A (z_e) tile: 2 k-stages, hi/lo ----
#pragma unroll
    for (int s2 = 0; s2 < 2; ++s2) {
#pragma unroll
        for (int i = 0; i < 4; ++i) {
            int row = lrow + i * 32;
            float4 v = *(const float4*)(A + (size_t)(row0 + row) * 64 + s2 * 32 + lc4 * 4);
            uint32_t h0, l0, h1, l1;
            split2(v.x, v.y, h0, l0);
            split2(v.z, v.w, h1, l1);
            uint32_t off = s2 * 10240 + row * 40 + lc4 * 4;
            *(uint2*)&sm[off]        = make_uint2(h0, h1);
            *(uint2*)&sm[off + 5120] = make_uint2(l0, l1);
        }
    }

    float4 pb[8];
    auto fetchB = [&](int cb) {
        int colcb = (blockIdx.x * VQ_CB + cb) * 128;
#pragma unroll
        for (int i = 0; i < 4; ++i) {
            int row = colcb + lrow + i * 32;
            pb[i]     = *(const float4*)(cbk + (size_t)row * 64 + lc4 * 4);
            pb[4 + i] = *(const float4*)(cbk + (size_t)row * 64 + 32 + lc4 * 4);
        }
    };
    auto storeB = [&](int buf) {
        uint32_t base = 20480 + (uint32_t)buf * 20480;
#pragma unroll
        for (int s2 = 0; s2 < 2; ++s2) {
#pragma unroll
            for (int i = 0; i < 4; ++i) {
                int row = lrow + i * 32;
                float4 v = pb[s2 * 4 + i];
                uint32_t h0, l0, h1, l1;
                split2(v.x, v.y, h0, l0);
                split2(v.z, v.w, h1, l1);
                uint32_t off = base + s2 * 10240 + row * 40 + lc4 * 4;
                *(uint2*)&sm[off]        = make_uint2(h0, h1);
                *(uint2*)&sm[off + 5120] = make_uint2(l0, l1);
            }
        }
    };

    const int wm = wid >> 1, wn = wid & 1;
    const int arow  = wm * 32 + (lane & 15);
    const int acolB = (lane >> 4) * 16;
    const int brow  = wn * 64 + ((lane >> 4) << 3) + (lane & 7);
    const int bkhB  = ((lane >> 3) & 1) * 16;

    fetchB(0);
    storeB(0);
    __syncthreads();

    float rbD[2][2] = {{3.4e38f, 3.4e38f}, {3.4e38f, 3.4e38f}};
    int   rbI[2][2] = {{0x7fffffff, 0x7fffffff}, {0x7fffffff, 0x7fffffff}};

    int buf = 0;
    for (int cb = 0; cb < VQ_CB; ++cb) {
        if (cb + 1 < VQ_CB) fetchB(cb + 1);

        float acc[2][8][4];
#pragma unroll
        for (int mt = 0; mt < 2; ++mt)
#pragma unroll
            for (int nt = 0; nt < 8; ++nt)
#pragma unroll
                for (int q = 0; q < 4; ++q) acc[mt][nt][q] = 0.0f;

        const uint32_t bbase = 40960u + (uint32_t)buf * 40960u;
#pragma unroll
        for (int s2 = 0; s2 < 2; ++s2) {
            const uint32_t aB = (uint32_t)s2 * 20480u;
            const uint32_t bB = bbase + (uint32_t)s2 * 20480u;
#pragma unroll
            for (int ks = 0; ks < 2; ++ks) {
                uint32_t ah[2][4], al[2][4];
#pragma unroll
                for (int mt = 0; mt < 2; ++mt) {
                    uint32_t addr = smb + aB + (uint32_t)(arow + mt * 16) * 80u
                                  + (uint32_t)ks * 32u + acolB;
                    ldsm4(ah[mt], addr);
                    ldsm4(al[mt], addr + 10240u);
                }
                uint32_t bh[8][2], bl[8][2];
#pragma unroll
                for (int p = 0; p < 4; ++p) {
                    uint32_t addr = smb + bB + (uint32_t)(brow + p * 16) * 80u
                                  + (uint32_t)ks * 32u + bkhB;
                    uint32_t r[4];
                    ldsm4(r, addr);
                    bh[2*p][0] = r[0]; bh[2*p][1] = r[1];
                    bh[2*p+1][0] = r[2]; bh[2*p+1][1] = r[3];
                    ldsm4(r, addr + 10240u);
                    bl[2*p][0] = r[0]; bl[2*p][1] = r[1];
                    bl[2*p+1][0] = r[2]; bl[2*p+1][1] = r[3];
                }
#pragma unroll
                for (int mt = 0; mt < 2; ++mt)
#pragma unroll
                    for (int nt = 0; nt < 8; ++nt) {
                        mma_bf16(acc[mt][nt], ah[mt], bh[nt][0], bh[nt][1]);
                        mma_bf16(acc[mt][nt], ah[mt], bl[nt][0], bl[nt][1]);
                        mma_bf16(acc[mt][nt], al[mt], bh[nt][0], bh[nt][1]);
                    }
            }
        }

        int colcb = (blockIdx.x * VQ_CB + cb) * 128;
#pragma unroll
        for (int mt = 0; mt < 2; ++mt) {
#pragma unroll
            for (int rp = 0; rp < 2; ++rp) {
                float best = 3.4e38f; int bidx = 0;
#pragma unroll
                for (int nt = 0; nt < 8; ++nt) {
                    int cg = colcb + wn * 64 + nt * 8 + (lane & 3) * 2;
                    float d0 = scsq[cg]     - 2.0f * acc[mt][nt][rp * 2 + 0];
                    float d1 = scsq[cg + 1] - 2.0f * acc[mt][nt][rp * 2 + 1];
                    if (d0 < best) { best = d0; bidx = cg;     }
                    if (d1 < best) { best = d1; bidx = cg + 1; }
                }
#pragma unroll
                for (int msk = 1; msk <= 2; msk <<= 1) {
                    float od = __shfl_xor_sync(0xffffffffu, best, msk);
                    int   oi = __shfl_xor_sync(0xffffffffu, bidx, msk);
                    if (od < best || (od == best && oi < bidx)) { best = od; bidx = oi; }
                }
                if (best < rbD[mt][rp] || (best == rbD[mt][rp] && bidx < rbI[mt][rp])) {
                    rbD[mt][rp] = best; rbI[mt][rp] = bidx;
                }
            }
        }

        if (cb + 1 < VQ_CB) {
            __syncthreads();
            storeB(buf ^ 1);
            __syncthreads();
            buf ^= 1;
        }
    }

    if ((lane & 3) == 0) {
#pragma unroll
        for (int mt = 0; mt < 2; ++mt)
#pragma unroll
            for (int rp = 0; rp < 2; ++rp) {
                int rl = wm * 32 + mt * 16 + rp * 8 + (lane >> 2);
                sdm[wn * 128 + rl] = rbD[mt][rp];
                sim[wn * 128 + rl] = rbI[mt][rp];
            }
    }
    __syncthreads();
    if (tid < 128) {
        float d0 = sdm[tid], d1 = sdm[128 + tid];
        int   i0 = sim[tid], i1 = sim[128 + tid];
        bool t1 = (d1 < d0) || (d1 == d0 && i1 < i0);
        g_candD[(size_t)blockIdx.x * T_ + row0 + tid] = t1 ? d1 : d0;
        g_candI[(size_t)blockIdx.x * T_ + row0 + tid] = t1 ? i1 : i0;
    }
}

// ---------------- fused prep: 3 weight transposes + codebook sq norms ------------
__device__ __forceinline__ void transpose_tile(const float* __restrict__ W,
                                               float* __restrict__ Wt,
                                               int K, int N, int kb, int nb, int tid)
{
    __shared__ float tile[32][33];
    int tx = tid & 31, ty = tid >> 5;   // 32 x 8
#pragma unroll
    for (int i = 0; i < 32; i += 8) {
        int k = kb + ty + i, n = nb + tx;
        tile[ty + i][tx] = (k < K && n < N) ? W[(size_t)k * N + n] : 0.0f;
    }
    __syncthreads();
#pragma unroll
    for (int i = 0; i < 32; i += 8) {
        int n = nb + ty + i, k = kb + tx;
        if (n < N && k < K) Wt[(size_t)n * K + k] = tile[tx][ty + i];
    }
}

__global__ void prep_kernel(const float* __restrict__ We1, const float* __restrict__ We2,
                            const float* __restrict__ We3, const float* __restrict__ cb)
{
    int bx = blockIdx.x, tid = threadIdx.x;
    if (bx < 352) {               // W1: 16 x 22 tiles
        transpose_tile(We1, g_wt1, F_,  H1_, (bx >> 4) * 32, (bx & 15) * 32, tid);
    } else if (bx < 480) {        // W2: 8 x 16 tiles
        int b = bx - 352;
        transpose_tile(We2, g_wt2, H1_, H2_, (b >> 3) * 32, (b & 7) * 32, tid);
    } else if (bx < 512) {        // W3: 4 x 8 tiles
        int b = bx - 480;
        transpose_tile(We3, g_wt3, H2_, ENC_, (b >> 2) * 32, (b & 3) * 32, tid);
    } else {                      // csq: 4 blocks x 256 codes
        int k = (bx - 512) * 256 + tid;
        const float4* c = (const float4*)cb + k * 16;
        float s = 0.0f;
#pragma unroll
        for (int i = 0; i < 16; ++i) {
            float4 v = c[i];
            s += v.x * v.x + v.y * v.y + v.z * v.z + v.w * v.w;
        }
        g_csq[k] = s;
    }
}

// ---------------- fused VQ-finish + decoder GEMM1 split-K partials ----------------
// CTA c owns K-chunk [256c, 256c+256) = tokens (b, s in [4c, 4c+4)), 64 tokens.
__global__ __launch_bounds__(256) void dec1_vq_kernel(const float* __restrict__ W,
                                                      const float* __restrict__ cbk)
{
    __shared__ __align__(16) float zs[256 * 16];   // zs[kk*16 + b]
    const int c    = blockIdx.x;
    const int k0   = c * 256;
    const int wid  = threadIdx.x >> 5;
    const int lane = threadIdx.x & 31;

    // 64 tokens, 8 warps x 8 iterations
#pragma unroll
    for (int i = 0; i < 8; ++i) {
        int tt = i * 8 + wid;                 // 0..63
        int b = tt >> 2, j = tt & 3;
        int t = b * S_ + 4 * c + j;

        float d = 3.4e38f; int ix = 0x7fffffff;
        if (lane < NCB) {
            d  = g_candD[(size_t)lane * T_ + t];
            ix = g_candI[(size_t)lane * T_ + t];
        }
        {
            float od = __shfl_down_sync(0xffffffffu, d, 1);
            int   oi = __shfl_down_sync(0xffffffffu, ix, 1);
            if (od < d || (od == d && oi < ix)) { d = od; ix = oi; }
        }
        ix = __shfl_sync(0xffffffffu, ix, 0);

        float l = 0.0f;
        if (lane < 16) {
            float4 cv = ((const float4*)cbk)[ix * 16 + lane];
            float4 zv = ((const float4*)g_ze)[t * 16 + lane];
            int kk = j * 64 + lane * 4;
            zs[(kk + 0) * 16 + b] = cv.x;
            zs[(kk + 1) * 16 + b] = cv.y;
            zs[(kk + 2) * 16 + b] = cv.z;
            zs[(kk + 3) * 16 + b] = cv.w;
            float dx = zv.x - cv.x, dy = zv.y - cv.y;
            float dz = zv.z - cv.z, dw = zv.w - cv.w;
            l = dx * dx + dy * dy + dz * dz + dw * dw;
        }
#pragma unroll
        for (int off = 16; off; off >>= 1)
            l += __shfl_down_sync(0xffffffffu, l, off);
        if (lane == 0) g_tokloss[t] = l;
    }
    __syncthreads();

    int n = threadIdx.x;
    u64 acc[8];
#pragma unroll
    for (int b2 = 0; b2 < 8; ++b2) acc[b2] = 0ULL;

    // depth-8 register prefetch on the W stream (raise LDG MLP)
    const float* Wp = W + (size_t)k0 * H2_ + n;
    float wreg[8];
#pragma unroll
    for (int i = 0; i < 8; ++i) wreg[i] = Wp[(size_t)i * H2_];

    for (int kk0 = 0; kk0 < 256; kk0 += 8) {
#pragma unroll
        for (int i = 0; i < 8; ++i) {
            float wv = wreg[i];
            int kn = kk0 + 8 + i;
            if (kn < 256) wreg[i] = Wp[(size_t)kn * H2_];
            u64 wd = dupf(wv);
            const ulonglong2* dk = (const ulonglong2*)(zs + (kk0 + i) * 16);
            ulonglong2 p0 = dk[0], p1 = dk[1], p2 = dk[2], p3 = dk[3];
            u64 dp[8] = {p0.x, p0.y, p1.x, p1.y, p2.x, p2.y, p3.x, p3.y};
#pragma unroll
            for (int b2 = 0; b2 < 8; ++b2) ffma2(acc[b2], dp[b2], wd);
        }
    }
#pragma unroll
    for (int b2 = 0; b2 < 8; ++b2) {
        float2 f = unpk(acc[b2]);
        g_dpart[blockIdx.x * 4096 + (2*b2)   * H2_ + n] = f.x;
        g_dpart[blockIdx.x * 4096 + (2*b2+1) * H2_ + n] = f.y;
    }
}

// fused: blocks 0-15 finish dec1; block 16 does vq_loss
__global__ void dec1fin_vqloss_kernel(const float* __restrict__ bias, float* __restrict__ out) {
    if (blockIdx.x < 16) {
        int n = blockIdx.x * 256 + threadIdx.x;
        float s = 0.0f;
        for (int c = 0; c < DEC1_CHUNKS; ++c) s += g_dpart[c * 4096 + n];
        g_dvec[n] = fmaxf(s + bias[n & 255], 0.0f);
    } else {
        __shared__ float sb[256];
        float a = 0.0f;
        for (int i = threadIdx.x; i < T_; i += 256) a += g_tokloss[i];
        sb[threadIdx.x] = a;
        __syncthreads();
        for (int s = 128; s > 0; s >>= 1) {
            if (threadIdx.x < s) sb[threadIdx.x] += sb[threadIdx.x + s];
            __syncthreads();
        }
        if (threadIdx.x == 0) out[OUT_VQL] = sb[0] / (float)(T_ * D_);
    }
}

// decoder GEMM2 + softplus — depth-8 register prefetch on the W stream
__global__ __launch_bounds__(256, 2) void dec2_kernel(
    const float* __restrict__ W, const float* __restrict__ bias,
    float* __restrict__ out)
{
    __shared__ __align__(16) float ds[H2_ * 16];
    for (int i = threadIdx.x; i < 4096; i += 256) {
        int b = i >> 8, k = i & 255;
        ds[k * 16 + b] = g_dvec[i];
    }
    __syncthreads();

    int n = (blockIdx.x * 256 + threadIdx.x) * 4;
    if (n >= SF_) return;

    u64 acc[8][4];
#pragma unroll
    for (int b2 = 0; b2 < 8; ++b2)
#pragma unroll
        for (int c = 0; c < 4; ++c) acc[b2][c] = 0ULL;

    const float* Wp = W + n;
    float4 wbuf[8];
#pragma unroll
    for (int i = 0; i < 8; ++i) wbuf[i] = *(const float4*)(Wp + (size_t)i * SF_);

    for (int k0 = 0; k0 < H2_; k0 += 8) {
#pragma unroll
        for (int i = 0; i < 8; ++i) {
            float4 w = wbuf[i];
            int kn = k0 + 8 + i;
            if (kn < H2_) wbuf[i] = *(const float4*)(Wp + (size_t)kn * SF_);
            u64 wd[4] = {dupf(w.x), dupf(w.y), dupf(w.z), dupf(w.w)};
            const ulonglong2* dk = (const ulonglong2*)(ds + (k0 + i) * 16);
            ulonglong2 p0 = dk[0], p1 = dk[1], p2 = dk[2], p3 = dk[3];
            u64 dp[8] = {p0.x, p0.y, p1.x, p1.y, p2.x, p2.y, p3.x, p3.y};
#pragma unroll
            for (int b2 = 0; b2 < 8; ++b2)
#pragma unroll
                for (int c = 0; c < 4; ++c)
                    ffma2(acc[b2][c], dp[b2], wd[c]);
        }
    }

    float4 bb = *(const float4*)(bias + n);
#pragma unroll
    for (int b2 = 0; b2 < 8; ++b2) {
        float2 f0 = unpk(acc[b2][0]);
        float2 f1 = unpk(acc[b2][1]);
        float2 f2 = unpk(acc[b2][2]);
        float2 f3 = unpk(acc[b2][3]);
        float4 v0, v1;
        v0.x = softplusf(f0.x + bb.x);
        v0.y = softplusf(f1.x + bb.y);
        v0.z = softplusf(f2.x + bb.z);
        v0.w = softplusf(f3.x + bb.w);
        v1.x = softplusf(f0.y + bb.x);
        v1.y = softplusf(f1.y + bb.y);
        v1.z = softplusf(f2.y + bb.z);
        v1.w = softplusf(f3.y + bb.w);
        *(float4*)(out + (size_t)(2*b2)   * SF_ + n) = v0;
        *(float4*)(out + (size_t)(2*b2+1) * SF_ + n) = v1;
    }
}

// ---------------- launch ----------------
#define SYM(var) ({ void* _p; cudaGetSymbolAddress(&_p, var); _p; })

extern "C" void kernel_launch(void* const* d_in, const int* in_sizes, int n_in,
                              void* d_out, int out_size)
{
    const float* x   = (const float*)d_in[0];
    const float* eps = (const float*)d_in[1];
    const float* We1 = (const float*)d_in[2];
    const float* be1 = (const float*)d_in[3];
    const float* We2 = (const float*)d_in[4];
    const float* be2 = (const float*)d_in[5];
    const float* We3 = (const float*)d_in[6];
    const float* be3 = (const float*)d_in[7];
    const float* cb  = (const float*)d_in[8];
    const float* Wd1 = (const float*)d_in[9];
    const float* bd1 = (const float*)d_in[10];
    const float* Wd2 = (const float*)d_in[11];
    const float* bd2 = (const float*)d_in[12];
    float* out = (float*)d_out;

    float *h1  = (float*)SYM(g_h1);
    float *h2  = (float*)SYM(g_h2);
    float *ze  = (float*)SYM(g_ze);
    float *wt1 = (float*)SYM(g_wt1);
    float *wt2 = (float*)SYM(g_wt2);
    float *wt3 = (float*)SYM(g_wt3);

    cudaFuncSetAttribute(mma_gemm<1>, cudaFuncAttributeMaxDynamicSharedMemorySize, SMEM_BYTES);
    cudaFuncSetAttribute(mma_gemm<5>, cudaFuncAttributeMaxDynamicSharedMemorySize, SMEM_BYTES);
    cudaFuncSetAttribute(vq_kernel,   cudaFuncAttributeMaxDynamicSharedMemorySize, SMEM_BYTES);

    // fused prep: 3 transposes + codebook norms
    prep_kernel<<<516, 256>>>(We1, We2, We3, cb);

    // encoder MLP on tensor cores (bf16x3)
    mma_gemm<1><<<dim3(4, 72), 256, SMEM_BYTES>>>(T_, H1_, F_,
        x,  wt1, be1, h1, nullptr, nullptr);
    mma_gemm<1><<<dim3(2, 72), 256, SMEM_BYTES>>>(T_, H2_, H1_,
        h1, wt2, be2, h2, nullptr, nullptr);
    // encoder head: GEMM + bias + reparameterize fused
    mma_gemm<5><<<dim3(1, 72), 256, SMEM_BYTES>>>(T_, ENC_, H2_,
        h2, wt3, be3, nullptr, eps, out);

    // persistent VQ: cross GEMM + running argmin (2 candidates/token)
    vq_kernel<<<dim3(NCB, 72), 256, SMEM_BYTES>>>(ze, cb);

    // decoder: fused VQ-finish + GEMM1 partials, then reduce + dec2
    dec1_vq_kernel<<<DEC1_CHUNKS, 256>>>(Wd1, cb);
    dec1fin_vqloss_kernel<<<17, 256>>>(bd1, out);
    dec2_kernel<<<(SF_ / 4 + 255) / 256, 256>>>(Wd2, bd2, out);
}